// round 1
// baseline (speedup 1.0000x reference)
#include <cuda_runtime.h>
#include <cstddef>

// Problem-shape constants (this dataset instance)
#define NMAX 100000
#define EMAX 1600000
#define TOTMAX (EMAX + NMAX)

// ---------------- device scratch (module-load allocated, allowed) ----------
__device__ int   g_indeg[NMAX];
__device__ float g_dinv[NMAX];
__device__ int   g_rowptr[NMAX + 1];
__device__ int   g_cursor[NMAX];
__device__ int   g_bsum[1024];
__device__ int   g_esrc[TOTMAX];
__device__ float g_enorm[TOTMAX];
__device__ float g_bufA[(size_t)NMAX * 128];
__device__ float g_bufB[(size_t)NMAX * 128];

// ---------------- degree / norm ----------------
__global__ void k_deg_init(int* indeg, int n) {
    int g = blockIdx.x * blockDim.x + threadIdx.x;
    if (g < n) indeg[g] = 1;  // self loop
}

__global__ void k_deg_count(const int* __restrict__ ei, int* indeg, int E) {
    int g = blockIdx.x * blockDim.x + threadIdx.x;
    if (g < E) atomicAdd(&indeg[ei[E + g]], 1);  // dst row
}

__global__ void k_dinv(const int* __restrict__ indeg, float* dinv, int n) {
    int g = blockIdx.x * blockDim.x + threadIdx.x;
    if (g < n) dinv[g] = rsqrtf((float)indeg[g]);  // deg >= 1 always
}

// ---------------- exclusive scan (3 phases) ----------------
__global__ void k_scan1(const int* __restrict__ in, int* out, int* bsum, int n) {
    __shared__ int s[1024];
    int g = blockIdx.x * 1024 + threadIdx.x;
    int v = (g < n) ? in[g] : 0;
    s[threadIdx.x] = v;
    __syncthreads();
    for (int off = 1; off < 1024; off <<= 1) {
        int t = (threadIdx.x >= off) ? s[threadIdx.x - off] : 0;
        __syncthreads();
        s[threadIdx.x] += t;
        __syncthreads();
    }
    if (g < n) out[g] = s[threadIdx.x] - v;  // exclusive partial
    if (threadIdx.x == 1023) bsum[blockIdx.x] = s[1023];
}

__global__ void k_scan2(int* bsum, int nb) {
    __shared__ int s[1024];
    int v = (threadIdx.x < nb) ? bsum[threadIdx.x] : 0;
    s[threadIdx.x] = v;
    __syncthreads();
    for (int off = 1; off < 1024; off <<= 1) {
        int t = (threadIdx.x >= off) ? s[threadIdx.x - off] : 0;
        __syncthreads();
        s[threadIdx.x] += t;
        __syncthreads();
    }
    if (threadIdx.x < nb) bsum[threadIdx.x] = s[threadIdx.x] - v;  // exclusive
}

__global__ void k_scan3(int* rowptr, const int* __restrict__ bsum, int* cursor,
                        int n, int total) {
    int g = blockIdx.x * 1024 + threadIdx.x;
    if (g < n) {
        int r = rowptr[g] + bsum[g >> 10];
        rowptr[g] = r;
        cursor[g] = r;
    }
    if (g == 0) rowptr[n] = total;
}

// ---------------- CSR fill (edges + self loops) ----------------
__global__ void k_fill(const int* __restrict__ ei, int E, int n,
                       const float* __restrict__ dinv, int* cursor,
                       int* esrc, float* enorm) {
    int g = blockIdx.x * blockDim.x + threadIdx.x;
    if (g < E) {
        int s = ei[g];
        int d = ei[E + g];
        int pos = atomicAdd(&cursor[d], 1);
        esrc[pos] = s;
        enorm[pos] = dinv[s] * dinv[d];
    } else if (g < E + n) {
        int i = g - E;
        int pos = atomicAdd(&cursor[i], 1);
        esrc[pos] = i;
        float dv = dinv[i];
        enorm[pos] = dv * dv;
    }
}

// ---------------- SGEMM: C[n][fout] = A[n][128] @ W[128][fout] ------------
// BM=BN=BK=64, 256 threads, 4x4 per thread.
__global__ void k_gemm(const float* __restrict__ A, const float* __restrict__ W,
                       float* __restrict__ C, int n, int fout) {
    __shared__ float As[64][64];  // [k][m]
    __shared__ float Bs[64][64];  // [k][n]
    int bm = blockIdx.x * 64;
    int bn = blockIdx.y * 64;
    int tid = threadIdx.x;
    int ty = tid / 16, tx = tid % 16;
    float acc[4][4] = {};

    for (int k0 = 0; k0 < 128; k0 += 64) {
        // load A tile (transposed into smem)
#pragma unroll
        for (int i = 0; i < 4; i++) {
            int f = tid + i * 256;       // float4 index 0..1023
            int row = f / 16;
            int c4 = (f % 16) * 4;
            float4 v = make_float4(0.f, 0.f, 0.f, 0.f);
            int gr = bm + row;
            if (gr < n) v = *(const float4*)&A[(size_t)gr * 128 + k0 + c4];
            As[c4 + 0][row] = v.x;
            As[c4 + 1][row] = v.y;
            As[c4 + 2][row] = v.z;
            As[c4 + 3][row] = v.w;
        }
        // load W tile
#pragma unroll
        for (int i = 0; i < 4; i++) {
            int f = tid + i * 256;
            int kr = f / 16;
            int c4 = (f % 16) * 4;
            float4 v = *(const float4*)&W[(size_t)(k0 + kr) * fout + bn + c4];
            *(float4*)&Bs[kr][c4] = v;
        }
        __syncthreads();
#pragma unroll 16
        for (int k = 0; k < 64; k++) {
            float4 a4 = *(float4*)&As[k][ty * 4];
            float4 b4 = *(float4*)&Bs[k][tx * 4];
            float a[4] = {a4.x, a4.y, a4.z, a4.w};
            float b[4] = {b4.x, b4.y, b4.z, b4.w};
#pragma unroll
            for (int i = 0; i < 4; i++)
#pragma unroll
                for (int j = 0; j < 4; j++) acc[i][j] += a[i] * b[j];
        }
        __syncthreads();
    }
#pragma unroll
    for (int i = 0; i < 4; i++) {
        int gr = bm + ty * 4 + i;
        if (gr < n)
            *(float4*)&C[(size_t)gr * fout + bn + tx * 4] =
                make_float4(acc[i][0], acc[i][1], acc[i][2], acc[i][3]);
    }
}

// ---------------- aggregation: out[d] = sum_{e in CSR[d]} h[src_e]*norm_e + b
// one warp per node; 128 feats -> float4/lane, 64 feats -> float2/lane.
__global__ void k_agg128(const float* __restrict__ h, const int* __restrict__ rowptr,
                         const int* __restrict__ esrc, const float* __restrict__ enorm,
                         const float* __restrict__ bias, float* __restrict__ out,
                         int n, int dorelu) {
    int w = (blockIdx.x * blockDim.x + threadIdx.x) >> 5;
    if (w >= n) return;
    int lane = threadIdx.x & 31;
    int beg = rowptr[w], end = rowptr[w + 1];
    float ax = 0.f, ay = 0.f, az = 0.f, aw = 0.f;
    int e = beg;
    for (; e + 1 < end; e += 2) {
        int s0 = esrc[e], s1 = esrc[e + 1];
        float n0 = enorm[e], n1 = enorm[e + 1];
        float4 v0 = *(const float4*)&h[(size_t)s0 * 128 + lane * 4];
        float4 v1 = *(const float4*)&h[(size_t)s1 * 128 + lane * 4];
        ax += v0.x * n0 + v1.x * n1;
        ay += v0.y * n0 + v1.y * n1;
        az += v0.z * n0 + v1.z * n1;
        aw += v0.w * n0 + v1.w * n1;
    }
    if (e < end) {
        int s0 = esrc[e];
        float n0 = enorm[e];
        float4 v0 = *(const float4*)&h[(size_t)s0 * 128 + lane * 4];
        ax += v0.x * n0;
        ay += v0.y * n0;
        az += v0.z * n0;
        aw += v0.w * n0;
    }
    float4 b4 = *(const float4*)&bias[lane * 4];
    ax += b4.x;
    ay += b4.y;
    az += b4.z;
    aw += b4.w;
    if (dorelu) {
        ax = fmaxf(ax, 0.f);
        ay = fmaxf(ay, 0.f);
        az = fmaxf(az, 0.f);
        aw = fmaxf(aw, 0.f);
    }
    *(float4*)&out[(size_t)w * 128 + lane * 4] = make_float4(ax, ay, az, aw);
}

__global__ void k_agg64(const float* __restrict__ h, const int* __restrict__ rowptr,
                        const int* __restrict__ esrc, const float* __restrict__ enorm,
                        const float* __restrict__ bias, float* __restrict__ out,
                        int n, int dorelu) {
    int w = (blockIdx.x * blockDim.x + threadIdx.x) >> 5;
    if (w >= n) return;
    int lane = threadIdx.x & 31;
    int beg = rowptr[w], end = rowptr[w + 1];
    float ax = 0.f, ay = 0.f;
    int e = beg;
    for (; e + 1 < end; e += 2) {
        int s0 = esrc[e], s1 = esrc[e + 1];
        float n0 = enorm[e], n1 = enorm[e + 1];
        float2 v0 = *(const float2*)&h[(size_t)s0 * 64 + lane * 2];
        float2 v1 = *(const float2*)&h[(size_t)s1 * 64 + lane * 2];
        ax += v0.x * n0 + v1.x * n1;
        ay += v0.y * n0 + v1.y * n1;
    }
    if (e < end) {
        int s0 = esrc[e];
        float n0 = enorm[e];
        float2 v0 = *(const float2*)&h[(size_t)s0 * 64 + lane * 2];
        ax += v0.x * n0;
        ay += v0.y * n0;
    }
    float2 b2 = *(const float2*)&bias[lane * 2];
    ax += b2.x;
    ay += b2.y;
    if (dorelu) {
        ax = fmaxf(ax, 0.f);
        ay = fmaxf(ay, 0.f);
    }
    *(float2*)&out[(size_t)w * 64 + lane * 2] = make_float2(ax, ay);
}

// ---------------- host ----------------
extern "C" void kernel_launch(void* const* d_in, const int* in_sizes, int n_in,
                              void* d_out, int out_size) {
    const float* x   = (const float*)d_in[0];
    const int*   ei  = (const int*)d_in[1];
    const float* W1  = (const float*)d_in[2];
    const float* b1  = (const float*)d_in[3];
    const float* Wm1 = (const float*)d_in[4];
    const float* bm1 = (const float*)d_in[5];
    const float* Wm2 = (const float*)d_in[6];
    const float* bm2 = (const float*)d_in[7];
    const float* W2  = (const float*)d_in[8];
    const float* b2  = (const float*)d_in[9];

    int n = in_sizes[0] / 128;
    int E = in_sizes[1] / 2;

    void *p;
    int   *indeg, *rowptr, *cursor, *bsum, *esrc;
    float *dinv, *enorm, *bufA, *bufB;
    cudaGetSymbolAddress(&p, g_indeg);  indeg  = (int*)p;
    cudaGetSymbolAddress(&p, g_dinv);   dinv   = (float*)p;
    cudaGetSymbolAddress(&p, g_rowptr); rowptr = (int*)p;
    cudaGetSymbolAddress(&p, g_cursor); cursor = (int*)p;
    cudaGetSymbolAddress(&p, g_bsum);   bsum   = (int*)p;
    cudaGetSymbolAddress(&p, g_esrc);   esrc   = (int*)p;
    cudaGetSymbolAddress(&p, g_enorm);  enorm  = (float*)p;
    cudaGetSymbolAddress(&p, g_bufA);   bufA   = (float*)p;
    cudaGetSymbolAddress(&p, g_bufB);   bufB   = (float*)p;

    int nb = (n + 1023) / 1024;

    // ---- graph normalization + CSR build ----
    k_deg_init<<<(n + 255) / 256, 256>>>(indeg, n);
    k_deg_count<<<(E + 255) / 256, 256>>>(ei, indeg, E);
    k_dinv<<<(n + 255) / 256, 256>>>(indeg, dinv, n);
    k_scan1<<<nb, 1024>>>(indeg, rowptr, bsum, n);
    k_scan2<<<1, 1024>>>(bsum, nb);
    k_scan3<<<nb, 1024>>>(rowptr, bsum, cursor, n, E + n);
    k_fill<<<(E + n + 255) / 256, 256>>>(ei, E, n, dinv, cursor, esrc, enorm);

    dim3 gemm_grid2((n + 63) / 64, 2);
    dim3 gemm_grid1((n + 63) / 64, 1);
    int agg_blocks = (n * 32 + 255) / 256;

    // ---- layer 1 ----
    k_gemm<<<gemm_grid2, 256>>>(x, W1, bufA, n, 128);
    k_agg128<<<agg_blocks, 256>>>(bufA, rowptr, esrc, enorm, b1, bufB, n, 1);
    // ---- layer 2 ----
    k_gemm<<<gemm_grid2, 256>>>(bufB, Wm1, bufA, n, 128);
    k_agg128<<<agg_blocks, 256>>>(bufA, rowptr, esrc, enorm, bm1, bufB, n, 1);
    // ---- layer 3 ----
    k_gemm<<<gemm_grid2, 256>>>(bufB, Wm2, bufA, n, 128);
    k_agg128<<<agg_blocks, 256>>>(bufA, rowptr, esrc, enorm, bm2, bufB, n, 1);
    // ---- layer 4 (64 out, no relu) ----
    k_gemm<<<gemm_grid1, 256>>>(bufB, W2, bufA, n, 64);
    k_agg64<<<agg_blocks, 256>>>(bufA, rowptr, esrc, enorm, b2, (float*)d_out, n, 0);
}

// round 6
// speedup vs baseline: 1.2709x; 1.2709x over previous
#include <cuda_runtime.h>
#include <cuda_bf16.h>
#include <cstdint>
#include <cstddef>

#define NMAX 100000
#define EMAX 1600000
#define TOTMAX (EMAX + NMAX)

// tcgen05 is arch-SPECIFIC: only compile it in the 'a'/family pass.
#if defined(__CUDA_ARCH_FEAT_SM103_ALL) || defined(__CUDA_ARCH_FEAT_SM100_ALL) || \
    defined(__CUDA_ARCH_FEAT_SM101_ALL)
#define HAS_TCGEN05 1
#else
#define HAS_TCGEN05 0
#endif

// ---------------- device scratch ----------
__device__ int   g_indeg[NMAX];
__device__ float g_dinv[NMAX];
__device__ int   g_rowptr[NMAX + 1];
__device__ int   g_cursor[NMAX];
__device__ int   g_bsum[1024];
__device__ int   g_esrc[TOTMAX];
__device__ float g_enorm[TOTMAX];
__device__ float g_bufA[(size_t)NMAX * 128];
__device__ float g_bufB[(size_t)NMAX * 128];
__device__ __nv_bfloat16 g_wht[128 * 128];
__device__ __nv_bfloat16 g_wlt[128 * 128];

// ---------------- PTX helpers ----------------
__device__ __forceinline__ uint32_t smem_u32(const void* p) {
    uint32_t a;
    asm("{ .reg .u64 t; cvta.to.shared.u64 t, %1; cvt.u32.u64 %0, t; }" : "=r"(a) : "l"(p));
    return a;
}

#if HAS_TCGEN05
__device__ __forceinline__ uint32_t elect_one() {
    uint32_t pred;
    asm volatile("{\n .reg .pred p;\n elect.sync _|p, 0xFFFFFFFF;\n selp.b32 %0, 1, 0, p;\n}"
                 : "=r"(pred));
    return pred;
}
#define TC_ALLOC(smem_addr, ncols) \
    asm volatile("tcgen05.alloc.cta_group::1.sync.aligned.shared::cta.b32 [%0], %1;" \
                 :: "r"(smem_addr), "r"(ncols) : "memory")
#define TC_DEALLOC(tmem, ncols) \
    asm volatile("tcgen05.dealloc.cta_group::1.sync.aligned.b32 %0, %1;" :: "r"(tmem), "r"(ncols))
#define TC_COMMIT(mbar) \
    asm volatile("tcgen05.commit.cta_group::1.mbarrier::arrive::one.shared::cluster.b64 [%0];" \
                 :: "r"(mbar) : "memory")
#define TC_WAIT_LD() asm volatile("tcgen05.wait::ld.sync.aligned;" ::: "memory")
#define TC_WAIT_ST() asm volatile("tcgen05.wait::st.sync.aligned;" ::: "memory")
#define TC_FENCE_BEFORE() asm volatile("tcgen05.fence::before_thread_sync;" ::: "memory")
#define TC_FENCE_AFTER() asm volatile("tcgen05.fence::after_thread_sync;" ::: "memory")
#define FENCE_ASYNC_SHARED() asm volatile("fence.proxy.async.shared::cta;" ::: "memory")
#define MBAR_INIT(mbar, cnt) \
    asm volatile("mbarrier.init.shared.b64 [%0], %1;" :: "r"(mbar), "r"(cnt) : "memory")
#define MBAR_INVAL(mbar) \
    asm volatile("mbarrier.inval.shared.b64 [%0];" :: "r"(mbar) : "memory")

__device__ __forceinline__ void mbar_wait(uint32_t mbar, uint32_t parity) {
    asm volatile(
        "{\n .reg .pred P1;\n"
        "WAIT_LOOP_%=:\n"
        " mbarrier.try_wait.parity.acquire.cta.shared::cta.b64 P1, [%0], %1, 0x989680;\n"
        " @P1 bra.uni WAIT_DONE_%=;\n"
        " bra.uni WAIT_LOOP_%=;\n"
        "WAIT_DONE_%=:\n}"
        :: "r"(mbar), "r"(parity) : "memory");
}

// RS-mode f16 MMA: A in TMEM (validated by test_mma / test_mma_iter).
__device__ __forceinline__ void mma_f16_rs(uint32_t d, uint32_t a_tmem, uint64_t b,
                                           uint32_t idesc, uint32_t en) {
    uint32_t z = 0;
    asm volatile(
        "{\n .reg .pred p;\n setp.ne.u32 p, %5, 0;\n"
        " tcgen05.mma.cta_group::1.kind::f16 [%0], [%1], %2, %3, {%4, %4, %4, %4}, p;\n}"
        :: "r"(d), "r"(a_tmem), "l"(b), "r"(idesc), "r"(z), "r"(en) : "memory");
}

#define LDTM_X32(r, addr) \
    asm volatile( \
        "tcgen05.ld.sync.aligned.32x32b.x32.b32 " \
        "{%0, %1, %2, %3, %4, %5, %6, %7, %8, %9, %10, %11, %12, %13, %14, %15, " \
        " %16, %17, %18, %19, %20, %21, %22, %23, %24, %25, %26, %27, %28, %29, %30, %31}, [%32];" \
        : "=r"((r)[0]),  "=r"((r)[1]),  "=r"((r)[2]),  "=r"((r)[3]), \
          "=r"((r)[4]),  "=r"((r)[5]),  "=r"((r)[6]),  "=r"((r)[7]), \
          "=r"((r)[8]),  "=r"((r)[9]),  "=r"((r)[10]), "=r"((r)[11]), \
          "=r"((r)[12]), "=r"((r)[13]), "=r"((r)[14]), "=r"((r)[15]), \
          "=r"((r)[16]), "=r"((r)[17]), "=r"((r)[18]), "=r"((r)[19]), \
          "=r"((r)[20]), "=r"((r)[21]), "=r"((r)[22]), "=r"((r)[23]), \
          "=r"((r)[24]), "=r"((r)[25]), "=r"((r)[26]), "=r"((r)[27]), \
          "=r"((r)[28]), "=r"((r)[29]), "=r"((r)[30]), "=r"((r)[31]) \
        : "r"(addr))

#define STTM_X64(addr, r) \
    asm volatile( \
        "tcgen05.st.sync.aligned.32x32b.x64.b32 [%0], " \
        "{%1, %2, %3, %4, %5, %6, %7, %8, " \
        " %9, %10, %11, %12, %13, %14, %15, %16, " \
        " %17, %18, %19, %20, %21, %22, %23, %24, " \
        " %25, %26, %27, %28, %29, %30, %31, %32, " \
        " %33, %34, %35, %36, %37, %38, %39, %40, " \
        " %41, %42, %43, %44, %45, %46, %47, %48, " \
        " %49, %50, %51, %52, %53, %54, %55, %56, " \
        " %57, %58, %59, %60, %61, %62, %63, %64};" \
        :: "r"(addr), \
           "r"((r)[0]),  "r"((r)[1]),  "r"((r)[2]),  "r"((r)[3]), \
           "r"((r)[4]),  "r"((r)[5]),  "r"((r)[6]),  "r"((r)[7]), \
           "r"((r)[8]),  "r"((r)[9]),  "r"((r)[10]), "r"((r)[11]), \
           "r"((r)[12]), "r"((r)[13]), "r"((r)[14]), "r"((r)[15]), \
           "r"((r)[16]), "r"((r)[17]), "r"((r)[18]), "r"((r)[19]), \
           "r"((r)[20]), "r"((r)[21]), "r"((r)[22]), "r"((r)[23]), \
           "r"((r)[24]), "r"((r)[25]), "r"((r)[26]), "r"((r)[27]), \
           "r"((r)[28]), "r"((r)[29]), "r"((r)[30]), "r"((r)[31]), \
           "r"((r)[32]), "r"((r)[33]), "r"((r)[34]), "r"((r)[35]), \
           "r"((r)[36]), "r"((r)[37]), "r"((r)[38]), "r"((r)[39]), \
           "r"((r)[40]), "r"((r)[41]), "r"((r)[42]), "r"((r)[43]), \
           "r"((r)[44]), "r"((r)[45]), "r"((r)[46]), "r"((r)[47]), \
           "r"((r)[48]), "r"((r)[49]), "r"((r)[50]), "r"((r)[51]), \
           "r"((r)[52]), "r"((r)[53]), "r"((r)[54]), "r"((r)[55]), \
           "r"((r)[56]), "r"((r)[57]), "r"((r)[58]), "r"((r)[59]), \
           "r"((r)[60]), "r"((r)[61]), "r"((r)[62]), "r"((r)[63]) \
        : "memory")

// SMEM descriptor: SW128, Blackwell, LBO=1, SBO=64 (MAKE_SMEM_DESC)
__device__ __forceinline__ uint64_t make_desc(uint32_t addr) {
    const uint64_t base = (uint64_t(2) << 61) | (uint64_t(1) << 46) |
                          (uint64_t(64) << 32) | (uint64_t(1) << 16);
    return base | ((uint64_t)(addr >> 4) & 0x3FFF);
}
#endif  // HAS_TCGEN05

// ---------------- degree / norm ----------------
__global__ void k_deg_init(int* indeg, int n) {
    int g = blockIdx.x * blockDim.x + threadIdx.x;
    if (g < n) indeg[g] = 1;
}
__global__ void k_deg_count(const int* __restrict__ ei, int* indeg, int E) {
    int g = blockIdx.x * blockDim.x + threadIdx.x;
    if (g < E) atomicAdd(&indeg[ei[E + g]], 1);
}
__global__ void k_dinv(const int* __restrict__ indeg, float* dinv, int n) {
    int g = blockIdx.x * blockDim.x + threadIdx.x;
    if (g < n) dinv[g] = rsqrtf((float)indeg[g]);
}

// ---------------- exclusive scan ----------------
__global__ void k_scan1(const int* __restrict__ in, int* out, int* bsum, int n) {
    __shared__ int s[1024];
    int g = blockIdx.x * 1024 + threadIdx.x;
    int v = (g < n) ? in[g] : 0;
    s[threadIdx.x] = v;
    __syncthreads();
    for (int off = 1; off < 1024; off <<= 1) {
        int t = (threadIdx.x >= off) ? s[threadIdx.x - off] : 0;
        __syncthreads();
        s[threadIdx.x] += t;
        __syncthreads();
    }
    if (g < n) out[g] = s[threadIdx.x] - v;
    if (threadIdx.x == 1023) bsum[blockIdx.x] = s[1023];
}
__global__ void k_scan2(int* bsum, int nb) {
    __shared__ int s[1024];
    int v = (threadIdx.x < nb) ? bsum[threadIdx.x] : 0;
    s[threadIdx.x] = v;
    __syncthreads();
    for (int off = 1; off < 1024; off <<= 1) {
        int t = (threadIdx.x >= off) ? s[threadIdx.x - off] : 0;
        __syncthreads();
        s[threadIdx.x] += t;
        __syncthreads();
    }
    if (threadIdx.x < nb) bsum[threadIdx.x] = s[threadIdx.x] - v;
}
__global__ void k_scan3(int* rowptr, const int* __restrict__ bsum, int* cursor,
                        int n, int total) {
    int g = blockIdx.x * 1024 + threadIdx.x;
    if (g < n) {
        int r = rowptr[g] + bsum[g >> 10];
        rowptr[g] = r;
        cursor[g] = r;
    }
    if (g == 0) rowptr[n] = total;
}

// ---------------- CSR fill ----------------
__global__ void k_fill(const int* __restrict__ ei, int E, int n,
                       const float* __restrict__ dinv, int* cursor,
                       int* esrc, float* enorm) {
    int g = blockIdx.x * blockDim.x + threadIdx.x;
    if (g < E) {
        int s = ei[g];
        int d = ei[E + g];
        int pos = atomicAdd(&cursor[d], 1);
        esrc[pos] = s;
        enorm[pos] = dinv[s] * dinv[d];
    } else if (g < E + n) {
        int i = g - E;
        int pos = atomicAdd(&cursor[i], 1);
        esrc[pos] = i;
        float dv = dinv[i];
        enorm[pos] = dv * dv;
    }
}

// ---------------- W split+transpose: W[k][fout] -> WhT/WlT[fout][128] bf16 ----
__global__ void k_wsplit(const float* __restrict__ W, __nv_bfloat16* WhT,
                         __nv_bfloat16* WlT, int fout) {
    int i = blockIdx.x * blockDim.x + threadIdx.x;
    if (i < 128 * fout) {
        int k = i / fout, nn = i % fout;
        float x = W[i];
        __nv_bfloat16 h = __float2bfloat16_rn(x);
        float l = x - __bfloat162float(h);
        WhT[nn * 128 + k] = h;
        WlT[nn * 128 + k] = __float2bfloat16_rn(l);
    }
}

// ---------------- tcgen05 GEMM (RS mode, clone of test_mma_iter) ----------
// C[n][FOUT] = A[n][128] @ (WT[FOUT][128])^T.
// A split into bf16 hi/lo stored in TMEM (cols 0 / 64); B (WhT/WlT) in SMEM
// blocked SW128 atom layout; D accumulates fp32 in TMEM cols 128..128+FOUT.
// D = Ah*Wh + Ah*Wl + Al*Wh.
template <int FOUT>
__global__ void __launch_bounds__(256, 1) __cluster_dims__(1, 1, 1) k_gemm_tc(
    const float* __restrict__ A, const __nv_bfloat16* __restrict__ WhT,
    const __nv_bfloat16* __restrict__ WlT, float* __restrict__ C, int n) {
#if HAS_TCGEN05
    extern __shared__ char smem[];
    constexpr int BH_OFF = 1024;
    constexpr int BL_OFF = BH_OFF + FOUT * 128 * 2;
    constexpr uint32_t IDESC =
        (1u << 4) | (1u << 7) | (1u << 10) | ((FOUT / 8) << 17) | (8u << 24);
    constexpr int TM_AH = 0, TM_AL = 64, TM_D = 128;

    uint32_t sbase = smem_u32(smem);
    int tid = threadIdx.x;
    int wid = tid >> 5;
    int lane = tid & 31;
    int bm = blockIdx.x * 128;

    if (wid == 0) TC_ALLOC(sbase, 512);
    if (tid == 0) MBAR_INIT(sbase + 8, 1);
    __syncthreads();
    uint32_t tmem;
    asm volatile("ld.shared.b32 %0, [%1];" : "=r"(tmem) : "r"(sbase));

    // ---- B fill: FOUT rows x 128 cols bf16, blocked atom layout + SW128 ----
    // atom = 8 rows x 64 bf16 (1024B); atom_offset = atom_row + atom_col*(FOUT/8)
    for (int g = tid; g < FOUT * 16; g += 256) {
        int r = g >> 4;
        int k8 = (g & 15) << 3;
        uint4 hv = *(const uint4*)&WhT[r * 128 + k8];
        uint4 lv = *(const uint4*)&WlT[r * 128 + k8];
        int atom = (r >> 3) + (k8 >> 6) * (FOUT >> 3);
        uint32_t boff = atom * 1024 + (r & 7) * 128 + (k8 & 63) * 2;
        uint32_t sw = boff ^ ((boff >> 3) & 0x70);
        *(uint4*)(smem + BH_OFF + sw) = hv;
        *(uint4*)(smem + BL_OFF + sw) = lv;
    }
    FENCE_ASYNC_SHARED();

    // ---- A split + store to TMEM (threads 0..127; one row each) ----
    if (tid < 128) {
        int row = bm + tid;
        uint32_t warp_off = (tid >> 5) << 21;
        const float4* a4 = (const float4*)&A[(size_t)row * 128];
        uint32_t v[64];
        // pass 1: high bf16
#pragma unroll
        for (int i = 0; i < 32; i++) {
            float4 f = (row < n) ? a4[i] : make_float4(0.f, 0.f, 0.f, 0.f);
            __nv_bfloat162 p0 = __halves2bfloat162(__float2bfloat16_rn(f.x),
                                                   __float2bfloat16_rn(f.y));
            __nv_bfloat162 p1 = __halves2bfloat162(__float2bfloat16_rn(f.z),
                                                   __float2bfloat16_rn(f.w));
            v[2 * i]     = *reinterpret_cast<uint32_t*>(&p0);
            v[2 * i + 1] = *reinterpret_cast<uint32_t*>(&p1);
        }
        STTM_X64(tmem + TM_AH + warp_off, v);
        TC_WAIT_ST();
        // pass 2: low residual bf16
#pragma unroll
        for (int i = 0; i < 32; i++) {
            float4 f = (row < n) ? a4[i] : make_float4(0.f, 0.f, 0.f, 0.f);
            float lx = f.x - __bfloat162float(__float2bfloat16_rn(f.x));
            float ly = f.y - __bfloat162float(__float2bfloat16_rn(f.y));
            float lz = f.z - __bfloat162float(__float2bfloat16_rn(f.z));
            float lw = f.w - __bfloat162float(__float2bfloat16_rn(f.w));
            __nv_bfloat162 p0 = __floats2bfloat162_rn(lx, ly);
            __nv_bfloat162 p1 = __floats2bfloat162_rn(lz, lw);
            v[2 * i]     = *reinterpret_cast<uint32_t*>(&p0);
            v[2 * i + 1] = *reinterpret_cast<uint32_t*>(&p1);
        }
        STTM_X64(tmem + TM_AL + warp_off, v);
        TC_WAIT_ST();
    }
    __syncthreads();

    // ---- MMA: 3 term-pairs x 8 K-steps of 16 (warp 0, one thread) ----
    if (wid == 0) {
        if (elect_one()) {
            uint64_t bh = make_desc(sbase + BH_OFF);
            uint64_t bl = make_desc(sbase + BL_OFF);
            const uint64_t BCOL = (uint64_t)FOUT * 8;  // atom-col stride, 16B units
#pragma unroll
            for (int t = 0; t < 3; t++) {
                uint32_t a_base = tmem + ((t == 2) ? TM_AL : TM_AH);
                uint64_t b_base = (t == 1) ? bl : bh;
#pragma unroll
                for (int k = 0; k < 8; k++) {
                    uint32_t a_tmem = a_base + k * 8;
                    uint64_t bd = b_base + ((k < 4) ? (uint64_t)(k * 2)
                                                    : BCOL + (uint64_t)((k - 4) * 2));
                    mma_f16_rs(tmem + TM_D, a_tmem, bd, IDESC, (t > 0 || k > 0) ? 1u : 0u);
                }
            }
            TC_COMMIT(sbase + 8);
        }
    }

    // ---- wait + epilogue (warps 0..3 read their subpartitions) ----
    __syncthreads();
    mbar_wait(sbase + 8, 0);
    TC_FENCE_AFTER();

    if (wid < 4) {
        int row = bm + wid * 32 + lane;
        for (int c0 = 0; c0 < FOUT; c0 += 32) {
            uint32_t r[32];
            LDTM_X32(r, tmem + TM_D + c0);
            TC_WAIT_LD();
            if (row < n) {
                float* dst = &C[(size_t)row * FOUT + c0];
#pragma unroll
                for (int j = 0; j < 8; j++) {
                    *(float4*)(dst + j * 4) =
                        make_float4(__uint_as_float(r[4 * j]), __uint_as_float(r[4 * j + 1]),
                                    __uint_as_float(r[4 * j + 2]), __uint_as_float(r[4 * j + 3]));
                }
            }
        }
        TC_FENCE_BEFORE();
    }
    __syncthreads();
    if (tid == 0) MBAR_INVAL(sbase + 8);
    __syncthreads();
    if (wid == 0) TC_DEALLOC(tmem, 512);
#else
    // Portable-PTX fallback (never executed on GB300: sm_103a SASS is loaded).
    int tid = threadIdx.x;
    int bm = blockIdx.x * 128;
    for (int idx = tid; idx < 128 * FOUT; idx += 256) {
        int r = bm + idx / FOUT;
        int c = idx % FOUT;
        if (r < n) {
            float acc = 0.f;
            for (int k = 0; k < 128; k++) {
                float w = __bfloat162float(WhT[c * 128 + k]) +
                          __bfloat162float(WlT[c * 128 + k]);
                acc += A[(size_t)r * 128 + k] * w;
            }
            C[(size_t)r * FOUT + c] = acc;
        }
    }
#endif
}

// ---------------- aggregation ----------------
__global__ void k_agg128(const float* __restrict__ h, const int* __restrict__ rowptr,
                         const int* __restrict__ esrc, const float* __restrict__ enorm,
                         const float* __restrict__ bias, float* __restrict__ out,
                         int n, int dorelu) {
    int w = (blockIdx.x * blockDim.x + threadIdx.x) >> 5;
    if (w >= n) return;
    int lane = threadIdx.x & 31;
    int beg = rowptr[w], end = rowptr[w + 1];
    float ax = 0.f, ay = 0.f, az = 0.f, aw = 0.f;
    int e = beg;
    for (; e + 1 < end; e += 2) {
        int s0 = esrc[e], s1 = esrc[e + 1];
        float n0 = enorm[e], n1 = enorm[e + 1];
        float4 v0 = *(const float4*)&h[(size_t)s0 * 128 + lane * 4];
        float4 v1 = *(const float4*)&h[(size_t)s1 * 128 + lane * 4];
        ax += v0.x * n0 + v1.x * n1;
        ay += v0.y * n0 + v1.y * n1;
        az += v0.z * n0 + v1.z * n1;
        aw += v0.w * n0 + v1.w * n1;
    }
    if (e < end) {
        int s0 = esrc[e];
        float n0 = enorm[e];
        float4 v0 = *(const float4*)&h[(size_t)s0 * 128 + lane * 4];
        ax += v0.x * n0;
        ay += v0.y * n0;
        az += v0.z * n0;
        aw += v0.w * n0;
    }
    float4 b4 = *(const float4*)&bias[lane * 4];
    ax += b4.x; ay += b4.y; az += b4.z; aw += b4.w;
    if (dorelu) {
        ax = fmaxf(ax, 0.f); ay = fmaxf(ay, 0.f);
        az = fmaxf(az, 0.f); aw = fmaxf(aw, 0.f);
    }
    *(float4*)&out[(size_t)w * 128 + lane * 4] = make_float4(ax, ay, az, aw);
}

__global__ void k_agg64(const float* __restrict__ h, const int* __restrict__ rowptr,
                        const int* __restrict__ esrc, const float* __restrict__ enorm,
                        const float* __restrict__ bias, float* __restrict__ out,
                        int n, int dorelu) {
    int w = (blockIdx.x * blockDim.x + threadIdx.x) >> 5;
    if (w >= n) return;
    int lane = threadIdx.x & 31;
    int beg = rowptr[w], end = rowptr[w + 1];
    float ax = 0.f, ay = 0.f;
    int e = beg;
    for (; e + 1 < end; e += 2) {
        int s0 = esrc[e], s1 = esrc[e + 1];
        float n0 = enorm[e], n1 = enorm[e + 1];
        float2 v0 = *(const float2*)&h[(size_t)s0 * 64 + lane * 2];
        float2 v1 = *(const float2*)&h[(size_t)s1 * 64 + lane * 2];
        ax += v0.x * n0 + v1.x * n1;
        ay += v0.y * n0 + v1.y * n1;
    }
    if (e < end) {
        int s0 = esrc[e];
        float n0 = enorm[e];
        float2 v0 = *(const float2*)&h[(size_t)s0 * 64 + lane * 2];
        ax += v0.x * n0;
        ay += v0.y * n0;
    }
    float2 b2 = *(const float2*)&bias[lane * 2];
    ax += b2.x; ay += b2.y;
    if (dorelu) { ax = fmaxf(ax, 0.f); ay = fmaxf(ay, 0.f); }
    *(float2*)&out[(size_t)w * 64 + lane * 2] = make_float2(ax, ay);
}

// ---------------- host ----------------
extern "C" void kernel_launch(void* const* d_in, const int* in_sizes, int n_in,
                              void* d_out, int out_size) {
    const float* x   = (const float*)d_in[0];
    const int*   ei  = (const int*)d_in[1];
    const float* W1  = (const float*)d_in[2];
    const float* b1  = (const float*)d_in[3];
    const float* Wm1 = (const float*)d_in[4];
    const float* bm1 = (const float*)d_in[5];
    const float* Wm2 = (const float*)d_in[6];
    const float* bm2 = (const float*)d_in[7];
    const float* W2  = (const float*)d_in[8];
    const float* b2  = (const float*)d_in[9];

    int n = in_sizes[0] / 128;
    int E = in_sizes[1] / 2;

    void* p;
    int *indeg, *rowptr, *cursor, *bsum, *esrc;
    float *dinv, *enorm, *bufA, *bufB;
    __nv_bfloat16 *wht, *wlt;
    cudaGetSymbolAddress(&p, g_indeg);  indeg  = (int*)p;
    cudaGetSymbolAddress(&p, g_dinv);   dinv   = (float*)p;
    cudaGetSymbolAddress(&p, g_rowptr); rowptr = (int*)p;
    cudaGetSymbolAddress(&p, g_cursor); cursor = (int*)p;
    cudaGetSymbolAddress(&p, g_bsum);   bsum   = (int*)p;
    cudaGetSymbolAddress(&p, g_esrc);   esrc   = (int*)p;
    cudaGetSymbolAddress(&p, g_enorm);  enorm  = (float*)p;
    cudaGetSymbolAddress(&p, g_bufA);   bufA   = (float*)p;
    cudaGetSymbolAddress(&p, g_bufB);   bufB   = (float*)p;
    cudaGetSymbolAddress(&p, g_wht);    wht    = (__nv_bfloat16*)p;
    cudaGetSymbolAddress(&p, g_wlt);    wlt    = (__nv_bfloat16*)p;

    int nb = (n + 1023) / 1024;

    // ---- graph normalization + CSR build ----
    k_deg_init<<<(n + 255) / 256, 256>>>(indeg, n);
    k_deg_count<<<(E + 255) / 256, 256>>>(ei, indeg, E);
    k_dinv<<<(n + 255) / 256, 256>>>(indeg, dinv, n);
    k_scan1<<<nb, 1024>>>(indeg, rowptr, bsum, n);
    k_scan2<<<1, 1024>>>(bsum, nb);
    k_scan3<<<nb, 1024>>>(rowptr, bsum, cursor, n, E + n);
    k_fill<<<(E + n + 255) / 256, 256>>>(ei, E, n, dinv, cursor, esrc, enorm);

    int gblocks = (n + 127) / 128;
    int agg_blocks = (n * 32 + 255) / 256;
    const int SMEM128 = 1024 + 2 * 128 * 128 * 2;  // 66560
    const int SMEM64  = 1024 + 2 * 64 * 128 * 2;   // 33792
    cudaFuncSetAttribute(k_gemm_tc<128>, cudaFuncAttributeMaxDynamicSharedMemorySize, SMEM128);
    cudaFuncSetAttribute(k_gemm_tc<64>,  cudaFuncAttributeMaxDynamicSharedMemorySize, SMEM64);

    // ---- layer 1 ----
    k_wsplit<<<(128 * 128 + 255) / 256, 256>>>(W1, wht, wlt, 128);
    k_gemm_tc<128><<<gblocks, 256, SMEM128>>>(x, wht, wlt, bufA, n);
    k_agg128<<<agg_blocks, 256>>>(bufA, rowptr, esrc, enorm, b1, bufB, n, 1);
    // ---- layer 2 ----
    k_wsplit<<<(128 * 128 + 255) / 256, 256>>>(Wm1, wht, wlt, 128);
    k_gemm_tc<128><<<gblocks, 256, SMEM128>>>(bufB, wht, wlt, bufA, n);
    k_agg128<<<agg_blocks, 256>>>(bufA, rowptr, esrc, enorm, bm1, bufB, n, 1);
    // ---- layer 3 ----
    k_wsplit<<<(128 * 128 + 255) / 256, 256>>>(Wm2, wht, wlt, 128);
    k_gemm_tc<128><<<gblocks, 256, SMEM128>>>(bufB, wht, wlt, bufA, n);
    k_agg128<<<agg_blocks, 256>>>(bufA, rowptr, esrc, enorm, bm2, bufB, n, 1);
    // ---- layer 4 (64 out, no relu) ----
    k_wsplit<<<(128 * 64 + 255) / 256, 256>>>(W2, wht, wlt, 64);
    k_gemm_tc<64><<<gblocks, 256, SMEM64>>>(bufB, wht, wlt, bufA, n);
    k_agg64<<<agg_blocks, 256>>>(bufA, rowptr, esrc, enorm, b2, (float*)d_out, n, 0);
}

// round 7
// speedup vs baseline: 1.3799x; 1.0858x over previous
#include <cuda_runtime.h>
#include <cuda_bf16.h>
#include <cstdint>
#include <cstddef>

#define NMAX 100000
#define EMAX 1600000
#define TOTMAX (EMAX + NMAX)

#if defined(__CUDA_ARCH_FEAT_SM103_ALL) || defined(__CUDA_ARCH_FEAT_SM100_ALL) || \
    defined(__CUDA_ARCH_FEAT_SM101_ALL)
#define HAS_TCGEN05 1
#else
#define HAS_TCGEN05 0
#endif

// ---------------- device scratch ----------
__device__ int   g_indeg[NMAX];
__device__ float g_dinv[NMAX];
__device__ int   g_rowptr[NMAX + 1];
__device__ int   g_cursor[NMAX];
__device__ int   g_bsum[1024];
__device__ int   g_esrc[TOTMAX];
__device__ float g_enorm[TOTMAX];
__device__ float g_bufA[(size_t)NMAX * 128];
__device__ float g_bufB[(size_t)NMAX * 128];

// ---------------- PTX helpers ----------------
__device__ __forceinline__ uint32_t smem_u32(const void* p) {
    uint32_t a;
    asm("{ .reg .u64 t; cvta.to.shared.u64 t, %1; cvt.u32.u64 %0, t; }" : "=r"(a) : "l"(p));
    return a;
}

#if HAS_TCGEN05
__device__ __forceinline__ uint32_t elect_one() {
    uint32_t pred;
    asm volatile("{\n .reg .pred p;\n elect.sync _|p, 0xFFFFFFFF;\n selp.b32 %0, 1, 0, p;\n}"
                 : "=r"(pred));
    return pred;
}
#define TC_ALLOC(smem_addr, ncols) \
    asm volatile("tcgen05.alloc.cta_group::1.sync.aligned.shared::cta.b32 [%0], %1;" \
                 :: "r"(smem_addr), "r"(ncols) : "memory")
#define TC_DEALLOC(tmem, ncols) \
    asm volatile("tcgen05.dealloc.cta_group::1.sync.aligned.b32 %0, %1;" :: "r"(tmem), "r"(ncols))
#define TC_COMMIT(mbar) \
    asm volatile("tcgen05.commit.cta_group::1.mbarrier::arrive::one.shared::cluster.b64 [%0];" \
                 :: "r"(mbar) : "memory")
#define TC_WAIT_LD() asm volatile("tcgen05.wait::ld.sync.aligned;" ::: "memory")
#define TC_WAIT_ST() asm volatile("tcgen05.wait::st.sync.aligned;" ::: "memory")
#define TC_FENCE_BEFORE() asm volatile("tcgen05.fence::before_thread_sync;" ::: "memory")
#define TC_FENCE_AFTER() asm volatile("tcgen05.fence::after_thread_sync;" ::: "memory")
#define FENCE_ASYNC_SHARED() asm volatile("fence.proxy.async.shared::cta;" ::: "memory")
#define MBAR_INIT(mbar, cnt) \
    asm volatile("mbarrier.init.shared.b64 [%0], %1;" :: "r"(mbar), "r"(cnt) : "memory")
#define MBAR_INVAL(mbar) \
    asm volatile("mbarrier.inval.shared.b64 [%0];" :: "r"(mbar) : "memory")

__device__ __forceinline__ void mbar_wait(uint32_t mbar, uint32_t parity) {
    asm volatile(
        "{\n .reg .pred P1;\n"
        "WAIT_LOOP_%=:\n"
        " mbarrier.try_wait.parity.acquire.cta.shared::cta.b64 P1, [%0], %1, 0x989680;\n"
        " @P1 bra.uni WAIT_DONE_%=;\n"
        " bra.uni WAIT_LOOP_%=;\n"
        "WAIT_DONE_%=:\n}"
        :: "r"(mbar), "r"(parity) : "memory");
}

// RS-mode f16 MMA: A in TMEM (validated by test_mma / test_mma_iter).
__device__ __forceinline__ void mma_f16_rs(uint32_t d, uint32_t a_tmem, uint64_t b,
                                           uint32_t idesc, uint32_t en) {
    uint32_t z = 0;
    asm volatile(
        "{\n .reg .pred p;\n setp.ne.u32 p, %5, 0;\n"
        " tcgen05.mma.cta_group::1.kind::f16 [%0], [%1], %2, %3, {%4, %4, %4, %4}, p;\n}"
        :: "r"(d), "r"(a_tmem), "l"(b), "r"(idesc), "r"(z), "r"(en) : "memory");
}

#define LDTM_X32(r, addr) \
    asm volatile( \
        "tcgen05.ld.sync.aligned.32x32b.x32.b32 " \
        "{%0, %1, %2, %3, %4, %5, %6, %7, %8, %9, %10, %11, %12, %13, %14, %15, " \
        " %16, %17, %18, %19, %20, %21, %22, %23, %24, %25, %26, %27, %28, %29, %30, %31}, [%32];" \
        : "=r"((r)[0]),  "=r"((r)[1]),  "=r"((r)[2]),  "=r"((r)[3]), \
          "=r"((r)[4]),  "=r"((r)[5]),  "=r"((r)[6]),  "=r"((r)[7]), \
          "=r"((r)[8]),  "=r"((r)[9]),  "=r"((r)[10]), "=r"((r)[11]), \
          "=r"((r)[12]), "=r"((r)[13]), "=r"((r)[14]), "=r"((r)[15]), \
          "=r"((r)[16]), "=r"((r)[17]), "=r"((r)[18]), "=r"((r)[19]), \
          "=r"((r)[20]), "=r"((r)[21]), "=r"((r)[22]), "=r"((r)[23]), \
          "=r"((r)[24]), "=r"((r)[25]), "=r"((r)[26]), "=r"((r)[27]), \
          "=r"((r)[28]), "=r"((r)[29]), "=r"((r)[30]), "=r"((r)[31]) \
        : "r"(addr))

#define STTM_X64(addr, r) \
    asm volatile( \
        "tcgen05.st.sync.aligned.32x32b.x64.b32 [%0], " \
        "{%1, %2, %3, %4, %5, %6, %7, %8, " \
        " %9, %10, %11, %12, %13, %14, %15, %16, " \
        " %17, %18, %19, %20, %21, %22, %23, %24, " \
        " %25, %26, %27, %28, %29, %30, %31, %32, " \
        " %33, %34, %35, %36, %37, %38, %39, %40, " \
        " %41, %42, %43, %44, %45, %46, %47, %48, " \
        " %49, %50, %51, %52, %53, %54, %55, %56, " \
        " %57, %58, %59, %60, %61, %62, %63, %64};" \
        :: "r"(addr), \
           "r"((r)[0]),  "r"((r)[1]),  "r"((r)[2]),  "r"((r)[3]), \
           "r"((r)[4]),  "r"((r)[5]),  "r"((r)[6]),  "r"((r)[7]), \
           "r"((r)[8]),  "r"((r)[9]),  "r"((r)[10]), "r"((r)[11]), \
           "r"((r)[12]), "r"((r)[13]), "r"((r)[14]), "r"((r)[15]), \
           "r"((r)[16]), "r"((r)[17]), "r"((r)[18]), "r"((r)[19]), \
           "r"((r)[20]), "r"((r)[21]), "r"((r)[22]), "r"((r)[23]), \
           "r"((r)[24]), "r"((r)[25]), "r"((r)[26]), "r"((r)[27]), \
           "r"((r)[28]), "r"((r)[29]), "r"((r)[30]), "r"((r)[31]), \
           "r"((r)[32]), "r"((r)[33]), "r"((r)[34]), "r"((r)[35]), \
           "r"((r)[36]), "r"((r)[37]), "r"((r)[38]), "r"((r)[39]), \
           "r"((r)[40]), "r"((r)[41]), "r"((r)[42]), "r"((r)[43]), \
           "r"((r)[44]), "r"((r)[45]), "r"((r)[46]), "r"((r)[47]), \
           "r"((r)[48]), "r"((r)[49]), "r"((r)[50]), "r"((r)[51]), \
           "r"((r)[52]), "r"((r)[53]), "r"((r)[54]), "r"((r)[55]), \
           "r"((r)[56]), "r"((r)[57]), "r"((r)[58]), "r"((r)[59]), \
           "r"((r)[60]), "r"((r)[61]), "r"((r)[62]), "r"((r)[63]) \
        : "memory")

// SMEM descriptor: SW128, Blackwell, LBO=1, SBO=64
__device__ __forceinline__ uint64_t make_desc(uint32_t addr) {
    const uint64_t base = (uint64_t(2) << 61) | (uint64_t(1) << 46) |
                          (uint64_t(64) << 32) | (uint64_t(1) << 16);
    return base | ((uint64_t)(addr >> 4) & 0x3FFF);
}
#endif  // HAS_TCGEN05

// ---------------- degree / norm ----------------
__global__ void k_deg_init(int* indeg, int n) {
    int g = blockIdx.x * blockDim.x + threadIdx.x;
    if (g < n) indeg[g] = 1;
}
__global__ void k_deg_count(const int* __restrict__ ei, int* indeg, int E) {
    int g = blockIdx.x * blockDim.x + threadIdx.x;
    if (g < E) atomicAdd(&indeg[ei[E + g]], 1);
}
__global__ void k_dinv(const int* __restrict__ indeg, float* dinv, int n) {
    int g = blockIdx.x * blockDim.x + threadIdx.x;
    if (g < n) dinv[g] = rsqrtf((float)indeg[g]);
}

// ---------------- exclusive scan ----------------
__global__ void k_scan1(const int* __restrict__ in, int* out, int* bsum, int n) {
    __shared__ int s[1024];
    int g = blockIdx.x * 1024 + threadIdx.x;
    int v = (g < n) ? in[g] : 0;
    s[threadIdx.x] = v;
    __syncthreads();
    for (int off = 1; off < 1024; off <<= 1) {
        int t = (threadIdx.x >= off) ? s[threadIdx.x - off] : 0;
        __syncthreads();
        s[threadIdx.x] += t;
        __syncthreads();
    }
    if (g < n) out[g] = s[threadIdx.x] - v;
    if (threadIdx.x == 1023) bsum[blockIdx.x] = s[1023];
}
__global__ void k_scan2(int* bsum, int nb) {
    __shared__ int s[1024];
    int v = (threadIdx.x < nb) ? bsum[threadIdx.x] : 0;
    s[threadIdx.x] = v;
    __syncthreads();
    for (int off = 1; off < 1024; off <<= 1) {
        int t = (threadIdx.x >= off) ? s[threadIdx.x - off] : 0;
        __syncthreads();
        s[threadIdx.x] += t;
        __syncthreads();
    }
    if (threadIdx.x < nb) bsum[threadIdx.x] = s[threadIdx.x] - v;
}
__global__ void k_scan3(int* rowptr, const int* __restrict__ bsum, int* cursor,
                        int n, int total) {
    int g = blockIdx.x * 1024 + threadIdx.x;
    if (g < n) {
        int r = rowptr[g] + bsum[g >> 10];
        rowptr[g] = r;
        cursor[g] = r;
    }
    if (g == 0) rowptr[n] = total;
}

// ---------------- CSR fill ----------------
__global__ void k_fill(const int* __restrict__ ei, int E, int n,
                       const float* __restrict__ dinv, int* cursor,
                       int* esrc, float* enorm) {
    int g = blockIdx.x * blockDim.x + threadIdx.x;
    if (g < E) {
        int s = ei[g];
        int d = ei[E + g];
        int pos = atomicAdd(&cursor[d], 1);
        esrc[pos] = s;
        enorm[pos] = dinv[s] * dinv[d];
    } else if (g < E + n) {
        int i = g - E;
        int pos = atomicAdd(&cursor[i], 1);
        esrc[pos] = i;
        float dv = dinv[i];
        enorm[pos] = dv * dv;
    }
}

// ---------------- persistent pipelined tcgen05 GEMM (RS mode) --------------
// C[n][FOUT] = A[n][128] @ W[128][FOUT].  W split in-kernel to bf16 hi/lo in
// SMEM (blocked SW128 atom layout, validated in test_mma_iter).  A split to
// bf16 hi/lo in TMEM.  D = Ah*Wh + Ah*Wl + Al*Wh, fp32 accum in TMEM.
// TMEM double buffer: A[p] at cols p*128 (+64 lo), D[p] at 256 + p*128.
template <int FOUT>
__global__ void __launch_bounds__(256, 1) __cluster_dims__(1, 1, 1) k_gemm_tc(
    const float* __restrict__ A, const float* __restrict__ W,
    float* __restrict__ C, int n) {
#if HAS_TCGEN05
    extern __shared__ char smem[];
    constexpr int BH_OFF = 1024;
    constexpr int BL_OFF = BH_OFF + FOUT * 128 * 2;
    constexpr uint32_t IDESC =
        (1u << 4) | (1u << 7) | (1u << 10) | ((FOUT / 8) << 17) | (8u << 24);

    uint32_t sbase = smem_u32(smem);
    int tid = threadIdx.x;
    int wid = tid >> 5;
    int lane = tid & 31;

    if (wid == 0) TC_ALLOC(sbase, 512);
    if (tid == 0) { MBAR_INIT(sbase + 8, 1); MBAR_INIT(sbase + 16, 1); }
    __syncthreads();
    uint32_t tmem;
    asm volatile("ld.shared.b32 %0, [%1];" : "=r"(tmem) : "r"(sbase));

    // ---- B fill once: split W[k][FOUT] into bf16 hi/lo, blocked SW128 ----
    for (int g = tid; g < FOUT * 16; g += 256) {
        int r = g >> 4;              // output-feature row of B (0..FOUT-1)
        int k8 = (g & 15) << 3;      // k start (0..120 step 8)
        uint32_t hu[4], lu[4];
#pragma unroll
        for (int j = 0; j < 4; j++) {
            float x0 = W[(size_t)(k8 + 2 * j) * FOUT + r];
            float x1 = W[(size_t)(k8 + 2 * j + 1) * FOUT + r];
            __nv_bfloat16 h0 = __float2bfloat16_rn(x0);
            __nv_bfloat16 h1 = __float2bfloat16_rn(x1);
            float l0 = x0 - __bfloat162float(h0);
            float l1 = x1 - __bfloat162float(h1);
            __nv_bfloat162 hp = __halves2bfloat162(h0, h1);
            __nv_bfloat162 lp = __floats2bfloat162_rn(l0, l1);
            hu[j] = *reinterpret_cast<uint32_t*>(&hp);
            lu[j] = *reinterpret_cast<uint32_t*>(&lp);
        }
        int atom = (r >> 3) + (k8 >> 6) * (FOUT >> 3);
        uint32_t boff = atom * 1024 + (r & 7) * 128 + (k8 & 63) * 2;
        uint32_t sw = boff ^ ((boff >> 3) & 0x70);
        *(uint4*)(smem + BH_OFF + sw) = make_uint4(hu[0], hu[1], hu[2], hu[3]);
        *(uint4*)(smem + BL_OFF + sw) = make_uint4(lu[0], lu[1], lu[2], lu[3]);
    }
    FENCE_ASYNC_SHARED();
    __syncthreads();

    uint64_t bh = make_desc(sbase + BH_OFF);
    uint64_t bl = make_desc(sbase + BL_OFF);
    const uint64_t BCOL = (uint64_t)FOUT * 8;  // atom-col stride, 16B units

    int it = 0;
    int prev_bm = 0;
    for (int tile = blockIdx.x; tile * 128 < n; tile += gridDim.x, it++) {
        int p = it & 1;
        int bm = tile * 128;
        uint32_t tm_a = tmem + p * 128;         // Ah at +0, Al at +64
        uint32_t tm_d = tmem + 256 + p * 128;

        // ---- A split + STTM into buf p (warps 0..3; one row/thread) ----
        // Safe: buf p's previous MMA (tile it-2) was waited at iteration it-1.
        if (tid < 128) {
            int row = bm + tid;
            uint32_t warp_off = (tid >> 5) << 21;
            const float4* a4 = (const float4*)&A[(size_t)row * 128];
            uint32_t v[64];
#pragma unroll
            for (int i = 0; i < 32; i++) {
                float4 f = (row < n) ? a4[i] : make_float4(0.f, 0.f, 0.f, 0.f);
                __nv_bfloat162 p0 = __halves2bfloat162(__float2bfloat16_rn(f.x),
                                                       __float2bfloat16_rn(f.y));
                __nv_bfloat162 p1 = __halves2bfloat162(__float2bfloat16_rn(f.z),
                                                       __float2bfloat16_rn(f.w));
                v[2 * i]     = *reinterpret_cast<uint32_t*>(&p0);
                v[2 * i + 1] = *reinterpret_cast<uint32_t*>(&p1);
            }
            STTM_X64(tm_a, v);
            TC_WAIT_ST();
#pragma unroll
            for (int i = 0; i < 32; i++) {
                float4 f = (row < n) ? a4[i] : make_float4(0.f, 0.f, 0.f, 0.f);
                float lx = f.x - __bfloat162float(__float2bfloat16_rn(f.x));
                float ly = f.y - __bfloat162float(__float2bfloat16_rn(f.y));
                float lz = f.z - __bfloat162float(__float2bfloat16_rn(f.z));
                float lw = f.w - __bfloat162float(__float2bfloat16_rn(f.w));
                __nv_bfloat162 p0 = __floats2bfloat162_rn(lx, ly);
                __nv_bfloat162 p1 = __floats2bfloat162_rn(lz, lw);
                v[2 * i]     = *reinterpret_cast<uint32_t*>(&p0);
                v[2 * i + 1] = *reinterpret_cast<uint32_t*>(&p1);
            }
            STTM_X64(tm_a + 64, v);
            TC_WAIT_ST();
        }
        TC_FENCE_BEFORE();
        __syncthreads();

        // ---- MMA: 3 term-pairs x 8 K-steps (warp 0, elected thread) ----
        if (wid == 0) {
            TC_FENCE_AFTER();
            if (elect_one()) {
#pragma unroll
                for (int t = 0; t < 3; t++) {
                    uint32_t a_base = tm_a + ((t == 2) ? 64 : 0);
                    uint64_t b_base = (t == 1) ? bl : bh;
#pragma unroll
                    for (int k = 0; k < 8; k++) {
                        uint64_t bd = b_base + ((k < 4) ? (uint64_t)(k * 2)
                                                        : BCOL + (uint64_t)((k - 4) * 2));
                        mma_f16_rs(tm_d, a_base + k * 8, bd, IDESC,
                                   (t > 0 || k > 0) ? 1u : 0u);
                    }
                }
                TC_COMMIT(sbase + 8 + 8 * p);
            }
        }

        // ---- epilogue of tile it-1 (overlaps current MMA) ----
        if (it > 0) {
            int q = p ^ 1;
            mbar_wait(sbase + 8 + 8 * q, ((it - 1) >> 1) & 1);
            TC_FENCE_AFTER();
            if (wid < 4) {
                int row = prev_bm + wid * 32 + lane;
                uint32_t tm_dq = tmem + 256 + q * 128;
                for (int c0 = 0; c0 < FOUT; c0 += 32) {
                    uint32_t r[32];
                    LDTM_X32(r, tm_dq + c0);
                    TC_WAIT_LD();
                    if (row < n) {
                        float* dst = &C[(size_t)row * FOUT + c0];
#pragma unroll
                        for (int j = 0; j < 8; j++)
                            *(float4*)(dst + j * 4) = make_float4(
                                __uint_as_float(r[4 * j]), __uint_as_float(r[4 * j + 1]),
                                __uint_as_float(r[4 * j + 2]), __uint_as_float(r[4 * j + 3]));
                    }
                }
                TC_FENCE_BEFORE();
            }
        }
        prev_bm = bm;
    }

    // ---- final epilogue (last tile) ----
    if (it > 0) {
        int q = (it - 1) & 1;
        mbar_wait(sbase + 8 + 8 * q, ((it - 1) >> 1) & 1);
        TC_FENCE_AFTER();
        if (wid < 4) {
            int row = prev_bm + wid * 32 + lane;
            uint32_t tm_dq = tmem + 256 + q * 128;
            for (int c0 = 0; c0 < FOUT; c0 += 32) {
                uint32_t r[32];
                LDTM_X32(r, tm_dq + c0);
                TC_WAIT_LD();
                if (row < n) {
                    float* dst = &C[(size_t)row * FOUT + c0];
#pragma unroll
                    for (int j = 0; j < 8; j++)
                        *(float4*)(dst + j * 4) = make_float4(
                            __uint_as_float(r[4 * j]), __uint_as_float(r[4 * j + 1]),
                            __uint_as_float(r[4 * j + 2]), __uint_as_float(r[4 * j + 3]));
                }
            }
            TC_FENCE_BEFORE();
        }
    }
    __syncthreads();
    if (tid == 0) { MBAR_INVAL(sbase + 8); MBAR_INVAL(sbase + 16); }
    __syncthreads();
    if (wid == 0) TC_DEALLOC(tmem, 512);
#else
    // Portable-PTX fallback (never executed on GB300).
    int tid = threadIdx.x;
    for (int tile = blockIdx.x; tile * 128 < n; tile += gridDim.x) {
        int bm = tile * 128;
        for (int idx = tid; idx < 128 * FOUT; idx += 256) {
            int r = bm + idx / FOUT;
            int c = idx % FOUT;
            if (r < n) {
                float acc = 0.f;
                for (int k = 0; k < 128; k++)
                    acc += A[(size_t)r * 128 + k] * W[(size_t)k * FOUT + c];
                C[(size_t)r * FOUT + c] = acc;
            }
        }
    }
#endif
}

// ---------------- aggregation ----------------
__global__ void k_agg128(const float* __restrict__ h, const int* __restrict__ rowptr,
                         const int* __restrict__ esrc, const float* __restrict__ enorm,
                         const float* __restrict__ bias, float* __restrict__ out,
                         int n, int dorelu) {
    int w = (blockIdx.x * blockDim.x + threadIdx.x) >> 5;
    if (w >= n) return;
    int lane = threadIdx.x & 31;
    int beg = rowptr[w], end = rowptr[w + 1];
    float ax = 0.f, ay = 0.f, az = 0.f, aw = 0.f;
    int e = beg;
    for (; e + 1 < end; e += 2) {
        int s0 = esrc[e], s1 = esrc[e + 1];
        float n0 = enorm[e], n1 = enorm[e + 1];
        float4 v0 = *(const float4*)&h[(size_t)s0 * 128 + lane * 4];
        float4 v1 = *(const float4*)&h[(size_t)s1 * 128 + lane * 4];
        ax += v0.x * n0 + v1.x * n1;
        ay += v0.y * n0 + v1.y * n1;
        az += v0.z * n0 + v1.z * n1;
        aw += v0.w * n0 + v1.w * n1;
    }
    if (e < end) {
        int s0 = esrc[e];
        float n0 = enorm[e];
        float4 v0 = *(const float4*)&h[(size_t)s0 * 128 + lane * 4];
        ax += v0.x * n0;
        ay += v0.y * n0;
        az += v0.z * n0;
        aw += v0.w * n0;
    }
    float4 b4 = *(const float4*)&bias[lane * 4];
    ax += b4.x; ay += b4.y; az += b4.z; aw += b4.w;
    if (dorelu) {
        ax = fmaxf(ax, 0.f); ay = fmaxf(ay, 0.f);
        az = fmaxf(az, 0.f); aw = fmaxf(aw, 0.f);
    }
    *(float4*)&out[(size_t)w * 128 + lane * 4] = make_float4(ax, ay, az, aw);
}

__global__ void k_agg64(const float* __restrict__ h, const int* __restrict__ rowptr,
                        const int* __restrict__ esrc, const float* __restrict__ enorm,
                        const float* __restrict__ bias, float* __restrict__ out,
                        int n, int dorelu) {
    int w = (blockIdx.x * blockDim.x + threadIdx.x) >> 5;
    if (w >= n) return;
    int lane = threadIdx.x & 31;
    int beg = rowptr[w], end = rowptr[w + 1];
    float ax = 0.f, ay = 0.f;
    int e = beg;
    for (; e + 1 < end; e += 2) {
        int s0 = esrc[e], s1 = esrc[e + 1];
        float n0 = enorm[e], n1 = enorm[e + 1];
        float2 v0 = *(const float2*)&h[(size_t)s0 * 64 + lane * 2];
        float2 v1 = *(const float2*)&h[(size_t)s1 * 64 + lane * 2];
        ax += v0.x * n0 + v1.x * n1;
        ay += v0.y * n0 + v1.y * n1;
    }
    if (e < end) {
        int s0 = esrc[e];
        float n0 = enorm[e];
        float2 v0 = *(const float2*)&h[(size_t)s0 * 64 + lane * 2];
        ax += v0.x * n0;
        ay += v0.y * n0;
    }
    float2 b2 = *(const float2*)&bias[lane * 2];
    ax += b2.x; ay += b2.y;
    if (dorelu) { ax = fmaxf(ax, 0.f); ay = fmaxf(ay, 0.f); }
    *(float2*)&out[(size_t)w * 64 + lane * 2] = make_float2(ax, ay);
}

// ---------------- host ----------------
extern "C" void kernel_launch(void* const* d_in, const int* in_sizes, int n_in,
                              void* d_out, int out_size) {
    const float* x   = (const float*)d_in[0];
    const int*   ei  = (const int*)d_in[1];
    const float* W1  = (const float*)d_in[2];
    const float* b1  = (const float*)d_in[3];
    const float* Wm1 = (const float*)d_in[4];
    const float* bm1 = (const float*)d_in[5];
    const float* Wm2 = (const float*)d_in[6];
    const float* bm2 = (const float*)d_in[7];
    const float* W2  = (const float*)d_in[8];
    const float* b2  = (const float*)d_in[9];

    int n = in_sizes[0] / 128;
    int E = in_sizes[1] / 2;

    void* p;
    int *indeg, *rowptr, *cursor, *bsum, *esrc;
    float *dinv, *enorm, *bufA, *bufB;
    cudaGetSymbolAddress(&p, g_indeg);  indeg  = (int*)p;
    cudaGetSymbolAddress(&p, g_dinv);   dinv   = (float*)p;
    cudaGetSymbolAddress(&p, g_rowptr); rowptr = (int*)p;
    cudaGetSymbolAddress(&p, g_cursor); cursor = (int*)p;
    cudaGetSymbolAddress(&p, g_bsum);   bsum   = (int*)p;
    cudaGetSymbolAddress(&p, g_esrc);   esrc   = (int*)p;
    cudaGetSymbolAddress(&p, g_enorm);  enorm  = (float*)p;
    cudaGetSymbolAddress(&p, g_bufA);   bufA   = (float*)p;
    cudaGetSymbolAddress(&p, g_bufB);   bufB   = (float*)p;

    int nb = (n + 1023) / 1024;

    // ---- graph normalization + CSR build ----
    k_deg_init<<<(n + 255) / 256, 256>>>(indeg, n);
    k_deg_count<<<(E + 255) / 256, 256>>>(ei, indeg, E);
    k_dinv<<<(n + 255) / 256, 256>>>(indeg, dinv, n);
    k_scan1<<<nb, 1024>>>(indeg, rowptr, bsum, n);
    k_scan2<<<1, 1024>>>(bsum, nb);
    k_scan3<<<nb, 1024>>>(rowptr, bsum, cursor, n, E + n);
    k_fill<<<(E + n + 255) / 256, 256>>>(ei, E, n, dinv, cursor, esrc, enorm);

    int gblocks = (n + 127) / 128;
    int ggrid = gblocks < 148 ? gblocks : 148;    // persistent CTAs
    int agg_blocks = (n * 32 + 255) / 256;
    const int SMEM128 = 1024 + 2 * 128 * 128 * 2;  // 66560
    const int SMEM64  = 1024 + 2 * 64 * 128 * 2;   // 33792
    cudaFuncSetAttribute(k_gemm_tc<128>, cudaFuncAttributeMaxDynamicSharedMemorySize, SMEM128);
    cudaFuncSetAttribute(k_gemm_tc<64>,  cudaFuncAttributeMaxDynamicSharedMemorySize, SMEM64);

    // ---- layer 1 ----
    k_gemm_tc<128><<<ggrid, 256, SMEM128>>>(x, W1, bufA, n);
    k_agg128<<<agg_blocks, 256>>>(bufA, rowptr, esrc, enorm, b1, bufB, n, 1);
    // ---- layer 2 ----
    k_gemm_tc<128><<<ggrid, 256, SMEM128>>>(bufB, Wm1, bufA, n);
    k_agg128<<<agg_blocks, 256>>>(bufA, rowptr, esrc, enorm, bm1, bufB, n, 1);
    // ---- layer 3 ----
    k_gemm_tc<128><<<ggrid, 256, SMEM128>>>(bufB, Wm2, bufA, n);
    k_agg128<<<agg_blocks, 256>>>(bufA, rowptr, esrc, enorm, bm2, bufB, n, 1);
    // ---- layer 4 (64 out, no relu) ----
    k_gemm_tc<64><<<ggrid, 256, SMEM64>>>(bufB, W2, bufA, n);
    k_agg64<<<agg_blocks, 256>>>(bufA, rowptr, esrc, enorm, b2, (float*)d_out, n, 0);
}

// round 8
// speedup vs baseline: 1.7610x; 1.2762x over previous
#include <cuda_runtime.h>
#include <cuda_bf16.h>
#include <cuda_fp16.h>
#include <cstdint>
#include <cstddef>

#define NMAX 100000
#define EMAX 1600000
#define TOTMAX (EMAX + NMAX)

#if defined(__CUDA_ARCH_FEAT_SM103_ALL) || defined(__CUDA_ARCH_FEAT_SM100_ALL) || \
    defined(__CUDA_ARCH_FEAT_SM101_ALL)
#define HAS_TCGEN05 1
#else
#define HAS_TCGEN05 0
#endif

// ---------------- device scratch ----------
__device__ int    g_indeg[NMAX];
__device__ float  g_dinv[NMAX];
__device__ int    g_rowptr[NMAX + 1];
__device__ int    g_cursor[NMAX];
__device__ int    g_bsum[1024];
__device__ int    g_esrc[TOTMAX];
__device__ float  g_enorm[TOTMAX];
__device__ float  g_bufA[(size_t)NMAX * 128];   // h (fp32) ping
__device__ float  g_bufB[(size_t)NMAX * 128];   // h (fp32) pong
__device__ __half g_bufT[(size_t)NMAX * 128];   // t = X@W (fp16)

// ---------------- PTX helpers ----------------
__device__ __forceinline__ uint32_t smem_u32(const void* p) {
    uint32_t a;
    asm("{ .reg .u64 t; cvta.to.shared.u64 t, %1; cvt.u32.u64 %0, t; }" : "=r"(a) : "l"(p));
    return a;
}

#if HAS_TCGEN05
__device__ __forceinline__ uint32_t elect_one() {
    uint32_t pred;
    asm volatile("{\n .reg .pred p;\n elect.sync _|p, 0xFFFFFFFF;\n selp.b32 %0, 1, 0, p;\n}"
                 : "=r"(pred));
    return pred;
}
#define TC_ALLOC(smem_addr, ncols) \
    asm volatile("tcgen05.alloc.cta_group::1.sync.aligned.shared::cta.b32 [%0], %1;" \
                 :: "r"(smem_addr), "r"(ncols) : "memory")
#define TC_DEALLOC(tmem, ncols) \
    asm volatile("tcgen05.dealloc.cta_group::1.sync.aligned.b32 %0, %1;" :: "r"(tmem), "r"(ncols))
#define TC_COMMIT(mbar) \
    asm volatile("tcgen05.commit.cta_group::1.mbarrier::arrive::one.shared::cluster.b64 [%0];" \
                 :: "r"(mbar) : "memory")
#define TC_WAIT_LD() asm volatile("tcgen05.wait::ld.sync.aligned;" ::: "memory")
#define TC_WAIT_ST() asm volatile("tcgen05.wait::st.sync.aligned;" ::: "memory")
#define TC_FENCE_BEFORE() asm volatile("tcgen05.fence::before_thread_sync;" ::: "memory")
#define TC_FENCE_AFTER() asm volatile("tcgen05.fence::after_thread_sync;" ::: "memory")
#define FENCE_ASYNC_SHARED() asm volatile("fence.proxy.async.shared::cta;" ::: "memory")
#define MBAR_INIT(mbar, cnt) \
    asm volatile("mbarrier.init.shared.b64 [%0], %1;" :: "r"(mbar), "r"(cnt) : "memory")
#define MBAR_INVAL(mbar) \
    asm volatile("mbarrier.inval.shared.b64 [%0];" :: "r"(mbar) : "memory")

__device__ __forceinline__ void mbar_wait(uint32_t mbar, uint32_t parity) {
    asm volatile(
        "{\n .reg .pred P1;\n"
        "WAIT_LOOP_%=:\n"
        " mbarrier.try_wait.parity.acquire.cta.shared::cta.b64 P1, [%0], %1, 0x989680;\n"
        " @P1 bra.uni WAIT_DONE_%=;\n"
        " bra.uni WAIT_LOOP_%=;\n"
        "WAIT_DONE_%=:\n}"
        :: "r"(mbar), "r"(parity) : "memory");
}

// RS-mode f16 MMA: A in TMEM (validated by test_mma / test_mma_iter).
__device__ __forceinline__ void mma_f16_rs(uint32_t d, uint32_t a_tmem, uint64_t b,
                                           uint32_t idesc, uint32_t en) {
    uint32_t z = 0;
    asm volatile(
        "{\n .reg .pred p;\n setp.ne.u32 p, %5, 0;\n"
        " tcgen05.mma.cta_group::1.kind::f16 [%0], [%1], %2, %3, {%4, %4, %4, %4}, p;\n}"
        :: "r"(d), "r"(a_tmem), "l"(b), "r"(idesc), "r"(z), "r"(en) : "memory");
}

#define LDTM_X32(r, addr) \
    asm volatile( \
        "tcgen05.ld.sync.aligned.32x32b.x32.b32 " \
        "{%0, %1, %2, %3, %4, %5, %6, %7, %8, %9, %10, %11, %12, %13, %14, %15, " \
        " %16, %17, %18, %19, %20, %21, %22, %23, %24, %25, %26, %27, %28, %29, %30, %31}, [%32];" \
        : "=r"((r)[0]),  "=r"((r)[1]),  "=r"((r)[2]),  "=r"((r)[3]), \
          "=r"((r)[4]),  "=r"((r)[5]),  "=r"((r)[6]),  "=r"((r)[7]), \
          "=r"((r)[8]),  "=r"((r)[9]),  "=r"((r)[10]), "=r"((r)[11]), \
          "=r"((r)[12]), "=r"((r)[13]), "=r"((r)[14]), "=r"((r)[15]), \
          "=r"((r)[16]), "=r"((r)[17]), "=r"((r)[18]), "=r"((r)[19]), \
          "=r"((r)[20]), "=r"((r)[21]), "=r"((r)[22]), "=r"((r)[23]), \
          "=r"((r)[24]), "=r"((r)[25]), "=r"((r)[26]), "=r"((r)[27]), \
          "=r"((r)[28]), "=r"((r)[29]), "=r"((r)[30]), "=r"((r)[31]) \
        : "r"(addr))

#define STTM_X64(addr, r) \
    asm volatile( \
        "tcgen05.st.sync.aligned.32x32b.x64.b32 [%0], " \
        "{%1, %2, %3, %4, %5, %6, %7, %8, " \
        " %9, %10, %11, %12, %13, %14, %15, %16, " \
        " %17, %18, %19, %20, %21, %22, %23, %24, " \
        " %25, %26, %27, %28, %29, %30, %31, %32, " \
        " %33, %34, %35, %36, %37, %38, %39, %40, " \
        " %41, %42, %43, %44, %45, %46, %47, %48, " \
        " %49, %50, %51, %52, %53, %54, %55, %56, " \
        " %57, %58, %59, %60, %61, %62, %63, %64};" \
        :: "r"(addr), \
           "r"((r)[0]),  "r"((r)[1]),  "r"((r)[2]),  "r"((r)[3]), \
           "r"((r)[4]),  "r"((r)[5]),  "r"((r)[6]),  "r"((r)[7]), \
           "r"((r)[8]),  "r"((r)[9]),  "r"((r)[10]), "r"((r)[11]), \
           "r"((r)[12]), "r"((r)[13]), "r"((r)[14]), "r"((r)[15]), \
           "r"((r)[16]), "r"((r)[17]), "r"((r)[18]), "r"((r)[19]), \
           "r"((r)[20]), "r"((r)[21]), "r"((r)[22]), "r"((r)[23]), \
           "r"((r)[24]), "r"((r)[25]), "r"((r)[26]), "r"((r)[27]), \
           "r"((r)[28]), "r"((r)[29]), "r"((r)[30]), "r"((r)[31]), \
           "r"((r)[32]), "r"((r)[33]), "r"((r)[34]), "r"((r)[35]), \
           "r"((r)[36]), "r"((r)[37]), "r"((r)[38]), "r"((r)[39]), \
           "r"((r)[40]), "r"((r)[41]), "r"((r)[42]), "r"((r)[43]), \
           "r"((r)[44]), "r"((r)[45]), "r"((r)[46]), "r"((r)[47]), \
           "r"((r)[48]), "r"((r)[49]), "r"((r)[50]), "r"((r)[51]), \
           "r"((r)[52]), "r"((r)[53]), "r"((r)[54]), "r"((r)[55]), \
           "r"((r)[56]), "r"((r)[57]), "r"((r)[58]), "r"((r)[59]), \
           "r"((r)[60]), "r"((r)[61]), "r"((r)[62]), "r"((r)[63]) \
        : "memory")

// SMEM descriptor: SW128, Blackwell, LBO=1, SBO=64
__device__ __forceinline__ uint64_t make_desc(uint32_t addr) {
    const uint64_t base = (uint64_t(2) << 61) | (uint64_t(1) << 46) |
                          (uint64_t(64) << 32) | (uint64_t(1) << 16);
    return base | ((uint64_t)(addr >> 4) & 0x3FFF);
}
#endif  // HAS_TCGEN05

// ---------------- degree / norm ----------------
__global__ void k_deg_init(int* indeg, int n) {
    int g = blockIdx.x * blockDim.x + threadIdx.x;
    if (g < n) indeg[g] = 1;
}
__global__ void k_deg_count(const int* __restrict__ ei, int* indeg, int E) {
    int g = blockIdx.x * blockDim.x + threadIdx.x;
    if (g < E) atomicAdd(&indeg[ei[E + g]], 1);
}
__global__ void k_dinv(const int* __restrict__ indeg, float* dinv, int n) {
    int g = blockIdx.x * blockDim.x + threadIdx.x;
    if (g < n) dinv[g] = rsqrtf((float)indeg[g]);
}

// ---------------- exclusive scan ----------------
__global__ void k_scan1(const int* __restrict__ in, int* out, int* bsum, int n) {
    __shared__ int s[1024];
    int g = blockIdx.x * 1024 + threadIdx.x;
    int v = (g < n) ? in[g] : 0;
    s[threadIdx.x] = v;
    __syncthreads();
    for (int off = 1; off < 1024; off <<= 1) {
        int t = (threadIdx.x >= off) ? s[threadIdx.x - off] : 0;
        __syncthreads();
        s[threadIdx.x] += t;
        __syncthreads();
    }
    if (g < n) out[g] = s[threadIdx.x] - v;
    if (threadIdx.x == 1023) bsum[blockIdx.x] = s[1023];
}
__global__ void k_scan2(int* bsum, int nb) {
    __shared__ int s[1024];
    int v = (threadIdx.x < nb) ? bsum[threadIdx.x] : 0;
    s[threadIdx.x] = v;
    __syncthreads();
    for (int off = 1; off < 1024; off <<= 1) {
        int t = (threadIdx.x >= off) ? s[threadIdx.x - off] : 0;
        __syncthreads();
        s[threadIdx.x] += t;
        __syncthreads();
    }
    if (threadIdx.x < nb) bsum[threadIdx.x] = s[threadIdx.x] - v;
}
__global__ void k_scan3(int* rowptr, const int* __restrict__ bsum, int* cursor,
                        int n, int total) {
    int g = blockIdx.x * 1024 + threadIdx.x;
    if (g < n) {
        int r = rowptr[g] + bsum[g >> 10];
        rowptr[g] = r;
        cursor[g] = r;
    }
    if (g == 0) rowptr[n] = total;
}

// ---------------- CSR fill ----------------
__global__ void k_fill(const int* __restrict__ ei, int E, int n,
                       const float* __restrict__ dinv, int* cursor,
                       int* esrc, float* enorm) {
    int g = blockIdx.x * blockDim.x + threadIdx.x;
    if (g < E) {
        int s = ei[g];
        int d = ei[E + g];
        int pos = atomicAdd(&cursor[d], 1);
        esrc[pos] = s;
        enorm[pos] = dinv[s] * dinv[d];
    } else if (g < E + n) {
        int i = g - E;
        int pos = atomicAdd(&cursor[i], 1);
        esrc[pos] = i;
        float dv = dinv[i];
        enorm[pos] = dv * dv;
    }
}

// ---------------- persistent pipelined tcgen05 GEMM (RS mode, fp16 split) ---
// C_half[n][FOUT] = A_fp32[n][128] @ W_fp32[128][FOUT].
// A, W split to fp16 hi/lo (residual ~2^-22); D = Ah*Wh + Ah*Wl + Al*Wh,
// fp32 accum in TMEM.  Output converted to fp16.
// TMEM double buffer: A[p] at cols p*128 (+64 lo), D[p] at 256 + p*128.
template <int FOUT>
__global__ void __launch_bounds__(256, 1) __cluster_dims__(1, 1, 1) k_gemm_tc(
    const float* __restrict__ A, const float* __restrict__ W,
    __half* __restrict__ C, int n) {
#if HAS_TCGEN05
    extern __shared__ char smem[];
    constexpr int BH_OFF = 1024;
    constexpr int BL_OFF = BH_OFF + FOUT * 128 * 2;
    // kind::f16, f16 inputs: dtype F32=1 (bit4), atype=btype=F16=0
    constexpr uint32_t IDESC = (1u << 4) | ((FOUT / 8) << 17) | (8u << 24);

    uint32_t sbase = smem_u32(smem);
    int tid = threadIdx.x;
    int wid = tid >> 5;
    int lane = tid & 31;

    if (wid == 0) TC_ALLOC(sbase, 512);
    if (tid == 0) { MBAR_INIT(sbase + 8, 1); MBAR_INIT(sbase + 16, 1); }
    __syncthreads();
    uint32_t tmem;
    asm volatile("ld.shared.b32 %0, [%1];" : "=r"(tmem) : "r"(sbase));

    // ---- B fill once: split W[k][FOUT] into fp16 hi/lo, blocked SW128 ----
    for (int g = tid; g < FOUT * 16; g += 256) {
        int r = g >> 4;
        int k8 = (g & 15) << 3;
        uint32_t hu[4], lu[4];
#pragma unroll
        for (int j = 0; j < 4; j++) {
            float x0 = W[(size_t)(k8 + 2 * j) * FOUT + r];
            float x1 = W[(size_t)(k8 + 2 * j + 1) * FOUT + r];
            __half h0 = __float2half_rn(x0);
            __half h1 = __float2half_rn(x1);
            float l0 = x0 - __half2float(h0);
            float l1 = x1 - __half2float(h1);
            __half2 hp = __halves2half2(h0, h1);
            __half2 lp = __halves2half2(__float2half_rn(l0), __float2half_rn(l1));
            hu[j] = *reinterpret_cast<uint32_t*>(&hp);
            lu[j] = *reinterpret_cast<uint32_t*>(&lp);
        }
        int atom = (r >> 3) + (k8 >> 6) * (FOUT >> 3);
        uint32_t boff = atom * 1024 + (r & 7) * 128 + (k8 & 63) * 2;
        uint32_t sw = boff ^ ((boff >> 3) & 0x70);
        *(uint4*)(smem + BH_OFF + sw) = make_uint4(hu[0], hu[1], hu[2], hu[3]);
        *(uint4*)(smem + BL_OFF + sw) = make_uint4(lu[0], lu[1], lu[2], lu[3]);
    }
    FENCE_ASYNC_SHARED();
    __syncthreads();

    uint64_t bh = make_desc(sbase + BH_OFF);
    uint64_t bl = make_desc(sbase + BL_OFF);
    const uint64_t BCOL = (uint64_t)FOUT * 8;

    int it = 0;
    int prev_bm = 0;
    for (int tile = blockIdx.x; tile * 128 < n; tile += gridDim.x, it++) {
        int p = it & 1;
        int bm = tile * 128;
        uint32_t tm_a = tmem + p * 128;
        uint32_t tm_d = tmem + 256 + p * 128;

        // ---- A split (fp16 hi/lo) + STTM into buf p ----
        if (tid < 128) {
            int row = bm + tid;
            const float4* a4 = (const float4*)&A[(size_t)row * 128];
            uint32_t v[64];
#pragma unroll
            for (int i = 0; i < 32; i++) {
                float4 f = (row < n) ? a4[i] : make_float4(0.f, 0.f, 0.f, 0.f);
                __half2 p0 = __halves2half2(__float2half_rn(f.x), __float2half_rn(f.y));
                __half2 p1 = __halves2half2(__float2half_rn(f.z), __float2half_rn(f.w));
                v[2 * i]     = *reinterpret_cast<uint32_t*>(&p0);
                v[2 * i + 1] = *reinterpret_cast<uint32_t*>(&p1);
            }
            STTM_X64(tm_a, v);
            TC_WAIT_ST();
#pragma unroll
            for (int i = 0; i < 32; i++) {
                float4 f = (row < n) ? a4[i] : make_float4(0.f, 0.f, 0.f, 0.f);
                float lx = f.x - __half2float(__float2half_rn(f.x));
                float ly = f.y - __half2float(__float2half_rn(f.y));
                float lz = f.z - __half2float(__float2half_rn(f.z));
                float lw = f.w - __half2float(__float2half_rn(f.w));
                __half2 p0 = __halves2half2(__float2half_rn(lx), __float2half_rn(ly));
                __half2 p1 = __halves2half2(__float2half_rn(lz), __float2half_rn(lw));
                v[2 * i]     = *reinterpret_cast<uint32_t*>(&p0);
                v[2 * i + 1] = *reinterpret_cast<uint32_t*>(&p1);
            }
            STTM_X64(tm_a + 64, v);
            TC_WAIT_ST();
        }
        TC_FENCE_BEFORE();
        __syncthreads();

        // ---- MMA: 3 term-pairs x 8 K-steps (warp 0, elected thread) ----
        if (wid == 0) {
            TC_FENCE_AFTER();
            if (elect_one()) {
#pragma unroll
                for (int t = 0; t < 3; t++) {
                    uint32_t a_base = tm_a + ((t == 2) ? 64 : 0);
                    uint64_t b_base = (t == 1) ? bl : bh;
#pragma unroll
                    for (int k = 0; k < 8; k++) {
                        uint64_t bd = b_base + ((k < 4) ? (uint64_t)(k * 2)
                                                        : BCOL + (uint64_t)((k - 4) * 2));
                        mma_f16_rs(tm_d, a_base + k * 8, bd, IDESC,
                                   (t > 0 || k > 0) ? 1u : 0u);
                    }
                }
                TC_COMMIT(sbase + 8 + 8 * p);
            }
        }

        // ---- epilogue of tile it-1 (overlaps current MMA): fp16 out ----
        if (it > 0) {
            int q = p ^ 1;
            mbar_wait(sbase + 8 + 8 * q, ((it - 1) >> 1) & 1);
            TC_FENCE_AFTER();
            if (wid < 4) {
                int row = prev_bm + wid * 32 + lane;
                uint32_t tm_dq = tmem + 256 + q * 128;
                for (int c0 = 0; c0 < FOUT; c0 += 32) {
                    uint32_t r[32];
                    LDTM_X32(r, tm_dq + c0);
                    TC_WAIT_LD();
                    if (row < n) {
                        __half* dst = &C[(size_t)row * FOUT + c0];
                        uint32_t o[16];
#pragma unroll
                        for (int j = 0; j < 16; j++) {
                            __half2 hp = __halves2half2(
                                __float2half_rn(__uint_as_float(r[2 * j])),
                                __float2half_rn(__uint_as_float(r[2 * j + 1])));
                            o[j] = *reinterpret_cast<uint32_t*>(&hp);
                        }
#pragma unroll
                        for (int j = 0; j < 4; j++)
                            *(uint4*)(dst + j * 8) =
                                make_uint4(o[4 * j], o[4 * j + 1], o[4 * j + 2], o[4 * j + 3]);
                    }
                }
                TC_FENCE_BEFORE();
            }
        }
        prev_bm = bm;
    }

    // ---- final epilogue ----
    if (it > 0) {
        int q = (it - 1) & 1;
        mbar_wait(sbase + 8 + 8 * q, ((it - 1) >> 1) & 1);
        TC_FENCE_AFTER();
        if (wid < 4) {
            int row = prev_bm + wid * 32 + lane;
            uint32_t tm_dq = tmem + 256 + q * 128;
            for (int c0 = 0; c0 < FOUT; c0 += 32) {
                uint32_t r[32];
                LDTM_X32(r, tm_dq + c0);
                TC_WAIT_LD();
                if (row < n) {
                    __half* dst = &C[(size_t)row * FOUT + c0];
                    uint32_t o[16];
#pragma unroll
                    for (int j = 0; j < 16; j++) {
                        __half2 hp = __halves2half2(
                            __float2half_rn(__uint_as_float(r[2 * j])),
                            __float2half_rn(__uint_as_float(r[2 * j + 1])));
                        o[j] = *reinterpret_cast<uint32_t*>(&hp);
                    }
#pragma unroll
                    for (int j = 0; j < 4; j++)
                        *(uint4*)(dst + j * 8) =
                            make_uint4(o[4 * j], o[4 * j + 1], o[4 * j + 2], o[4 * j + 3]);
                }
            }
            TC_FENCE_BEFORE();
        }
    }
    __syncthreads();
    if (tid == 0) { MBAR_INVAL(sbase + 8); MBAR_INVAL(sbase + 16); }
    __syncthreads();
    if (wid == 0) TC_DEALLOC(tmem, 512);
#else
    // Portable-PTX fallback (never executed on GB300).
    int tid = threadIdx.x;
    for (int tile = blockIdx.x; tile * 128 < n; tile += gridDim.x) {
        int bm = tile * 128;
        for (int idx = tid; idx < 128 * FOUT; idx += 256) {
            int r = bm + idx / FOUT;
            int c = idx % FOUT;
            if (r < n) {
                float acc = 0.f;
                for (int k = 0; k < 128; k++)
                    acc += A[(size_t)r * 128 + k] * W[(size_t)k * FOUT + c];
                C[(size_t)r * FOUT + c] = __float2half_rn(acc);
            }
        }
    }
#endif
}

// ---------------- aggregation (fp16 gather, fp32 accumulate) --------------
__global__ void k_agg128h(const __half* __restrict__ t, const int* __restrict__ rowptr,
                          const int* __restrict__ esrc, const float* __restrict__ enorm,
                          const float* __restrict__ bias, float* __restrict__ out,
                          int n, int dorelu) {
    int w = (blockIdx.x * blockDim.x + threadIdx.x) >> 5;
    if (w >= n) return;
    int lane = threadIdx.x & 31;
    int beg = rowptr[w], end = rowptr[w + 1];
    float ax = 0.f, ay = 0.f, az = 0.f, aw = 0.f;
    int e = beg;
    for (; e + 1 < end; e += 2) {
        int s0 = esrc[e], s1 = esrc[e + 1];
        float n0 = enorm[e], n1 = enorm[e + 1];
        uint2 u0 = *(const uint2*)&t[(size_t)s0 * 128 + lane * 4];
        uint2 u1 = *(const uint2*)&t[(size_t)s1 * 128 + lane * 4];
        float2 a0 = __half22float2(*reinterpret_cast<__half2*>(&u0.x));
        float2 b0 = __half22float2(*reinterpret_cast<__half2*>(&u0.y));
        float2 a1 = __half22float2(*reinterpret_cast<__half2*>(&u1.x));
        float2 b1 = __half22float2(*reinterpret_cast<__half2*>(&u1.y));
        ax += a0.x * n0 + a1.x * n1;
        ay += a0.y * n0 + a1.y * n1;
        az += b0.x * n0 + b1.x * n1;
        aw += b0.y * n0 + b1.y * n1;
    }
    if (e < end) {
        int s0 = esrc[e];
        float n0 = enorm[e];
        uint2 u0 = *(const uint2*)&t[(size_t)s0 * 128 + lane * 4];
        float2 a0 = __half22float2(*reinterpret_cast<__half2*>(&u0.x));
        float2 b0 = __half22float2(*reinterpret_cast<__half2*>(&u0.y));
        ax += a0.x * n0;
        ay += a0.y * n0;
        az += b0.x * n0;
        aw += b0.y * n0;
    }
    float4 b4 = *(const float4*)&bias[lane * 4];
    ax += b4.x; ay += b4.y; az += b4.z; aw += b4.w;
    if (dorelu) {
        ax = fmaxf(ax, 0.f); ay = fmaxf(ay, 0.f);
        az = fmaxf(az, 0.f); aw = fmaxf(aw, 0.f);
    }
    *(float4*)&out[(size_t)w * 128 + lane * 4] = make_float4(ax, ay, az, aw);
}

__global__ void k_agg64h(const __half* __restrict__ t, const int* __restrict__ rowptr,
                         const int* __restrict__ esrc, const float* __restrict__ enorm,
                         const float* __restrict__ bias, float* __restrict__ out,
                         int n, int dorelu) {
    int w = (blockIdx.x * blockDim.x + threadIdx.x) >> 5;
    if (w >= n) return;
    int lane = threadIdx.x & 31;
    int beg = rowptr[w], end = rowptr[w + 1];
    float ax = 0.f, ay = 0.f;
    int e = beg;
    for (; e + 1 < end; e += 2) {
        int s0 = esrc[e], s1 = esrc[e + 1];
        float n0 = enorm[e], n1 = enorm[e + 1];
        uint32_t u0 = *(const uint32_t*)&t[(size_t)s0 * 64 + lane * 2];
        uint32_t u1 = *(const uint32_t*)&t[(size_t)s1 * 64 + lane * 2];
        float2 a0 = __half22float2(*reinterpret_cast<__half2*>(&u0));
        float2 a1 = __half22float2(*reinterpret_cast<__half2*>(&u1));
        ax += a0.x * n0 + a1.x * n1;
        ay += a0.y * n0 + a1.y * n1;
    }
    if (e < end) {
        int s0 = esrc[e];
        float n0 = enorm[e];
        uint32_t u0 = *(const uint32_t*)&t[(size_t)s0 * 64 + lane * 2];
        float2 a0 = __half22float2(*reinterpret_cast<__half2*>(&u0));
        ax += a0.x * n0;
        ay += a0.y * n0;
    }
    float2 b2 = *(const float2*)&bias[lane * 2];
    ax += b2.x; ay += b2.y;
    if (dorelu) { ax = fmaxf(ax, 0.f); ay = fmaxf(ay, 0.f); }
    *(float2*)&out[(size_t)w * 64 + lane * 2] = make_float2(ax, ay);
}

// ---------------- host ----------------
extern "C" void kernel_launch(void* const* d_in, const int* in_sizes, int n_in,
                              void* d_out, int out_size) {
    const float* x   = (const float*)d_in[0];
    const int*   ei  = (const int*)d_in[1];
    const float* W1  = (const float*)d_in[2];
    const float* b1  = (const float*)d_in[3];
    const float* Wm1 = (const float*)d_in[4];
    const float* bm1 = (const float*)d_in[5];
    const float* Wm2 = (const float*)d_in[6];
    const float* bm2 = (const float*)d_in[7];
    const float* W2  = (const float*)d_in[8];
    const float* b2  = (const float*)d_in[9];

    int n = in_sizes[0] / 128;
    int E = in_sizes[1] / 2;

    void* p;
    int *indeg, *rowptr, *cursor, *bsum, *esrc;
    float *dinv, *enorm, *bufA, *bufB;
    __half* bufT;
    cudaGetSymbolAddress(&p, g_indeg);  indeg  = (int*)p;
    cudaGetSymbolAddress(&p, g_dinv);   dinv   = (float*)p;
    cudaGetSymbolAddress(&p, g_rowptr); rowptr = (int*)p;
    cudaGetSymbolAddress(&p, g_cursor); cursor = (int*)p;
    cudaGetSymbolAddress(&p, g_bsum);   bsum   = (int*)p;
    cudaGetSymbolAddress(&p, g_esrc);   esrc   = (int*)p;
    cudaGetSymbolAddress(&p, g_enorm);  enorm  = (float*)p;
    cudaGetSymbolAddress(&p, g_bufA);   bufA   = (float*)p;
    cudaGetSymbolAddress(&p, g_bufB);   bufB   = (float*)p;
    cudaGetSymbolAddress(&p, g_bufT);   bufT   = (__half*)p;

    int nb = (n + 1023) / 1024;

    // ---- graph normalization + CSR build ----
    k_deg_init<<<(n + 255) / 256, 256>>>(indeg, n);
    k_deg_count<<<(E + 255) / 256, 256>>>(ei, indeg, E);
    k_dinv<<<(n + 255) / 256, 256>>>(indeg, dinv, n);
    k_scan1<<<nb, 1024>>>(indeg, rowptr, bsum, n);
    k_scan2<<<1, 1024>>>(bsum, nb);
    k_scan3<<<nb, 1024>>>(rowptr, bsum, cursor, n, E + n);
    k_fill<<<(E + n + 255) / 256, 256>>>(ei, E, n, dinv, cursor, esrc, enorm);

    int gblocks = (n + 127) / 128;
    int ggrid = gblocks < 148 ? gblocks : 148;    // persistent CTAs
    int agg_blocks = (n * 32 + 255) / 256;
    const int SMEM128 = 1024 + 2 * 128 * 128 * 2;  // 66560
    const int SMEM64  = 1024 + 2 * 64 * 128 * 2;   // 33792
    cudaFuncSetAttribute(k_gemm_tc<128>, cudaFuncAttributeMaxDynamicSharedMemorySize, SMEM128);
    cudaFuncSetAttribute(k_gemm_tc<64>,  cudaFuncAttributeMaxDynamicSharedMemorySize, SMEM64);

    // ---- layer 1 ----
    k_gemm_tc<128><<<ggrid, 256, SMEM128>>>(x, W1, bufT, n);
    k_agg128h<<<agg_blocks, 256>>>(bufT, rowptr, esrc, enorm, b1, bufA, n, 1);
    // ---- layer 2 ----
    k_gemm_tc<128><<<ggrid, 256, SMEM128>>>(bufA, Wm1, bufT, n);
    k_agg128h<<<agg_blocks, 256>>>(bufT, rowptr, esrc, enorm, bm1, bufB, n, 1);
    // ---- layer 3 ----
    k_gemm_tc<128><<<ggrid, 256, SMEM128>>>(bufB, Wm2, bufT, n);
    k_agg128h<<<agg_blocks, 256>>>(bufT, rowptr, esrc, enorm, bm2, bufA, n, 1);
    // ---- layer 4 (64 out, no relu) ----
    k_gemm_tc<64><<<ggrid, 256, SMEM64>>>(bufA, W2, bufT, n);
    k_agg64h<<<agg_blocks, 256>>>(bufT, rowptr, esrc, enorm, b2, (float*)d_out, n, 0);
}

// round 9
// speedup vs baseline: 2.1529x; 1.2225x over previous
#include <cuda_runtime.h>
#include <cuda_fp16.h>
#include <cstdint>
#include <cstddef>

#define NMAX 100000
#define EMAX 1600000
#define TOTMAX (EMAX + NMAX)

#if defined(__CUDA_ARCH_FEAT_SM103_ALL) || defined(__CUDA_ARCH_FEAT_SM100_ALL) || \
    defined(__CUDA_ARCH_FEAT_SM101_ALL)
#define HAS_TCGEN05 1
#else
#define HAS_TCGEN05 0
#endif

// ---------------- device scratch ----------
__device__ int    g_indeg[NMAX];
__device__ float  g_dinv[NMAX];
__device__ int    g_rowptr[NMAX + 1];
__device__ int    g_cursor[NMAX];
__device__ int    g_bsum[1024];
__device__ int    g_esrc[TOTMAX];
__device__ float  g_enorm[TOTMAX];
__device__ __half g_bufA[(size_t)NMAX * 128];   // h (fp16) ping
__device__ __half g_bufB[(size_t)NMAX * 128];   // h (fp16) pong
__device__ __half g_bufT[(size_t)NMAX * 128];   // t = X@W (fp16)

// ---------------- PTX helpers ----------------
__device__ __forceinline__ uint32_t smem_u32(const void* p) {
    uint32_t a;
    asm("{ .reg .u64 t; cvta.to.shared.u64 t, %1; cvt.u32.u64 %0, t; }" : "=r"(a) : "l"(p));
    return a;
}

#if HAS_TCGEN05
__device__ __forceinline__ uint32_t elect_one() {
    uint32_t pred;
    asm volatile("{\n .reg .pred p;\n elect.sync _|p, 0xFFFFFFFF;\n selp.b32 %0, 1, 0, p;\n}"
                 : "=r"(pred));
    return pred;
}
#define TC_ALLOC(smem_addr, ncols) \
    asm volatile("tcgen05.alloc.cta_group::1.sync.aligned.shared::cta.b32 [%0], %1;" \
                 :: "r"(smem_addr), "r"(ncols) : "memory")
#define TC_DEALLOC(tmem, ncols) \
    asm volatile("tcgen05.dealloc.cta_group::1.sync.aligned.b32 %0, %1;" :: "r"(tmem), "r"(ncols))
#define TC_COMMIT(mbar) \
    asm volatile("tcgen05.commit.cta_group::1.mbarrier::arrive::one.shared::cluster.b64 [%0];" \
                 :: "r"(mbar) : "memory")
#define TC_WAIT_LD() asm volatile("tcgen05.wait::ld.sync.aligned;" ::: "memory")
#define TC_WAIT_ST() asm volatile("tcgen05.wait::st.sync.aligned;" ::: "memory")
#define TC_FENCE_BEFORE() asm volatile("tcgen05.fence::before_thread_sync;" ::: "memory")
#define TC_FENCE_AFTER() asm volatile("tcgen05.fence::after_thread_sync;" ::: "memory")
#define FENCE_ASYNC_SHARED() asm volatile("fence.proxy.async.shared::cta;" ::: "memory")
#define MBAR_INIT(mbar, cnt) \
    asm volatile("mbarrier.init.shared.b64 [%0], %1;" :: "r"(mbar), "r"(cnt) : "memory")
#define MBAR_INVAL(mbar) \
    asm volatile("mbarrier.inval.shared.b64 [%0];" :: "r"(mbar) : "memory")

__device__ __forceinline__ void mbar_wait(uint32_t mbar, uint32_t parity) {
    asm volatile(
        "{\n .reg .pred P1;\n"
        "WAIT_LOOP_%=:\n"
        " mbarrier.try_wait.parity.acquire.cta.shared::cta.b64 P1, [%0], %1, 0x989680;\n"
        " @P1 bra.uni WAIT_DONE_%=;\n"
        " bra.uni WAIT_LOOP_%=;\n"
        "WAIT_DONE_%=:\n}"
        :: "r"(mbar), "r"(parity) : "memory");
}

__device__ __forceinline__ void mma_f16_rs(uint32_t d, uint32_t a_tmem, uint64_t b,
                                           uint32_t idesc, uint32_t en) {
    uint32_t z = 0;
    asm volatile(
        "{\n .reg .pred p;\n setp.ne.u32 p, %5, 0;\n"
        " tcgen05.mma.cta_group::1.kind::f16 [%0], [%1], %2, %3, {%4, %4, %4, %4}, p;\n}"
        :: "r"(d), "r"(a_tmem), "l"(b), "r"(idesc), "r"(z), "r"(en) : "memory");
}

#define LDTM_X32(r, addr) \
    asm volatile( \
        "tcgen05.ld.sync.aligned.32x32b.x32.b32 " \
        "{%0, %1, %2, %3, %4, %5, %6, %7, %8, %9, %10, %11, %12, %13, %14, %15, " \
        " %16, %17, %18, %19, %20, %21, %22, %23, %24, %25, %26, %27, %28, %29, %30, %31}, [%32];" \
        : "=r"((r)[0]),  "=r"((r)[1]),  "=r"((r)[2]),  "=r"((r)[3]), \
          "=r"((r)[4]),  "=r"((r)[5]),  "=r"((r)[6]),  "=r"((r)[7]), \
          "=r"((r)[8]),  "=r"((r)[9]),  "=r"((r)[10]), "=r"((r)[11]), \
          "=r"((r)[12]), "=r"((r)[13]), "=r"((r)[14]), "=r"((r)[15]), \
          "=r"((r)[16]), "=r"((r)[17]), "=r"((r)[18]), "=r"((r)[19]), \
          "=r"((r)[20]), "=r"((r)[21]), "=r"((r)[22]), "=r"((r)[23]), \
          "=r"((r)[24]), "=r"((r)[25]), "=r"((r)[26]), "=r"((r)[27]), \
          "=r"((r)[28]), "=r"((r)[29]), "=r"((r)[30]), "=r"((r)[31]) \
        : "r"(addr))

#define STTM_X64(addr, r) \
    asm volatile( \
        "tcgen05.st.sync.aligned.32x32b.x64.b32 [%0], " \
        "{%1, %2, %3, %4, %5, %6, %7, %8, " \
        " %9, %10, %11, %12, %13, %14, %15, %16, " \
        " %17, %18, %19, %20, %21, %22, %23, %24, " \
        " %25, %26, %27, %28, %29, %30, %31, %32, " \
        " %33, %34, %35, %36, %37, %38, %39, %40, " \
        " %41, %42, %43, %44, %45, %46, %47, %48, " \
        " %49, %50, %51, %52, %53, %54, %55, %56, " \
        " %57, %58, %59, %60, %61, %62, %63, %64};" \
        :: "r"(addr), \
           "r"((r)[0]),  "r"((r)[1]),  "r"((r)[2]),  "r"((r)[3]), \
           "r"((r)[4]),  "r"((r)[5]),  "r"((r)[6]),  "r"((r)[7]), \
           "r"((r)[8]),  "r"((r)[9]),  "r"((r)[10]), "r"((r)[11]), \
           "r"((r)[12]), "r"((r)[13]), "r"((r)[14]), "r"((r)[15]), \
           "r"((r)[16]), "r"((r)[17]), "r"((r)[18]), "r"((r)[19]), \
           "r"((r)[20]), "r"((r)[21]), "r"((r)[22]), "r"((r)[23]), \
           "r"((r)[24]), "r"((r)[25]), "r"((r)[26]), "r"((r)[27]), \
           "r"((r)[28]), "r"((r)[29]), "r"((r)[30]), "r"((r)[31]), \
           "r"((r)[32]), "r"((r)[33]), "r"((r)[34]), "r"((r)[35]), \
           "r"((r)[36]), "r"((r)[37]), "r"((r)[38]), "r"((r)[39]), \
           "r"((r)[40]), "r"((r)[41]), "r"((r)[42]), "r"((r)[43]), \
           "r"((r)[44]), "r"((r)[45]), "r"((r)[46]), "r"((r)[47]), \
           "r"((r)[48]), "r"((r)[49]), "r"((r)[50]), "r"((r)[51]), \
           "r"((r)[52]), "r"((r)[53]), "r"((r)[54]), "r"((r)[55]), \
           "r"((r)[56]), "r"((r)[57]), "r"((r)[58]), "r"((r)[59]), \
           "r"((r)[60]), "r"((r)[61]), "r"((r)[62]), "r"((r)[63]) \
        : "memory")

// SMEM descriptor: SW128, Blackwell, LBO=1, SBO=64
__device__ __forceinline__ uint64_t make_desc(uint32_t addr) {
    const uint64_t base = (uint64_t(2) << 61) | (uint64_t(1) << 46) |
                          (uint64_t(64) << 32) | (uint64_t(1) << 16);
    return base | ((uint64_t)(addr >> 4) & 0x3FFF);
}
#endif  // HAS_TCGEN05

// ---------------- degree / norm ----------------
__global__ void k_deg_init(int* indeg, int n) {
    int g = blockIdx.x * blockDim.x + threadIdx.x;
    if (g < n) indeg[g] = 1;
}
__global__ void k_deg_count(const int* __restrict__ ei, int* indeg, int E) {
    int g = blockIdx.x * blockDim.x + threadIdx.x;
    if (g < E) atomicAdd(&indeg[ei[E + g]], 1);
}
__global__ void k_dinv(const int* __restrict__ indeg, float* dinv, int n) {
    int g = blockIdx.x * blockDim.x + threadIdx.x;
    if (g < n) dinv[g] = rsqrtf((float)indeg[g]);
}

// ---------------- exclusive scan ----------------
__global__ void k_scan1(const int* __restrict__ in, int* out, int* bsum, int n) {
    __shared__ int s[1024];
    int g = blockIdx.x * 1024 + threadIdx.x;
    int v = (g < n) ? in[g] : 0;
    s[threadIdx.x] = v;
    __syncthreads();
    for (int off = 1; off < 1024; off <<= 1) {
        int t = (threadIdx.x >= off) ? s[threadIdx.x - off] : 0;
        __syncthreads();
        s[threadIdx.x] += t;
        __syncthreads();
    }
    if (g < n) out[g] = s[threadIdx.x] - v;
    if (threadIdx.x == 1023) bsum[blockIdx.x] = s[1023];
}
__global__ void k_scan2(int* bsum, int nb) {
    __shared__ int s[1024];
    int v = (threadIdx.x < nb) ? bsum[threadIdx.x] : 0;
    s[threadIdx.x] = v;
    __syncthreads();
    for (int off = 1; off < 1024; off <<= 1) {
        int t = (threadIdx.x >= off) ? s[threadIdx.x - off] : 0;
        __syncthreads();
        s[threadIdx.x] += t;
        __syncthreads();
    }
    if (threadIdx.x < nb) bsum[threadIdx.x] = s[threadIdx.x] - v;
}
__global__ void k_scan3(int* rowptr, const int* __restrict__ bsum, int* cursor,
                        int n, int total) {
    int g = blockIdx.x * 1024 + threadIdx.x;
    if (g < n) {
        int r = rowptr[g] + bsum[g >> 10];
        rowptr[g] = r;
        cursor[g] = r;
    }
    if (g == 0) rowptr[n] = total;
}

// ---------------- CSR fill ----------------
__global__ void k_fill(const int* __restrict__ ei, int E, int n,
                       const float* __restrict__ dinv, int* cursor,
                       int* esrc, float* enorm) {
    int g = blockIdx.x * blockDim.x + threadIdx.x;
    if (g < E) {
        int s = ei[g];
        int d = ei[E + g];
        int pos = atomicAdd(&cursor[d], 1);
        esrc[pos] = s;
        enorm[pos] = dinv[s] * dinv[d];
    } else if (g < E + n) {
        int i = g - E;
        int pos = atomicAdd(&cursor[i], 1);
        esrc[pos] = i;
        float dv = dinv[i];
        enorm[pos] = dv * dv;
    }
}

#if HAS_TCGEN05
// Shared epilogue: read D from TMEM, convert fp32->fp16, store.
template <int FOUT>
__device__ __forceinline__ void gemm_epilogue(uint32_t tm_d, int bm, int wid, int lane,
                                              __half* __restrict__ C, int n) {
    if (wid < 4) {
        int row = bm + wid * 32 + lane;
        for (int c0 = 0; c0 < FOUT; c0 += 32) {
            uint32_t r[32];
            LDTM_X32(r, tm_d + c0);
            TC_WAIT_LD();
            if (row < n) {
                __half* dst = &C[(size_t)row * FOUT + c0];
                uint32_t o[16];
#pragma unroll
                for (int j = 0; j < 16; j++) {
                    __half2 hp = __halves2half2(
                        __float2half_rn(__uint_as_float(r[2 * j])),
                        __float2half_rn(__uint_as_float(r[2 * j + 1])));
                    o[j] = *reinterpret_cast<uint32_t*>(&hp);
                }
#pragma unroll
                for (int j = 0; j < 4; j++)
                    *(uint4*)(dst + j * 8) =
                        make_uint4(o[4 * j], o[4 * j + 1], o[4 * j + 2], o[4 * j + 3]);
            }
        }
        TC_FENCE_BEFORE();
    }
}
#endif

// ---------------- GEMM #1: fp32 input, 3-term fp16 split (layer 1 only) ----
template <int FOUT>
__global__ void __launch_bounds__(256, 1) __cluster_dims__(1, 1, 1) k_gemm_f32(
    const float* __restrict__ A, const float* __restrict__ W,
    __half* __restrict__ C, int n) {
#if HAS_TCGEN05
    extern __shared__ char smem[];
    constexpr int BH_OFF = 1024;
    constexpr int BL_OFF = BH_OFF + FOUT * 128 * 2;
    constexpr uint32_t IDESC = (1u << 4) | ((FOUT / 8) << 17) | (8u << 24);

    uint32_t sbase = smem_u32(smem);
    int tid = threadIdx.x;
    int wid = tid >> 5;
    int lane = tid & 31;

    if (wid == 0) TC_ALLOC(sbase, 512);
    if (tid == 0) { MBAR_INIT(sbase + 8, 1); MBAR_INIT(sbase + 16, 1); }
    __syncthreads();
    uint32_t tmem;
    asm volatile("ld.shared.b32 %0, [%1];" : "=r"(tmem) : "r"(sbase));

    // B fill once: split W[k][FOUT] into fp16 hi/lo, blocked SW128
    for (int g = tid; g < FOUT * 16; g += 256) {
        int r = g >> 4;
        int k8 = (g & 15) << 3;
        uint32_t hu[4], lu[4];
#pragma unroll
        for (int j = 0; j < 4; j++) {
            float x0 = W[(size_t)(k8 + 2 * j) * FOUT + r];
            float x1 = W[(size_t)(k8 + 2 * j + 1) * FOUT + r];
            __half h0 = __float2half_rn(x0);
            __half h1 = __float2half_rn(x1);
            float l0 = x0 - __half2float(h0);
            float l1 = x1 - __half2float(h1);
            __half2 hp = __halves2half2(h0, h1);
            __half2 lp = __halves2half2(__float2half_rn(l0), __float2half_rn(l1));
            hu[j] = *reinterpret_cast<uint32_t*>(&hp);
            lu[j] = *reinterpret_cast<uint32_t*>(&lp);
        }
        int atom = (r >> 3) + (k8 >> 6) * (FOUT >> 3);
        uint32_t boff = atom * 1024 + (r & 7) * 128 + (k8 & 63) * 2;
        uint32_t sw = boff ^ ((boff >> 3) & 0x70);
        *(uint4*)(smem + BH_OFF + sw) = make_uint4(hu[0], hu[1], hu[2], hu[3]);
        *(uint4*)(smem + BL_OFF + sw) = make_uint4(lu[0], lu[1], lu[2], lu[3]);
    }
    FENCE_ASYNC_SHARED();
    __syncthreads();

    uint64_t bh = make_desc(sbase + BH_OFF);
    uint64_t bl = make_desc(sbase + BL_OFF);
    const uint64_t BCOL = (uint64_t)FOUT * 8;

    int it = 0;
    int prev_bm = 0;
    for (int tile = blockIdx.x; tile * 128 < n; tile += gridDim.x, it++) {
        int p = it & 1;
        int bm = tile * 128;
        uint32_t tm_a = tmem + p * 128;
        uint32_t tm_d = tmem + 256 + p * 128;

        if (tid < 128) {
            int row = bm + tid;
            const float4* a4 = (const float4*)&A[(size_t)row * 128];
            uint32_t v[64];
#pragma unroll
            for (int i = 0; i < 32; i++) {
                float4 f = (row < n) ? a4[i] : make_float4(0.f, 0.f, 0.f, 0.f);
                __half2 p0 = __halves2half2(__float2half_rn(f.x), __float2half_rn(f.y));
                __half2 p1 = __halves2half2(__float2half_rn(f.z), __float2half_rn(f.w));
                v[2 * i]     = *reinterpret_cast<uint32_t*>(&p0);
                v[2 * i + 1] = *reinterpret_cast<uint32_t*>(&p1);
            }
            STTM_X64(tm_a, v);
            TC_WAIT_ST();
#pragma unroll
            for (int i = 0; i < 32; i++) {
                float4 f = (row < n) ? a4[i] : make_float4(0.f, 0.f, 0.f, 0.f);
                float lx = f.x - __half2float(__float2half_rn(f.x));
                float ly = f.y - __half2float(__float2half_rn(f.y));
                float lz = f.z - __half2float(__float2half_rn(f.z));
                float lw = f.w - __half2float(__float2half_rn(f.w));
                __half2 p0 = __halves2half2(__float2half_rn(lx), __float2half_rn(ly));
                __half2 p1 = __halves2half2(__float2half_rn(lz), __float2half_rn(lw));
                v[2 * i]     = *reinterpret_cast<uint32_t*>(&p0);
                v[2 * i + 1] = *reinterpret_cast<uint32_t*>(&p1);
            }
            STTM_X64(tm_a + 64, v);
            TC_WAIT_ST();
        }
        TC_FENCE_BEFORE();
        __syncthreads();

        if (wid == 0) {
            TC_FENCE_AFTER();
            if (elect_one()) {
#pragma unroll
                for (int t = 0; t < 3; t++) {
                    uint32_t a_base = tm_a + ((t == 2) ? 64 : 0);
                    uint64_t b_base = (t == 1) ? bl : bh;
#pragma unroll
                    for (int k = 0; k < 8; k++) {
                        uint64_t bd = b_base + ((k < 4) ? (uint64_t)(k * 2)
                                                        : BCOL + (uint64_t)((k - 4) * 2));
                        mma_f16_rs(tm_d, a_base + k * 8, bd, IDESC,
                                   (t > 0 || k > 0) ? 1u : 0u);
                    }
                }
                TC_COMMIT(sbase + 8 + 8 * p);
            }
        }

        if (it > 0) {
            int q = p ^ 1;
            mbar_wait(sbase + 8 + 8 * q, ((it - 1) >> 1) & 1);
            TC_FENCE_AFTER();
            gemm_epilogue<FOUT>(tmem + 256 + q * 128, prev_bm, wid, lane, C, n);
        }
        prev_bm = bm;
    }
    if (it > 0) {
        int q = (it - 1) & 1;
        mbar_wait(sbase + 8 + 8 * q, ((it - 1) >> 1) & 1);
        TC_FENCE_AFTER();
        gemm_epilogue<FOUT>(tmem + 256 + q * 128, prev_bm, wid, lane, C, n);
    }
    __syncthreads();
    if (tid == 0) { MBAR_INVAL(sbase + 8); MBAR_INVAL(sbase + 16); }
    __syncthreads();
    if (wid == 0) TC_DEALLOC(tmem, 512);
#else
    int tid = threadIdx.x;
    for (int tile = blockIdx.x; tile * 128 < n; tile += gridDim.x) {
        int bm = tile * 128;
        for (int idx = tid; idx < 128 * FOUT; idx += 256) {
            int r = bm + idx / FOUT, c = idx % FOUT;
            if (r < n) {
                float acc = 0.f;
                for (int k = 0; k < 128; k++)
                    acc += A[(size_t)r * 128 + k] * W[(size_t)k * FOUT + c];
                C[(size_t)r * FOUT + c] = __float2half_rn(acc);
            }
        }
    }
#endif
}

// ---------------- GEMM #2: fp16 input, 2-term (layers 2..4) ----------------
// A exact fp16 => Al == 0 => D = A*Wh + A*Wl.
template <int FOUT>
__global__ void __launch_bounds__(256, 1) __cluster_dims__(1, 1, 1) k_gemm_f16(
    const __half* __restrict__ A, const float* __restrict__ W,
    __half* __restrict__ C, int n) {
#if HAS_TCGEN05
    extern __shared__ char smem[];
    constexpr int BH_OFF = 1024;
    constexpr int BL_OFF = BH_OFF + FOUT * 128 * 2;
    constexpr uint32_t IDESC = (1u << 4) | ((FOUT / 8) << 17) | (8u << 24);

    uint32_t sbase = smem_u32(smem);
    int tid = threadIdx.x;
    int wid = tid >> 5;
    int lane = tid & 31;

    if (wid == 0) TC_ALLOC(sbase, 512);
    if (tid == 0) { MBAR_INIT(sbase + 8, 1); MBAR_INIT(sbase + 16, 1); }
    __syncthreads();
    uint32_t tmem;
    asm volatile("ld.shared.b32 %0, [%1];" : "=r"(tmem) : "r"(sbase));

    for (int g = tid; g < FOUT * 16; g += 256) {
        int r = g >> 4;
        int k8 = (g & 15) << 3;
        uint32_t hu[4], lu[4];
#pragma unroll
        for (int j = 0; j < 4; j++) {
            float x0 = W[(size_t)(k8 + 2 * j) * FOUT + r];
            float x1 = W[(size_t)(k8 + 2 * j + 1) * FOUT + r];
            __half h0 = __float2half_rn(x0);
            __half h1 = __float2half_rn(x1);
            float l0 = x0 - __half2float(h0);
            float l1 = x1 - __half2float(h1);
            __half2 hp = __halves2half2(h0, h1);
            __half2 lp = __halves2half2(__float2half_rn(l0), __float2half_rn(l1));
            hu[j] = *reinterpret_cast<uint32_t*>(&hp);
            lu[j] = *reinterpret_cast<uint32_t*>(&lp);
        }
        int atom = (r >> 3) + (k8 >> 6) * (FOUT >> 3);
        uint32_t boff = atom * 1024 + (r & 7) * 128 + (k8 & 63) * 2;
        uint32_t sw = boff ^ ((boff >> 3) & 0x70);
        *(uint4*)(smem + BH_OFF + sw) = make_uint4(hu[0], hu[1], hu[2], hu[3]);
        *(uint4*)(smem + BL_OFF + sw) = make_uint4(lu[0], lu[1], lu[2], lu[3]);
    }
    FENCE_ASYNC_SHARED();
    __syncthreads();

    uint64_t bh = make_desc(sbase + BH_OFF);
    uint64_t bl = make_desc(sbase + BL_OFF);
    const uint64_t BCOL = (uint64_t)FOUT * 8;

    int it = 0;
    int prev_bm = 0;
    for (int tile = blockIdx.x; tile * 128 < n; tile += gridDim.x, it++) {
        int p = it & 1;
        int bm = tile * 128;
        uint32_t tm_a = tmem + p * 64;          // A: 64 cols (128 fp16)
        uint32_t tm_d = tmem + 256 + p * 128;

        // A load (fp16 direct) + STTM into buf p
        if (tid < 128) {
            int row = bm + tid;
            const uint4* a4 = (const uint4*)&A[(size_t)row * 128];
            uint32_t v[64];
#pragma unroll
            for (int i = 0; i < 16; i++) {
                uint4 u = (row < n) ? a4[i] : make_uint4(0, 0, 0, 0);
                v[4 * i] = u.x; v[4 * i + 1] = u.y; v[4 * i + 2] = u.z; v[4 * i + 3] = u.w;
            }
            STTM_X64(tm_a, v);
            TC_WAIT_ST();
        }
        TC_FENCE_BEFORE();
        __syncthreads();

        // MMA: 2 terms x 8 K-steps
        if (wid == 0) {
            TC_FENCE_AFTER();
            if (elect_one()) {
#pragma unroll
                for (int t = 0; t < 2; t++) {
                    uint64_t b_base = (t == 1) ? bl : bh;
#pragma unroll
                    for (int k = 0; k < 8; k++) {
                        uint64_t bd = b_base + ((k < 4) ? (uint64_t)(k * 2)
                                                        : BCOL + (uint64_t)((k - 4) * 2));
                        mma_f16_rs(tm_d, tm_a + k * 8, bd, IDESC,
                                   (t > 0 || k > 0) ? 1u : 0u);
                    }
                }
                TC_COMMIT(sbase + 8 + 8 * p);
            }
        }

        if (it > 0) {
            int q = p ^ 1;
            mbar_wait(sbase + 8 + 8 * q, ((it - 1) >> 1) & 1);
            TC_FENCE_AFTER();
            gemm_epilogue<FOUT>(tmem + 256 + q * 128, prev_bm, wid, lane, C, n);
        }
        prev_bm = bm;
    }
    if (it > 0) {
        int q = (it - 1) & 1;
        mbar_wait(sbase + 8 + 8 * q, ((it - 1) >> 1) & 1);
        TC_FENCE_AFTER();
        gemm_epilogue<FOUT>(tmem + 256 + q * 128, prev_bm, wid, lane, C, n);
    }
    __syncthreads();
    if (tid == 0) { MBAR_INVAL(sbase + 8); MBAR_INVAL(sbase + 16); }
    __syncthreads();
    if (wid == 0) TC_DEALLOC(tmem, 512);
#else
    int tid = threadIdx.x;
    for (int tile = blockIdx.x; tile * 128 < n; tile += gridDim.x) {
        int bm = tile * 128;
        for (int idx = tid; idx < 128 * FOUT; idx += 256) {
            int r = bm + idx / FOUT, c = idx % FOUT;
            if (r < n) {
                float acc = 0.f;
                for (int k = 0; k < 128; k++)
                    acc += __half2float(A[(size_t)r * 128 + k]) * W[(size_t)k * FOUT + c];
                C[(size_t)r * FOUT + c] = __float2half_rn(acc);
            }
        }
    }
#endif
}

// ---------------- aggregation (fp16 gather, fp32 accumulate) --------------
// out fp16 (feeds next GEMM); 4-way unrolled gather.
__global__ void k_agg128h(const __half* __restrict__ t, const int* __restrict__ rowptr,
                          const int* __restrict__ esrc, const float* __restrict__ enorm,
                          const float* __restrict__ bias, __half* __restrict__ out,
                          int n) {
    int w = (blockIdx.x * blockDim.x + threadIdx.x) >> 5;
    if (w >= n) return;
    int lane = threadIdx.x & 31;
    int beg = rowptr[w], end = rowptr[w + 1];
    float ax = 0.f, ay = 0.f, az = 0.f, aw = 0.f;
    int e = beg;
    for (; e + 3 < end; e += 4) {
        int s0 = esrc[e], s1 = esrc[e + 1], s2 = esrc[e + 2], s3 = esrc[e + 3];
        float n0 = enorm[e], n1 = enorm[e + 1], n2 = enorm[e + 2], n3 = enorm[e + 3];
        uint2 u0 = *(const uint2*)&t[(size_t)s0 * 128 + lane * 4];
        uint2 u1 = *(const uint2*)&t[(size_t)s1 * 128 + lane * 4];
        uint2 u2 = *(const uint2*)&t[(size_t)s2 * 128 + lane * 4];
        uint2 u3 = *(const uint2*)&t[(size_t)s3 * 128 + lane * 4];
        float2 a0 = __half22float2(*reinterpret_cast<__half2*>(&u0.x));
        float2 b0 = __half22float2(*reinterpret_cast<__half2*>(&u0.y));
        float2 a1 = __half22float2(*reinterpret_cast<__half2*>(&u1.x));
        float2 b1 = __half22float2(*reinterpret_cast<__half2*>(&u1.y));
        float2 a2 = __half22float2(*reinterpret_cast<__half2*>(&u2.x));
        float2 b2 = __half22float2(*reinterpret_cast<__half2*>(&u2.y));
        float2 a3 = __half22float2(*reinterpret_cast<__half2*>(&u3.x));
        float2 b3 = __half22float2(*reinterpret_cast<__half2*>(&u3.y));
        ax += a0.x * n0 + a1.x * n1 + a2.x * n2 + a3.x * n3;
        ay += a0.y * n0 + a1.y * n1 + a2.y * n2 + a3.y * n3;
        az += b0.x * n0 + b1.x * n1 + b2.x * n2 + b3.x * n3;
        aw += b0.y * n0 + b1.y * n1 + b2.y * n2 + b3.y * n3;
    }
    for (; e < end; e++) {
        int s0 = esrc[e];
        float n0 = enorm[e];
        uint2 u0 = *(const uint2*)&t[(size_t)s0 * 128 + lane * 4];
        float2 a0 = __half22float2(*reinterpret_cast<__half2*>(&u0.x));
        float2 b0 = __half22float2(*reinterpret_cast<__half2*>(&u0.y));
        ax += a0.x * n0;
        ay += a0.y * n0;
        az += b0.x * n0;
        aw += b0.y * n0;
    }
    float4 b4 = *(const float4*)&bias[lane * 4];
    ax = fmaxf(ax + b4.x, 0.f);
    ay = fmaxf(ay + b4.y, 0.f);
    az = fmaxf(az + b4.z, 0.f);
    aw = fmaxf(aw + b4.w, 0.f);
    __half2 h0 = __halves2half2(__float2half_rn(ax), __float2half_rn(ay));
    __half2 h1 = __halves2half2(__float2half_rn(az), __float2half_rn(aw));
    *(uint2*)&out[(size_t)w * 128 + lane * 4] =
        make_uint2(*reinterpret_cast<uint32_t*>(&h0), *reinterpret_cast<uint32_t*>(&h1));
}

// final layer: fp16 gather, fp32 out, no relu
__global__ void k_agg64h(const __half* __restrict__ t, const int* __restrict__ rowptr,
                         const int* __restrict__ esrc, const float* __restrict__ enorm,
                         const float* __restrict__ bias, float* __restrict__ out,
                         int n) {
    int w = (blockIdx.x * blockDim.x + threadIdx.x) >> 5;
    if (w >= n) return;
    int lane = threadIdx.x & 31;
    int beg = rowptr[w], end = rowptr[w + 1];
    float ax = 0.f, ay = 0.f;
    int e = beg;
    for (; e + 3 < end; e += 4) {
        int s0 = esrc[e], s1 = esrc[e + 1], s2 = esrc[e + 2], s3 = esrc[e + 3];
        float n0 = enorm[e], n1 = enorm[e + 1], n2 = enorm[e + 2], n3 = enorm[e + 3];
        uint32_t u0 = *(const uint32_t*)&t[(size_t)s0 * 64 + lane * 2];
        uint32_t u1 = *(const uint32_t*)&t[(size_t)s1 * 64 + lane * 2];
        uint32_t u2 = *(const uint32_t*)&t[(size_t)s2 * 64 + lane * 2];
        uint32_t u3 = *(const uint32_t*)&t[(size_t)s3 * 64 + lane * 2];
        float2 a0 = __half22float2(*reinterpret_cast<__half2*>(&u0));
        float2 a1 = __half22float2(*reinterpret_cast<__half2*>(&u1));
        float2 a2 = __half22float2(*reinterpret_cast<__half2*>(&u2));
        float2 a3 = __half22float2(*reinterpret_cast<__half2*>(&u3));
        ax += a0.x * n0 + a1.x * n1 + a2.x * n2 + a3.x * n3;
        ay += a0.y * n0 + a1.y * n1 + a2.y * n2 + a3.y * n3;
    }
    for (; e < end; e++) {
        int s0 = esrc[e];
        float n0 = enorm[e];
        uint32_t u0 = *(const uint32_t*)&t[(size_t)s0 * 64 + lane * 2];
        float2 a0 = __half22float2(*reinterpret_cast<__half2*>(&u0));
        ax += a0.x * n0;
        ay += a0.y * n0;
    }
    float2 b2 = *(const float2*)&bias[lane * 2];
    ax += b2.x; ay += b2.y;
    *(float2*)&out[(size_t)w * 64 + lane * 2] = make_float2(ax, ay);
}

// ---------------- host ----------------
extern "C" void kernel_launch(void* const* d_in, const int* in_sizes, int n_in,
                              void* d_out, int out_size) {
    const float* x   = (const float*)d_in[0];
    const int*   ei  = (const int*)d_in[1];
    const float* W1  = (const float*)d_in[2];
    const float* b1  = (const float*)d_in[3];
    const float* Wm1 = (const float*)d_in[4];
    const float* bm1 = (const float*)d_in[5];
    const float* Wm2 = (const float*)d_in[6];
    const float* bm2 = (const float*)d_in[7];
    const float* W2  = (const float*)d_in[8];
    const float* b2  = (const float*)d_in[9];

    int n = in_sizes[0] / 128;
    int E = in_sizes[1] / 2;

    void* p;
    int *indeg, *rowptr, *cursor, *bsum, *esrc;
    float *dinv, *enorm;
    __half *hA, *hB, *bufT;
    cudaGetSymbolAddress(&p, g_indeg);  indeg  = (int*)p;
    cudaGetSymbolAddress(&p, g_dinv);   dinv   = (float*)p;
    cudaGetSymbolAddress(&p, g_rowptr); rowptr = (int*)p;
    cudaGetSymbolAddress(&p, g_cursor); cursor = (int*)p;
    cudaGetSymbolAddress(&p, g_bsum);   bsum   = (int*)p;
    cudaGetSymbolAddress(&p, g_esrc);   esrc   = (int*)p;
    cudaGetSymbolAddress(&p, g_enorm);  enorm  = (float*)p;
    cudaGetSymbolAddress(&p, g_bufA);   hA     = (__half*)p;
    cudaGetSymbolAddress(&p, g_bufB);   hB     = (__half*)p;
    cudaGetSymbolAddress(&p, g_bufT);   bufT   = (__half*)p;

    int nb = (n + 1023) / 1024;

    // ---- graph normalization + CSR build ----
    k_deg_init<<<(n + 255) / 256, 256>>>(indeg, n);
    k_deg_count<<<(E + 255) / 256, 256>>>(ei, indeg, E);
    k_dinv<<<(n + 255) / 256, 256>>>(indeg, dinv, n);
    k_scan1<<<nb, 1024>>>(indeg, rowptr, bsum, n);
    k_scan2<<<1, 1024>>>(bsum, nb);
    k_scan3<<<nb, 1024>>>(rowptr, bsum, cursor, n, E + n);
    k_fill<<<(E + n + 255) / 256, 256>>>(ei, E, n, dinv, cursor, esrc, enorm);

    int gblocks = (n + 127) / 128;
    int ggrid = gblocks < 148 ? gblocks : 148;
    int agg_blocks = (n * 32 + 255) / 256;
    const int SMEM128 = 1024 + 2 * 128 * 128 * 2;  // 66560
    const int SMEM64  = 1024 + 2 * 64 * 128 * 2;   // 33792
    cudaFuncSetAttribute(k_gemm_f32<128>, cudaFuncAttributeMaxDynamicSharedMemorySize, SMEM128);
    cudaFuncSetAttribute(k_gemm_f16<128>, cudaFuncAttributeMaxDynamicSharedMemorySize, SMEM128);
    cudaFuncSetAttribute(k_gemm_f16<64>,  cudaFuncAttributeMaxDynamicSharedMemorySize, SMEM64);

    // ---- layer 1 (fp32 input) ----
    k_gemm_f32<128><<<ggrid, 256, SMEM128>>>(x, W1, bufT, n);
    k_agg128h<<<agg_blocks, 256>>>(bufT, rowptr, esrc, enorm, b1, hA, n);
    // ---- layer 2 ----
    k_gemm_f16<128><<<ggrid, 256, SMEM128>>>(hA, Wm1, bufT, n);
    k_agg128h<<<agg_blocks, 256>>>(bufT, rowptr, esrc, enorm, bm1, hB, n);
    // ---- layer 3 ----
    k_gemm_f16<128><<<ggrid, 256, SMEM128>>>(hB, Wm2, bufT, n);
    k_agg128h<<<agg_blocks, 256>>>(bufT, rowptr, esrc, enorm, bm2, hA, n);
    // ---- layer 4 (64 out, fp32 out, no relu) ----
    k_gemm_f16<64><<<ggrid, 256, SMEM64>>>(hA, W2, bufT, n);
    k_agg64h<<<agg_blocks, 256>>>(bufT, rowptr, esrc, enorm, b2, (float*)d_out, n);
}

// round 10
// speedup vs baseline: 2.1776x; 1.0115x over previous
#include <cuda_runtime.h>
#include <cuda_fp16.h>
#include <cstdint>
#include <cstddef>

#define NMAX 100000
#define EMAX 1600000
#define TOTMAX (EMAX + NMAX)

#if defined(__CUDA_ARCH_FEAT_SM103_ALL) || defined(__CUDA_ARCH_FEAT_SM100_ALL) || \
    defined(__CUDA_ARCH_FEAT_SM101_ALL)
#define HAS_TCGEN05 1
#else
#define HAS_TCGEN05 0
#endif

// ---------------- device scratch ----------
__device__ int    g_indeg[NMAX];
__device__ float  g_dinv[NMAX];
__device__ int    g_rowptr[NMAX + 1];
__device__ int    g_cursor[NMAX];
__device__ int    g_bsum[1024];
__device__ int    g_esrc[TOTMAX];
__device__ float  g_enorm[TOTMAX];
__device__ __half g_bufA[(size_t)NMAX * 128];
__device__ __half g_bufB[(size_t)NMAX * 128];
__device__ __half g_bufT[(size_t)NMAX * 128];

// ---------------- PTX helpers ----------------
__device__ __forceinline__ uint32_t smem_u32(const void* p) {
    uint32_t a;
    asm("{ .reg .u64 t; cvta.to.shared.u64 t, %1; cvt.u32.u64 %0, t; }" : "=r"(a) : "l"(p));
    return a;
}

#if HAS_TCGEN05
__device__ __forceinline__ uint32_t elect_one() {
    uint32_t pred;
    asm volatile("{\n .reg .pred p;\n elect.sync _|p, 0xFFFFFFFF;\n selp.b32 %0, 1, 0, p;\n}"
                 : "=r"(pred));
    return pred;
}
#define TC_ALLOC(smem_addr, ncols) \
    asm volatile("tcgen05.alloc.cta_group::1.sync.aligned.shared::cta.b32 [%0], %1;" \
                 :: "r"(smem_addr), "r"(ncols) : "memory")
#define TC_DEALLOC(tmem, ncols) \
    asm volatile("tcgen05.dealloc.cta_group::1.sync.aligned.b32 %0, %1;" :: "r"(tmem), "r"(ncols))
#define TC_COMMIT(mbar) \
    asm volatile("tcgen05.commit.cta_group::1.mbarrier::arrive::one.shared::cluster.b64 [%0];" \
                 :: "r"(mbar) : "memory")
#define TC_WAIT_LD() asm volatile("tcgen05.wait::ld.sync.aligned;" ::: "memory")
#define TC_WAIT_ST() asm volatile("tcgen05.wait::st.sync.aligned;" ::: "memory")
#define TC_FENCE_BEFORE() asm volatile("tcgen05.fence::before_thread_sync;" ::: "memory")
#define TC_FENCE_AFTER() asm volatile("tcgen05.fence::after_thread_sync;" ::: "memory")
#define FENCE_ASYNC_SHARED() asm volatile("fence.proxy.async.shared::cta;" ::: "memory")
#define MBAR_INIT(mbar, cnt) \
    asm volatile("mbarrier.init.shared.b64 [%0], %1;" :: "r"(mbar), "r"(cnt) : "memory")
#define MBAR_INVAL(mbar) \
    asm volatile("mbarrier.inval.shared.b64 [%0];" :: "r"(mbar) : "memory")

__device__ __forceinline__ void mbar_wait(uint32_t mbar, uint32_t parity) {
    asm volatile(
        "{\n .reg .pred P1;\n"
        "WAIT_LOOP_%=:\n"
        " mbarrier.try_wait.parity.acquire.cta.shared::cta.b64 P1, [%0], %1, 0x989680;\n"
        " @P1 bra.uni WAIT_DONE_%=;\n"
        " bra.uni WAIT_LOOP_%=;\n"
        "WAIT_DONE_%=:\n}"
        :: "r"(mbar), "r"(parity) : "memory");
}

__device__ __forceinline__ void mma_f16_rs(uint32_t d, uint32_t a_tmem, uint64_t b,
                                           uint32_t idesc, uint32_t en) {
    uint32_t z = 0;
    asm volatile(
        "{\n .reg .pred p;\n setp.ne.u32 p, %5, 0;\n"
        " tcgen05.mma.cta_group::1.kind::f16 [%0], [%1], %2, %3, {%4, %4, %4, %4}, p;\n}"
        :: "r"(d), "r"(a_tmem), "l"(b), "r"(idesc), "r"(z), "r"(en) : "memory");
}

#define LDTM_X32(r, addr) \
    asm volatile( \
        "tcgen05.ld.sync.aligned.32x32b.x32.b32 " \
        "{%0, %1, %2, %3, %4, %5, %6, %7, %8, %9, %10, %11, %12, %13, %14, %15, " \
        " %16, %17, %18, %19, %20, %21, %22, %23, %24, %25, %26, %27, %28, %29, %30, %31}, [%32];" \
        : "=r"((r)[0]),  "=r"((r)[1]),  "=r"((r)[2]),  "=r"((r)[3]), \
          "=r"((r)[4]),  "=r"((r)[5]),  "=r"((r)[6]),  "=r"((r)[7]), \
          "=r"((r)[8]),  "=r"((r)[9]),  "=r"((r)[10]), "=r"((r)[11]), \
          "=r"((r)[12]), "=r"((r)[13]), "=r"((r)[14]), "=r"((r)[15]), \
          "=r"((r)[16]), "=r"((r)[17]), "=r"((r)[18]), "=r"((r)[19]), \
          "=r"((r)[20]), "=r"((r)[21]), "=r"((r)[22]), "=r"((r)[23]), \
          "=r"((r)[24]), "=r"((r)[25]), "=r"((r)[26]), "=r"((r)[27]), \
          "=r"((r)[28]), "=r"((r)[29]), "=r"((r)[30]), "=r"((r)[31]) \
        : "r"(addr))

#define STTM_X64(addr, r) \
    asm volatile( \
        "tcgen05.st.sync.aligned.32x32b.x64.b32 [%0], " \
        "{%1, %2, %3, %4, %5, %6, %7, %8, " \
        " %9, %10, %11, %12, %13, %14, %15, %16, " \
        " %17, %18, %19, %20, %21, %22, %23, %24, " \
        " %25, %26, %27, %28, %29, %30, %31, %32, " \
        " %33, %34, %35, %36, %37, %38, %39, %40, " \
        " %41, %42, %43, %44, %45, %46, %47, %48, " \
        " %49, %50, %51, %52, %53, %54, %55, %56, " \
        " %57, %58, %59, %60, %61, %62, %63, %64};" \
        :: "r"(addr), \
           "r"((r)[0]),  "r"((r)[1]),  "r"((r)[2]),  "r"((r)[3]), \
           "r"((r)[4]),  "r"((r)[5]),  "r"((r)[6]),  "r"((r)[7]), \
           "r"((r)[8]),  "r"((r)[9]),  "r"((r)[10]), "r"((r)[11]), \
           "r"((r)[12]), "r"((r)[13]), "r"((r)[14]), "r"((r)[15]), \
           "r"((r)[16]), "r"((r)[17]), "r"((r)[18]), "r"((r)[19]), \
           "r"((r)[20]), "r"((r)[21]), "r"((r)[22]), "r"((r)[23]), \
           "r"((r)[24]), "r"((r)[25]), "r"((r)[26]), "r"((r)[27]), \
           "r"((r)[28]), "r"((r)[29]), "r"((r)[30]), "r"((r)[31]), \
           "r"((r)[32]), "r"((r)[33]), "r"((r)[34]), "r"((r)[35]), \
           "r"((r)[36]), "r"((r)[37]), "r"((r)[38]), "r"((r)[39]), \
           "r"((r)[40]), "r"((r)[41]), "r"((r)[42]), "r"((r)[43]), \
           "r"((r)[44]), "r"((r)[45]), "r"((r)[46]), "r"((r)[47]), \
           "r"((r)[48]), "r"((r)[49]), "r"((r)[50]), "r"((r)[51]), \
           "r"((r)[52]), "r"((r)[53]), "r"((r)[54]), "r"((r)[55]), \
           "r"((r)[56]), "r"((r)[57]), "r"((r)[58]), "r"((r)[59]), \
           "r"((r)[60]), "r"((r)[61]), "r"((r)[62]), "r"((r)[63]) \
        : "memory")

__device__ __forceinline__ uint64_t make_desc(uint32_t addr) {
    const uint64_t base = (uint64_t(2) << 61) | (uint64_t(1) << 46) |
                          (uint64_t(64) << 32) | (uint64_t(1) << 16);
    return base | ((uint64_t)(addr >> 4) & 0x3FFF);
}
#endif  // HAS_TCGEN05

// ---------------- degree / norm ----------------
__global__ void k_deg_count(const int* __restrict__ ei, int* indeg, int E) {
    int g = blockIdx.x * blockDim.x + threadIdx.x;
    if (g < E) atomicAdd(&indeg[ei[E + g]], 1);
}
// deg includes self-loop: count+1
__global__ void k_dinv(const int* __restrict__ indeg, float* dinv, int n) {
    int g = blockIdx.x * blockDim.x + threadIdx.x;
    if (g < n) dinv[g] = rsqrtf((float)(indeg[g] + 1));
}

// ---------------- exclusive scan (shuffle-based, input = indeg+1) ----------
__global__ void k_scan1(const int* __restrict__ in, int* out, int* bsum, int n) {
    __shared__ int warp_sums[32];
    int g = blockIdx.x * 1024 + threadIdx.x;
    int lane = threadIdx.x & 31;
    int wid = threadIdx.x >> 5;
    int v = (g < n) ? (in[g] + 1) : 0;   // +1 self loop
    int x = v;
#pragma unroll
    for (int off = 1; off < 32; off <<= 1) {
        int t = __shfl_up_sync(0xFFFFFFFF, x, off);
        if (lane >= off) x += t;
    }
    if (lane == 31) warp_sums[wid] = x;
    __syncthreads();
    if (wid == 0) {
        int s = (lane < 32) ? warp_sums[lane] : 0;
#pragma unroll
        for (int off = 1; off < 32; off <<= 1) {
            int t = __shfl_up_sync(0xFFFFFFFF, s, off);
            if (lane >= off) s += t;
        }
        warp_sums[lane] = s;
    }
    __syncthreads();
    int wbase = (wid > 0) ? warp_sums[wid - 1] : 0;
    if (g < n) out[g] = wbase + x - v;  // exclusive
    if (threadIdx.x == 1023) bsum[blockIdx.x] = wbase + x;
}
__global__ void k_scan2(int* bsum, int nb) {
    __shared__ int warp_sums[32];
    int lane = threadIdx.x & 31;
    int wid = threadIdx.x >> 5;
    int v = (threadIdx.x < nb) ? bsum[threadIdx.x] : 0;
    int x = v;
#pragma unroll
    for (int off = 1; off < 32; off <<= 1) {
        int t = __shfl_up_sync(0xFFFFFFFF, x, off);
        if (lane >= off) x += t;
    }
    if (lane == 31) warp_sums[wid] = x;
    __syncthreads();
    if (wid == 0) {
        int s = (lane < 32) ? warp_sums[lane] : 0;
#pragma unroll
        for (int off = 1; off < 32; off <<= 1) {
            int t = __shfl_up_sync(0xFFFFFFFF, s, off);
            if (lane >= off) s += t;
        }
        warp_sums[lane] = s;
    }
    __syncthreads();
    int wbase = (wid > 0) ? warp_sums[wid - 1] : 0;
    if (threadIdx.x < nb) bsum[threadIdx.x] = wbase + x - v;
}
__global__ void k_scan3(int* rowptr, const int* __restrict__ bsum, int* cursor,
                        int n, int total) {
    int g = blockIdx.x * 1024 + threadIdx.x;
    if (g < n) {
        int r = rowptr[g] + bsum[g >> 10];
        rowptr[g] = r;
        cursor[g] = r;
    }
    if (g == 0) rowptr[n] = total;
}

// ---------------- CSR fill ----------------
__global__ void k_fill(const int* __restrict__ ei, int E, int n,
                       const float* __restrict__ dinv, int* cursor,
                       int* esrc, float* enorm) {
    int g = blockIdx.x * blockDim.x + threadIdx.x;
    if (g < E) {
        int s = ei[g];
        int d = ei[E + g];
        int pos = atomicAdd(&cursor[d], 1);
        esrc[pos] = s;
        enorm[pos] = dinv[s] * dinv[d];
    } else if (g < E + n) {
        int i = g - E;
        int pos = atomicAdd(&cursor[i], 1);
        esrc[pos] = i;
        float dv = dinv[i];
        enorm[pos] = dv * dv;
    }
}

#if HAS_TCGEN05
template <int FOUT>
__device__ __forceinline__ void gemm_epilogue(uint32_t tm_d, int bm, int wid, int lane,
                                              __half* __restrict__ C, int n) {
    if (wid < 4) {
        int row = bm + wid * 32 + lane;
        for (int c0 = 0; c0 < FOUT; c0 += 32) {
            uint32_t r[32];
            LDTM_X32(r, tm_d + c0);
            TC_WAIT_LD();
            if (row < n) {
                __half* dst = &C[(size_t)row * FOUT + c0];
                uint32_t o[16];
#pragma unroll
                for (int j = 0; j < 16; j++) {
                    __half2 hp = __halves2half2(
                        __float2half_rn(__uint_as_float(r[2 * j])),
                        __float2half_rn(__uint_as_float(r[2 * j + 1])));
                    o[j] = *reinterpret_cast<uint32_t*>(&hp);
                }
#pragma unroll
                for (int j = 0; j < 4; j++)
                    *(uint4*)(dst + j * 8) =
                        make_uint4(o[4 * j], o[4 * j + 1], o[4 * j + 2], o[4 * j + 3]);
            }
        }
        TC_FENCE_BEFORE();
    }
}
#endif

// ---------------- GEMM #1: fp32 input, 3-term fp16 split (layer 1) --------
template <int FOUT>
__global__ void __launch_bounds__(256, 1) __cluster_dims__(1, 1, 1) k_gemm_f32(
    const float* __restrict__ A, const float* __restrict__ W,
    __half* __restrict__ C, int n) {
#if HAS_TCGEN05
    extern __shared__ char smem[];
    constexpr int BH_OFF = 1024;
    constexpr int BL_OFF = BH_OFF + FOUT * 128 * 2;
    constexpr uint32_t IDESC = (1u << 4) | ((FOUT / 8) << 17) | (8u << 24);

    uint32_t sbase = smem_u32(smem);
    int tid = threadIdx.x;
    int wid = tid >> 5;
    int lane = tid & 31;

    if (wid == 0) TC_ALLOC(sbase, 512);
    if (tid == 0) { MBAR_INIT(sbase + 8, 1); MBAR_INIT(sbase + 16, 1); }
    __syncthreads();
    uint32_t tmem;
    asm volatile("ld.shared.b32 %0, [%1];" : "=r"(tmem) : "r"(sbase));

    for (int g = tid; g < FOUT * 16; g += 256) {
        int r = g >> 4;
        int k8 = (g & 15) << 3;
        uint32_t hu[4], lu[4];
#pragma unroll
        for (int j = 0; j < 4; j++) {
            float x0 = W[(size_t)(k8 + 2 * j) * FOUT + r];
            float x1 = W[(size_t)(k8 + 2 * j + 1) * FOUT + r];
            __half h0 = __float2half_rn(x0);
            __half h1 = __float2half_rn(x1);
            float l0 = x0 - __half2float(h0);
            float l1 = x1 - __half2float(h1);
            __half2 hp = __halves2half2(h0, h1);
            __half2 lp = __halves2half2(__float2half_rn(l0), __float2half_rn(l1));
            hu[j] = *reinterpret_cast<uint32_t*>(&hp);
            lu[j] = *reinterpret_cast<uint32_t*>(&lp);
        }
        int atom = (r >> 3) + (k8 >> 6) * (FOUT >> 3);
        uint32_t boff = atom * 1024 + (r & 7) * 128 + (k8 & 63) * 2;
        uint32_t sw = boff ^ ((boff >> 3) & 0x70);
        *(uint4*)(smem + BH_OFF + sw) = make_uint4(hu[0], hu[1], hu[2], hu[3]);
        *(uint4*)(smem + BL_OFF + sw) = make_uint4(lu[0], lu[1], lu[2], lu[3]);
    }
    FENCE_ASYNC_SHARED();
    __syncthreads();

    uint64_t bh = make_desc(sbase + BH_OFF);
    uint64_t bl = make_desc(sbase + BL_OFF);
    const uint64_t BCOL = (uint64_t)FOUT * 8;

    int it = 0;
    int prev_bm = 0;
    for (int tile = blockIdx.x; tile * 128 < n; tile += gridDim.x, it++) {
        int p = it & 1;
        int bm = tile * 128;
        uint32_t tm_a = tmem + p * 128;
        uint32_t tm_d = tmem + 256 + p * 128;

        if (tid < 128) {
            int row = bm + tid;
            const float4* a4 = (const float4*)&A[(size_t)row * 128];
            uint32_t v[64];
#pragma unroll
            for (int i = 0; i < 32; i++) {
                float4 f = (row < n) ? a4[i] : make_float4(0.f, 0.f, 0.f, 0.f);
                __half2 p0 = __halves2half2(__float2half_rn(f.x), __float2half_rn(f.y));
                __half2 p1 = __halves2half2(__float2half_rn(f.z), __float2half_rn(f.w));
                v[2 * i]     = *reinterpret_cast<uint32_t*>(&p0);
                v[2 * i + 1] = *reinterpret_cast<uint32_t*>(&p1);
            }
            STTM_X64(tm_a, v);
            TC_WAIT_ST();
#pragma unroll
            for (int i = 0; i < 32; i++) {
                float4 f = (row < n) ? a4[i] : make_float4(0.f, 0.f, 0.f, 0.f);
                float lx = f.x - __half2float(__float2half_rn(f.x));
                float ly = f.y - __half2float(__float2half_rn(f.y));
                float lz = f.z - __half2float(__float2half_rn(f.z));
                float lw = f.w - __half2float(__float2half_rn(f.w));
                __half2 p0 = __halves2half2(__float2half_rn(lx), __float2half_rn(ly));
                __half2 p1 = __halves2half2(__float2half_rn(lz), __float2half_rn(lw));
                v[2 * i]     = *reinterpret_cast<uint32_t*>(&p0);
                v[2 * i + 1] = *reinterpret_cast<uint32_t*>(&p1);
            }
            STTM_X64(tm_a + 64, v);
            TC_WAIT_ST();
        }
        TC_FENCE_BEFORE();
        __syncthreads();

        if (wid == 0) {
            TC_FENCE_AFTER();
            if (elect_one()) {
#pragma unroll
                for (int t = 0; t < 3; t++) {
                    uint32_t a_base = tm_a + ((t == 2) ? 64 : 0);
                    uint64_t b_base = (t == 1) ? bl : bh;
#pragma unroll
                    for (int k = 0; k < 8; k++) {
                        uint64_t bd = b_base + ((k < 4) ? (uint64_t)(k * 2)
                                                        : BCOL + (uint64_t)((k - 4) * 2));
                        mma_f16_rs(tm_d, a_base + k * 8, bd, IDESC,
                                   (t > 0 || k > 0) ? 1u : 0u);
                    }
                }
                TC_COMMIT(sbase + 8 + 8 * p);
            }
        }

        if (it > 0) {
            int q = p ^ 1;
            mbar_wait(sbase + 8 + 8 * q, ((it - 1) >> 1) & 1);
            TC_FENCE_AFTER();
            gemm_epilogue<FOUT>(tmem + 256 + q * 128, prev_bm, wid, lane, C, n);
        }
        prev_bm = bm;
    }
    if (it > 0) {
        int q = (it - 1) & 1;
        mbar_wait(sbase + 8 + 8 * q, ((it - 1) >> 1) & 1);
        TC_FENCE_AFTER();
        gemm_epilogue<FOUT>(tmem + 256 + q * 128, prev_bm, wid, lane, C, n);
    }
    __syncthreads();
    if (tid == 0) { MBAR_INVAL(sbase + 8); MBAR_INVAL(sbase + 16); }
    __syncthreads();
    if (wid == 0) TC_DEALLOC(tmem, 512);
#else
    int tid = threadIdx.x;
    for (int tile = blockIdx.x; tile * 128 < n; tile += gridDim.x) {
        int bm = tile * 128;
        for (int idx = tid; idx < 128 * FOUT; idx += 256) {
            int r = bm + idx / FOUT, c = idx % FOUT;
            if (r < n) {
                float acc = 0.f;
                for (int k = 0; k < 128; k++)
                    acc += A[(size_t)r * 128 + k] * W[(size_t)k * FOUT + c];
                C[(size_t)r * FOUT + c] = __float2half_rn(acc);
            }
        }
    }
#endif
}

// ---------------- GEMM #2: fp16 input, 2-term (layers 2..4) ----------------
template <int FOUT>
__global__ void __launch_bounds__(256, 1) __cluster_dims__(1, 1, 1) k_gemm_f16(
    const __half* __restrict__ A, const float* __restrict__ W,
    __half* __restrict__ C, int n) {
#if HAS_TCGEN05
    extern __shared__ char smem[];
    constexpr int BH_OFF = 1024;
    constexpr int BL_OFF = BH_OFF + FOUT * 128 * 2;
    constexpr uint32_t IDESC = (1u << 4) | ((FOUT / 8) << 17) | (8u << 24);

    uint32_t sbase = smem_u32(smem);
    int tid = threadIdx.x;
    int wid = tid >> 5;
    int lane = tid & 31;

    if (wid == 0) TC_ALLOC(sbase, 512);
    if (tid == 0) { MBAR_INIT(sbase + 8, 1); MBAR_INIT(sbase + 16, 1); }
    __syncthreads();
    uint32_t tmem;
    asm volatile("ld.shared.b32 %0, [%1];" : "=r"(tmem) : "r"(sbase));

    for (int g = tid; g < FOUT * 16; g += 256) {
        int r = g >> 4;
        int k8 = (g & 15) << 3;
        uint32_t hu[4], lu[4];
#pragma unroll
        for (int j = 0; j < 4; j++) {
            float x0 = W[(size_t)(k8 + 2 * j) * FOUT + r];
            float x1 = W[(size_t)(k8 + 2 * j + 1) * FOUT + r];
            __half h0 = __float2half_rn(x0);
            __half h1 = __float2half_rn(x1);
            float l0 = x0 - __half2float(h0);
            float l1 = x1 - __half2float(h1);
            __half2 hp = __halves2half2(h0, h1);
            __half2 lp = __halves2half2(__float2half_rn(l0), __float2half_rn(l1));
            hu[j] = *reinterpret_cast<uint32_t*>(&hp);
            lu[j] = *reinterpret_cast<uint32_t*>(&lp);
        }
        int atom = (r >> 3) + (k8 >> 6) * (FOUT >> 3);
        uint32_t boff = atom * 1024 + (r & 7) * 128 + (k8 & 63) * 2;
        uint32_t sw = boff ^ ((boff >> 3) & 0x70);
        *(uint4*)(smem + BH_OFF + sw) = make_uint4(hu[0], hu[1], hu[2], hu[3]);
        *(uint4*)(smem + BL_OFF + sw) = make_uint4(lu[0], lu[1], lu[2], lu[3]);
    }
    FENCE_ASYNC_SHARED();
    __syncthreads();

    uint64_t bh = make_desc(sbase + BH_OFF);
    uint64_t bl = make_desc(sbase + BL_OFF);
    const uint64_t BCOL = (uint64_t)FOUT * 8;

    int it = 0;
    int prev_bm = 0;
    for (int tile = blockIdx.x; tile * 128 < n; tile += gridDim.x, it++) {
        int p = it & 1;
        int bm = tile * 128;
        uint32_t tm_a = tmem + p * 64;
        uint32_t tm_d = tmem + 256 + p * 128;

        if (tid < 128) {
            int row = bm + tid;
            const uint4* a4 = (const uint4*)&A[(size_t)row * 128];
            uint32_t v[64];
#pragma unroll
            for (int i = 0; i < 16; i++) {
                uint4 u = (row < n) ? a4[i] : make_uint4(0, 0, 0, 0);
                v[4 * i] = u.x; v[4 * i + 1] = u.y; v[4 * i + 2] = u.z; v[4 * i + 3] = u.w;
            }
            STTM_X64(tm_a, v);
            TC_WAIT_ST();
        }
        TC_FENCE_BEFORE();
        __syncthreads();

        if (wid == 0) {
            TC_FENCE_AFTER();
            if (elect_one()) {
#pragma unroll
                for (int t = 0; t < 2; t++) {
                    uint64_t b_base = (t == 1) ? bl : bh;
#pragma unroll
                    for (int k = 0; k < 8; k++) {
                        uint64_t bd = b_base + ((k < 4) ? (uint64_t)(k * 2)
                                                        : BCOL + (uint64_t)((k - 4) * 2));
                        mma_f16_rs(tm_d, tm_a + k * 8, bd, IDESC,
                                   (t > 0 || k > 0) ? 1u : 0u);
                    }
                }
                TC_COMMIT(sbase + 8 + 8 * p);
            }
        }

        if (it > 0) {
            int q = p ^ 1;
            mbar_wait(sbase + 8 + 8 * q, ((it - 1) >> 1) & 1);
            TC_FENCE_AFTER();
            gemm_epilogue<FOUT>(tmem + 256 + q * 128, prev_bm, wid, lane, C, n);
        }
        prev_bm = bm;
    }
    if (it > 0) {
        int q = (it - 1) & 1;
        mbar_wait(sbase + 8 + 8 * q, ((it - 1) >> 1) & 1);
        TC_FENCE_AFTER();
        gemm_epilogue<FOUT>(tmem + 256 + q * 128, prev_bm, wid, lane, C, n);
    }
    __syncthreads();
    if (tid == 0) { MBAR_INVAL(sbase + 8); MBAR_INVAL(sbase + 16); }
    __syncthreads();
    if (wid == 0) TC_DEALLOC(tmem, 512);
#else
    int tid = threadIdx.x;
    for (int tile = blockIdx.x; tile * 128 < n; tile += gridDim.x) {
        int bm = tile * 128;
        for (int idx = tid; idx < 128 * FOUT; idx += 256) {
            int r = bm + idx / FOUT, c = idx % FOUT;
            if (r < n) {
                float acc = 0.f;
                for (int k = 0; k < 128; k++)
                    acc += __half2float(A[(size_t)r * 128 + k]) * W[(size_t)k * FOUT + c];
                C[(size_t)r * FOUT + c] = __float2half_rn(acc);
            }
        }
    }
#endif
}

// ---------------- aggregation: 8-edge unroll, vector index loads ----------
__global__ void k_agg128h(const __half* __restrict__ t, const int* __restrict__ rowptr,
                          const int* __restrict__ esrc, const float* __restrict__ enorm,
                          const float* __restrict__ bias, __half* __restrict__ out,
                          int n) {
    int w = (blockIdx.x * blockDim.x + threadIdx.x) >> 5;
    if (w >= n) return;
    int lane = threadIdx.x & 31;
    int beg = rowptr[w], end = rowptr[w + 1];
    float ax = 0.f, ay = 0.f, az = 0.f, aw = 0.f;
    int e = beg;
    // peel to 4-alignment for vector index loads
    for (; e < end && (e & 3); e++) {
        int s0 = esrc[e];
        float n0 = enorm[e];
        uint2 u0 = *(const uint2*)&t[(size_t)s0 * 128 + lane * 4];
        float2 a0 = __half22float2(*reinterpret_cast<__half2*>(&u0.x));
        float2 b0 = __half22float2(*reinterpret_cast<__half2*>(&u0.y));
        ax += a0.x * n0; ay += a0.y * n0; az += b0.x * n0; aw += b0.y * n0;
    }
    for (; e + 7 < end; e += 8) {
        int4 s4a = *(const int4*)&esrc[e];
        int4 s4b = *(const int4*)&esrc[e + 4];
        float4 n4a = *(const float4*)&enorm[e];
        float4 n4b = *(const float4*)&enorm[e + 4];
        uint2 u0 = *(const uint2*)&t[(size_t)s4a.x * 128 + lane * 4];
        uint2 u1 = *(const uint2*)&t[(size_t)s4a.y * 128 + lane * 4];
        uint2 u2 = *(const uint2*)&t[(size_t)s4a.z * 128 + lane * 4];
        uint2 u3 = *(const uint2*)&t[(size_t)s4a.w * 128 + lane * 4];
        uint2 u4 = *(const uint2*)&t[(size_t)s4b.x * 128 + lane * 4];
        uint2 u5 = *(const uint2*)&t[(size_t)s4b.y * 128 + lane * 4];
        uint2 u6 = *(const uint2*)&t[(size_t)s4b.z * 128 + lane * 4];
        uint2 u7 = *(const uint2*)&t[(size_t)s4b.w * 128 + lane * 4];
#define ACC(u, nn)                                                             \
        {                                                                      \
            float2 _a = __half22float2(*reinterpret_cast<__half2*>(&(u).x));   \
            float2 _b = __half22float2(*reinterpret_cast<__half2*>(&(u).y));   \
            ax += _a.x * (nn); ay += _a.y * (nn);                              \
            az += _b.x * (nn); aw += _b.y * (nn);                              \
        }
        ACC(u0, n4a.x) ACC(u1, n4a.y) ACC(u2, n4a.z) ACC(u3, n4a.w)
        ACC(u4, n4b.x) ACC(u5, n4b.y) ACC(u6, n4b.z) ACC(u7, n4b.w)
#undef ACC
    }
    for (; e < end; e++) {
        int s0 = esrc[e];
        float n0 = enorm[e];
        uint2 u0 = *(const uint2*)&t[(size_t)s0 * 128 + lane * 4];
        float2 a0 = __half22float2(*reinterpret_cast<__half2*>(&u0.x));
        float2 b0 = __half22float2(*reinterpret_cast<__half2*>(&u0.y));
        ax += a0.x * n0; ay += a0.y * n0; az += b0.x * n0; aw += b0.y * n0;
    }
    float4 b4 = *(const float4*)&bias[lane * 4];
    ax = fmaxf(ax + b4.x, 0.f);
    ay = fmaxf(ay + b4.y, 0.f);
    az = fmaxf(az + b4.z, 0.f);
    aw = fmaxf(aw + b4.w, 0.f);
    __half2 h0 = __halves2half2(__float2half_rn(ax), __float2half_rn(ay));
    __half2 h1 = __halves2half2(__float2half_rn(az), __float2half_rn(aw));
    *(uint2*)&out[(size_t)w * 128 + lane * 4] =
        make_uint2(*reinterpret_cast<uint32_t*>(&h0), *reinterpret_cast<uint32_t*>(&h1));
}

__global__ void k_agg64h(const __half* __restrict__ t, const int* __restrict__ rowptr,
                         const int* __restrict__ esrc, const float* __restrict__ enorm,
                         const float* __restrict__ bias, float* __restrict__ out,
                         int n) {
    int w = (blockIdx.x * blockDim.x + threadIdx.x) >> 5;
    if (w >= n) return;
    int lane = threadIdx.x & 31;
    int beg = rowptr[w], end = rowptr[w + 1];
    float ax = 0.f, ay = 0.f;
    int e = beg;
    for (; e < end && (e & 3); e++) {
        int s0 = esrc[e];
        float n0 = enorm[e];
        uint32_t u0 = *(const uint32_t*)&t[(size_t)s0 * 64 + lane * 2];
        float2 a0 = __half22float2(*reinterpret_cast<__half2*>(&u0));
        ax += a0.x * n0; ay += a0.y * n0;
    }
    for (; e + 7 < end; e += 8) {
        int4 s4a = *(const int4*)&esrc[e];
        int4 s4b = *(const int4*)&esrc[e + 4];
        float4 n4a = *(const float4*)&enorm[e];
        float4 n4b = *(const float4*)&enorm[e + 4];
        uint32_t u0 = *(const uint32_t*)&t[(size_t)s4a.x * 64 + lane * 2];
        uint32_t u1 = *(const uint32_t*)&t[(size_t)s4a.y * 64 + lane * 2];
        uint32_t u2 = *(const uint32_t*)&t[(size_t)s4a.z * 64 + lane * 2];
        uint32_t u3 = *(const uint32_t*)&t[(size_t)s4a.w * 64 + lane * 2];
        uint32_t u4 = *(const uint32_t*)&t[(size_t)s4b.x * 64 + lane * 2];
        uint32_t u5 = *(const uint32_t*)&t[(size_t)s4b.y * 64 + lane * 2];
        uint32_t u6 = *(const uint32_t*)&t[(size_t)s4b.z * 64 + lane * 2];
        uint32_t u7 = *(const uint32_t*)&t[(size_t)s4b.w * 64 + lane * 2];
#define ACC(u, nn)                                                             \
        {                                                                      \
            float2 _a = __half22float2(*reinterpret_cast<__half2*>(&(u)));     \
            ax += _a.x * (nn); ay += _a.y * (nn);                              \
        }
        ACC(u0, n4a.x) ACC(u1, n4a.y) ACC(u2, n4a.z) ACC(u3, n4a.w)
        ACC(u4, n4b.x) ACC(u5, n4b.y) ACC(u6, n4b.z) ACC(u7, n4b.w)
#undef ACC
    }
    for (; e < end; e++) {
        int s0 = esrc[e];
        float n0 = enorm[e];
        uint32_t u0 = *(const uint32_t*)&t[(size_t)s0 * 64 + lane * 2];
        float2 a0 = __half22float2(*reinterpret_cast<__half2*>(&u0));
        ax += a0.x * n0; ay += a0.y * n0;
    }
    float2 b2 = *(const float2*)&bias[lane * 2];
    ax += b2.x; ay += b2.y;
    *(float2*)&out[(size_t)w * 64 + lane * 2] = make_float2(ax, ay);
}

// ---------------- host ----------------
extern "C" void kernel_launch(void* const* d_in, const int* in_sizes, int n_in,
                              void* d_out, int out_size) {
    const float* x   = (const float*)d_in[0];
    const int*   ei  = (const int*)d_in[1];
    const float* W1  = (const float*)d_in[2];
    const float* b1  = (const float*)d_in[3];
    const float* Wm1 = (const float*)d_in[4];
    const float* bm1 = (const float*)d_in[5];
    const float* Wm2 = (const float*)d_in[6];
    const float* bm2 = (const float*)d_in[7];
    const float* W2  = (const float*)d_in[8];
    const float* b2  = (const float*)d_in[9];

    int n = in_sizes[0] / 128;
    int E = in_sizes[1] / 2;

    void* p;
    int *indeg, *rowptr, *cursor, *bsum, *esrc;
    float *dinv, *enorm;
    __half *hA, *hB, *bufT;
    cudaGetSymbolAddress(&p, g_indeg);  indeg  = (int*)p;
    cudaGetSymbolAddress(&p, g_dinv);   dinv   = (float*)p;
    cudaGetSymbolAddress(&p, g_rowptr); rowptr = (int*)p;
    cudaGetSymbolAddress(&p, g_cursor); cursor = (int*)p;
    cudaGetSymbolAddress(&p, g_bsum);   bsum   = (int*)p;
    cudaGetSymbolAddress(&p, g_esrc);   esrc   = (int*)p;
    cudaGetSymbolAddress(&p, g_enorm);  enorm  = (float*)p;
    cudaGetSymbolAddress(&p, g_bufA);   hA     = (__half*)p;
    cudaGetSymbolAddress(&p, g_bufB);   hB     = (__half*)p;
    cudaGetSymbolAddress(&p, g_bufT);   bufT   = (__half*)p;

    int nb = (n + 1023) / 1024;

    // ---- graph normalization + CSR build ----
    cudaMemsetAsync(indeg, 0, n * sizeof(int));
    k_deg_count<<<(E + 255) / 256, 256>>>(ei, indeg, E);
    k_dinv<<<(n + 255) / 256, 256>>>(indeg, dinv, n);
    k_scan1<<<nb, 1024>>>(indeg, rowptr, bsum, n);
    k_scan2<<<1, 1024>>>(bsum, nb);
    k_scan3<<<nb, 1024>>>(rowptr, bsum, cursor, n, E + n);
    k_fill<<<(E + n + 255) / 256, 256>>>(ei, E, n, dinv, cursor, esrc, enorm);

    int gblocks = (n + 127) / 128;
    int ggrid = gblocks < 148 ? gblocks : 148;
    int agg_blocks = (n * 32 + 255) / 256;
    const int SMEM128 = 1024 + 2 * 128 * 128 * 2;  // 66560
    const int SMEM64  = 1024 + 2 * 64 * 128 * 2;   // 33792
    cudaFuncSetAttribute(k_gemm_f32<128>, cudaFuncAttributeMaxDynamicSharedMemorySize, SMEM128);
    cudaFuncSetAttribute(k_gemm_f16<128>, cudaFuncAttributeMaxDynamicSharedMemorySize, SMEM128);
    cudaFuncSetAttribute(k_gemm_f16<64>,  cudaFuncAttributeMaxDynamicSharedMemorySize, SMEM64);

    // ---- layer 1 (fp32 input) ----
    k_gemm_f32<128><<<ggrid, 256, SMEM128>>>(x, W1, bufT, n);
    k_agg128h<<<agg_blocks, 256>>>(bufT, rowptr, esrc, enorm, b1, hA, n);
    // ---- layer 2 ----
    k_gemm_f16<128><<<ggrid, 256, SMEM128>>>(hA, Wm1, bufT, n);
    k_agg128h<<<agg_blocks, 256>>>(bufT, rowptr, esrc, enorm, bm1, hB, n);
    // ---- layer 3 ----
    k_gemm_f16<128><<<ggrid, 256, SMEM128>>>(hB, Wm2, bufT, n);
    k_agg128h<<<agg_blocks, 256>>>(bufT, rowptr, esrc, enorm, bm2, hA, n);
    // ---- layer 4 (64 out, fp32 out, no relu) ----
    k_gemm_f16<64><<<ggrid, 256, SMEM64>>>(hA, W2, bufT, n);
    k_agg64h<<<agg_blocks, 256>>>(bufT, rowptr, esrc, enorm, b2, (float*)d_out, n);
}

// round 11
// speedup vs baseline: 2.2069x; 1.0134x over previous
#include <cuda_runtime.h>
#include <cuda_fp16.h>
#include <cstdint>
#include <cstddef>

#define NMAX 100000
#define EMAX 1600000
#define TOTMAX (EMAX + NMAX)

#if defined(__CUDA_ARCH_FEAT_SM103_ALL) || defined(__CUDA_ARCH_FEAT_SM100_ALL) || \
    defined(__CUDA_ARCH_FEAT_SM101_ALL)
#define HAS_TCGEN05 1
#else
#define HAS_TCGEN05 0
#endif

// ---------------- device scratch ----------
__device__ int    g_indeg[NMAX];
__device__ float  g_dinv[NMAX];
__device__ int    g_rowptr[NMAX + 1];
__device__ int    g_cursor[NMAX];
__device__ int    g_bsum[1024];
__device__ int    g_esrc[TOTMAX];
__device__ float  g_enorm[TOTMAX];
__device__ __half g_bufA[(size_t)NMAX * 128];
__device__ __half g_bufB[(size_t)NMAX * 128];
__device__ __half g_bufT[(size_t)NMAX * 128];

// ---------------- PTX helpers ----------------
__device__ __forceinline__ uint32_t smem_u32(const void* p) {
    uint32_t a;
    asm("{ .reg .u64 t; cvta.to.shared.u64 t, %1; cvt.u32.u64 %0, t; }" : "=r"(a) : "l"(p));
    return a;
}

#if HAS_TCGEN05
__device__ __forceinline__ uint32_t elect_one() {
    uint32_t pred;
    asm volatile("{\n .reg .pred p;\n elect.sync _|p, 0xFFFFFFFF;\n selp.b32 %0, 1, 0, p;\n}"
                 : "=r"(pred));
    return pred;
}
#define TC_ALLOC(smem_addr, ncols) \
    asm volatile("tcgen05.alloc.cta_group::1.sync.aligned.shared::cta.b32 [%0], %1;" \
                 :: "r"(smem_addr), "r"(ncols) : "memory")
#define TC_DEALLOC(tmem, ncols) \
    asm volatile("tcgen05.dealloc.cta_group::1.sync.aligned.b32 %0, %1;" :: "r"(tmem), "r"(ncols))
#define TC_COMMIT(mbar) \
    asm volatile("tcgen05.commit.cta_group::1.mbarrier::arrive::one.shared::cluster.b64 [%0];" \
                 :: "r"(mbar) : "memory")
#define TC_WAIT_LD() asm volatile("tcgen05.wait::ld.sync.aligned;" ::: "memory")
#define TC_WAIT_ST() asm volatile("tcgen05.wait::st.sync.aligned;" ::: "memory")
#define TC_FENCE_BEFORE() asm volatile("tcgen05.fence::before_thread_sync;" ::: "memory")
#define TC_FENCE_AFTER() asm volatile("tcgen05.fence::after_thread_sync;" ::: "memory")
#define FENCE_ASYNC_SHARED() asm volatile("fence.proxy.async.shared::cta;" ::: "memory")
#define MBAR_INIT(mbar, cnt) \
    asm volatile("mbarrier.init.shared.b64 [%0], %1;" :: "r"(mbar), "r"(cnt) : "memory")
#define MBAR_INVAL(mbar) \
    asm volatile("mbarrier.inval.shared.b64 [%0];" :: "r"(mbar) : "memory")

__device__ __forceinline__ void mbar_wait(uint32_t mbar, uint32_t parity) {
    asm volatile(
        "{\n .reg .pred P1;\n"
        "WAIT_LOOP_%=:\n"
        " mbarrier.try_wait.parity.acquire.cta.shared::cta.b64 P1, [%0], %1, 0x989680;\n"
        " @P1 bra.uni WAIT_DONE_%=;\n"
        " bra.uni WAIT_LOOP_%=;\n"
        "WAIT_DONE_%=:\n}"
        :: "r"(mbar), "r"(parity) : "memory");
}

__device__ __forceinline__ void mma_f16_rs(uint32_t d, uint32_t a_tmem, uint64_t b,
                                           uint32_t idesc, uint32_t en) {
    uint32_t z = 0;
    asm volatile(
        "{\n .reg .pred p;\n setp.ne.u32 p, %5, 0;\n"
        " tcgen05.mma.cta_group::1.kind::f16 [%0], [%1], %2, %3, {%4, %4, %4, %4}, p;\n}"
        :: "r"(d), "r"(a_tmem), "l"(b), "r"(idesc), "r"(z), "r"(en) : "memory");
}

#define LDTM_X32(r, addr) \
    asm volatile( \
        "tcgen05.ld.sync.aligned.32x32b.x32.b32 " \
        "{%0, %1, %2, %3, %4, %5, %6, %7, %8, %9, %10, %11, %12, %13, %14, %15, " \
        " %16, %17, %18, %19, %20, %21, %22, %23, %24, %25, %26, %27, %28, %29, %30, %31}, [%32];" \
        : "=r"((r)[0]),  "=r"((r)[1]),  "=r"((r)[2]),  "=r"((r)[3]), \
          "=r"((r)[4]),  "=r"((r)[5]),  "=r"((r)[6]),  "=r"((r)[7]), \
          "=r"((r)[8]),  "=r"((r)[9]),  "=r"((r)[10]), "=r"((r)[11]), \
          "=r"((r)[12]), "=r"((r)[13]), "=r"((r)[14]), "=r"((r)[15]), \
          "=r"((r)[16]), "=r"((r)[17]), "=r"((r)[18]), "=r"((r)[19]), \
          "=r"((r)[20]), "=r"((r)[21]), "=r"((r)[22]), "=r"((r)[23]), \
          "=r"((r)[24]), "=r"((r)[25]), "=r"((r)[26]), "=r"((r)[27]), \
          "=r"((r)[28]), "=r"((r)[29]), "=r"((r)[30]), "=r"((r)[31]) \
        : "r"(addr))

#define STTM_X64(addr, r) \
    asm volatile( \
        "tcgen05.st.sync.aligned.32x32b.x64.b32 [%0], " \
        "{%1, %2, %3, %4, %5, %6, %7, %8, " \
        " %9, %10, %11, %12, %13, %14, %15, %16, " \
        " %17, %18, %19, %20, %21, %22, %23, %24, " \
        " %25, %26, %27, %28, %29, %30, %31, %32, " \
        " %33, %34, %35, %36, %37, %38, %39, %40, " \
        " %41, %42, %43, %44, %45, %46, %47, %48, " \
        " %49, %50, %51, %52, %53, %54, %55, %56, " \
        " %57, %58, %59, %60, %61, %62, %63, %64};" \
        :: "r"(addr), \
           "r"((r)[0]),  "r"((r)[1]),  "r"((r)[2]),  "r"((r)[3]), \
           "r"((r)[4]),  "r"((r)[5]),  "r"((r)[6]),  "r"((r)[7]), \
           "r"((r)[8]),  "r"((r)[9]),  "r"((r)[10]), "r"((r)[11]), \
           "r"((r)[12]), "r"((r)[13]), "r"((r)[14]), "r"((r)[15]), \
           "r"((r)[16]), "r"((r)[17]), "r"((r)[18]), "r"((r)[19]), \
           "r"((r)[20]), "r"((r)[21]), "r"((r)[22]), "r"((r)[23]), \
           "r"((r)[24]), "r"((r)[25]), "r"((r)[26]), "r"((r)[27]), \
           "r"((r)[28]), "r"((r)[29]), "r"((r)[30]), "r"((r)[31]), \
           "r"((r)[32]), "r"((r)[33]), "r"((r)[34]), "r"((r)[35]), \
           "r"((r)[36]), "r"((r)[37]), "r"((r)[38]), "r"((r)[39]), \
           "r"((r)[40]), "r"((r)[41]), "r"((r)[42]), "r"((r)[43]), \
           "r"((r)[44]), "r"((r)[45]), "r"((r)[46]), "r"((r)[47]), \
           "r"((r)[48]), "r"((r)[49]), "r"((r)[50]), "r"((r)[51]), \
           "r"((r)[52]), "r"((r)[53]), "r"((r)[54]), "r"((r)[55]), \
           "r"((r)[56]), "r"((r)[57]), "r"((r)[58]), "r"((r)[59]), \
           "r"((r)[60]), "r"((r)[61]), "r"((r)[62]), "r"((r)[63]) \
        : "memory")

__device__ __forceinline__ uint64_t make_desc(uint32_t addr) {
    const uint64_t base = (uint64_t(2) << 61) | (uint64_t(1) << 46) |
                          (uint64_t(64) << 32) | (uint64_t(1) << 16);
    return base | ((uint64_t)(addr >> 4) & 0x3FFF);
}
#endif  // HAS_TCGEN05

// ---------------- degree count ----------------
__global__ void k_deg_count(const int* __restrict__ ei, int* indeg, int E) {
    int g = blockIdx.x * blockDim.x + threadIdx.x;
    if (g < E) atomicAdd(&indeg[ei[E + g]], 1);
}

// ---------------- scan1 (+ fused dinv) ----------
__global__ void k_scan1(const int* __restrict__ in, int* out, int* bsum,
                        float* dinv, int n) {
    __shared__ int warp_sums[32];
    int g = blockIdx.x * 1024 + threadIdx.x;
    int lane = threadIdx.x & 31;
    int wid = threadIdx.x >> 5;
    int v = 0;
    if (g < n) {
        v = in[g] + 1;                 // +1 self loop
        dinv[g] = rsqrtf((float)v);    // fused dinv
    }
    int x = v;
#pragma unroll
    for (int off = 1; off < 32; off <<= 1) {
        int t = __shfl_up_sync(0xFFFFFFFF, x, off);
        if (lane >= off) x += t;
    }
    if (lane == 31) warp_sums[wid] = x;
    __syncthreads();
    if (wid == 0) {
        int s = (lane < 32) ? warp_sums[lane] : 0;
#pragma unroll
        for (int off = 1; off < 32; off <<= 1) {
            int t = __shfl_up_sync(0xFFFFFFFF, s, off);
            if (lane >= off) s += t;
        }
        warp_sums[lane] = s;
    }
    __syncthreads();
    int wbase = (wid > 0) ? warp_sums[wid - 1] : 0;
    if (g < n) out[g] = wbase + x - v;
    if (threadIdx.x == 1023) bsum[blockIdx.x] = wbase + x;
}
__global__ void k_scan2(int* bsum, int nb) {
    __shared__ int warp_sums[32];
    int lane = threadIdx.x & 31;
    int wid = threadIdx.x >> 5;
    int v = (threadIdx.x < nb) ? bsum[threadIdx.x] : 0;
    int x = v;
#pragma unroll
    for (int off = 1; off < 32; off <<= 1) {
        int t = __shfl_up_sync(0xFFFFFFFF, x, off);
        if (lane >= off) x += t;
    }
    if (lane == 31) warp_sums[wid] = x;
    __syncthreads();
    if (wid == 0) {
        int s = (lane < 32) ? warp_sums[lane] : 0;
#pragma unroll
        for (int off = 1; off < 32; off <<= 1) {
            int t = __shfl_up_sync(0xFFFFFFFF, s, off);
            if (lane >= off) s += t;
        }
        warp_sums[lane] = s;
    }
    __syncthreads();
    int wbase = (wid > 0) ? warp_sums[wid - 1] : 0;
    if (threadIdx.x < nb) bsum[threadIdx.x] = wbase + x - v;
}
__global__ void k_scan3(int* rowptr, const int* __restrict__ bsum, int* cursor,
                        int n, int total) {
    int g = blockIdx.x * 1024 + threadIdx.x;
    if (g < n) {
        int r = rowptr[g] + bsum[g >> 10];
        rowptr[g] = r;
        cursor[g] = r;
    }
    if (g == 0) rowptr[n] = total;
}

// ---------------- CSR fill ----------------
__global__ void k_fill(const int* __restrict__ ei, int E, int n,
                       const float* __restrict__ dinv, int* cursor,
                       int* esrc, float* enorm) {
    int g = blockIdx.x * blockDim.x + threadIdx.x;
    if (g < E) {
        int s = ei[g];
        int d = ei[E + g];
        int pos = atomicAdd(&cursor[d], 1);
        esrc[pos] = s;
        enorm[pos] = dinv[s] * dinv[d];
    } else if (g < E + n) {
        int i = g - E;
        int pos = atomicAdd(&cursor[i], 1);
        esrc[pos] = i;
        float dv = dinv[i];
        enorm[pos] = dv * dv;
    }
}

#if HAS_TCGEN05
template <int FOUT>
__device__ __forceinline__ void gemm_epilogue(uint32_t tm_d, int bm, int wid, int lane,
                                              __half* __restrict__ C, int n) {
    // caller guarantees wid < 4
    int row = bm + wid * 32 + lane;
    for (int c0 = 0; c0 < FOUT; c0 += 32) {
        uint32_t r[32];
        LDTM_X32(r, tm_d + c0);
        TC_WAIT_LD();
        if (row < n) {
            __half* dst = &C[(size_t)row * FOUT + c0];
            uint32_t o[16];
#pragma unroll
            for (int j = 0; j < 16; j++) {
                __half2 hp = __halves2half2(
                    __float2half_rn(__uint_as_float(r[2 * j])),
                    __float2half_rn(__uint_as_float(r[2 * j + 1])));
                o[j] = *reinterpret_cast<uint32_t*>(&hp);
            }
#pragma unroll
            for (int j = 0; j < 4; j++)
                *(uint4*)(dst + j * 8) =
                    make_uint4(o[4 * j], o[4 * j + 1], o[4 * j + 2], o[4 * j + 3]);
        }
    }
    TC_FENCE_BEFORE();
}
#endif

// ---------------- GEMM #1: fp32 input, 3-term fp16 split (layer 1) --------
// Warp-specialized: warps 4-7 load+split A into TMEM buf p while warps 0-3
// run the epilogue of tile it-1.  Then warp 0 issues the MMA.
template <int FOUT>
__global__ void __launch_bounds__(256, 1) __cluster_dims__(1, 1, 1) k_gemm_f32(
    const float* __restrict__ A, const float* __restrict__ W,
    __half* __restrict__ C, int n) {
#if HAS_TCGEN05
    extern __shared__ char smem[];
    constexpr int BH_OFF = 1024;
    constexpr int BL_OFF = BH_OFF + FOUT * 128 * 2;
    constexpr uint32_t IDESC = (1u << 4) | ((FOUT / 8) << 17) | (8u << 24);

    uint32_t sbase = smem_u32(smem);
    int tid = threadIdx.x;
    int wid = tid >> 5;
    int lane = tid & 31;

    if (wid == 0) TC_ALLOC(sbase, 512);
    if (tid == 0) { MBAR_INIT(sbase + 8, 1); MBAR_INIT(sbase + 16, 1); }
    __syncthreads();
    uint32_t tmem;
    asm volatile("ld.shared.b32 %0, [%1];" : "=r"(tmem) : "r"(sbase));

    for (int g = tid; g < FOUT * 16; g += 256) {
        int r = g >> 4;
        int k8 = (g & 15) << 3;
        uint32_t hu[4], lu[4];
#pragma unroll
        for (int j = 0; j < 4; j++) {
            float x0 = W[(size_t)(k8 + 2 * j) * FOUT + r];
            float x1 = W[(size_t)(k8 + 2 * j + 1) * FOUT + r];
            __half h0 = __float2half_rn(x0);
            __half h1 = __float2half_rn(x1);
            float l0 = x0 - __half2float(h0);
            float l1 = x1 - __half2float(h1);
            __half2 hp = __halves2half2(h0, h1);
            __half2 lp = __halves2half2(__float2half_rn(l0), __float2half_rn(l1));
            hu[j] = *reinterpret_cast<uint32_t*>(&hp);
            lu[j] = *reinterpret_cast<uint32_t*>(&lp);
        }
        int atom = (r >> 3) + (k8 >> 6) * (FOUT >> 3);
        uint32_t boff = atom * 1024 + (r & 7) * 128 + (k8 & 63) * 2;
        uint32_t sw = boff ^ ((boff >> 3) & 0x70);
        *(uint4*)(smem + BH_OFF + sw) = make_uint4(hu[0], hu[1], hu[2], hu[3]);
        *(uint4*)(smem + BL_OFF + sw) = make_uint4(lu[0], lu[1], lu[2], lu[3]);
    }
    FENCE_ASYNC_SHARED();
    __syncthreads();

    uint64_t bh = make_desc(sbase + BH_OFF);
    uint64_t bl = make_desc(sbase + BL_OFF);
    const uint64_t BCOL = (uint64_t)FOUT * 8;

    int it = 0;
    int prev_bm = 0;
    for (int tile = blockIdx.x; tile * 128 < n; tile += gridDim.x, it++) {
        int p = it & 1;
        int bm = tile * 128;
        uint32_t tm_a = tmem + p * 128;
        uint32_t tm_d = tmem + 256 + p * 128;

        if (tid >= 128) {
            // -- producer warps 4-7: A load + split + STTM into buf p --
            int wg_tid = tid - 128;
            int row = bm + wg_tid;
            const float4* a4 = (const float4*)&A[(size_t)row * 128];
            uint32_t v[64];
#pragma unroll
            for (int i = 0; i < 32; i++) {
                float4 f = (row < n) ? a4[i] : make_float4(0.f, 0.f, 0.f, 0.f);
                __half2 p0 = __halves2half2(__float2half_rn(f.x), __float2half_rn(f.y));
                __half2 p1 = __halves2half2(__float2half_rn(f.z), __float2half_rn(f.w));
                v[2 * i]     = *reinterpret_cast<uint32_t*>(&p0);
                v[2 * i + 1] = *reinterpret_cast<uint32_t*>(&p1);
            }
            uint32_t warp_off = (wg_tid >> 5) << 21;
            STTM_X64(tm_a + warp_off, v);
            TC_WAIT_ST();
#pragma unroll
            for (int i = 0; i < 32; i++) {
                float4 f = (row < n) ? a4[i] : make_float4(0.f, 0.f, 0.f, 0.f);
                float lx = f.x - __half2float(__float2half_rn(f.x));
                float ly = f.y - __half2float(__float2half_rn(f.y));
                float lz = f.z - __half2float(__float2half_rn(f.z));
                float lw = f.w - __half2float(__float2half_rn(f.w));
                __half2 p0 = __halves2half2(__float2half_rn(lx), __float2half_rn(ly));
                __half2 p1 = __halves2half2(__float2half_rn(lz), __float2half_rn(lw));
                v[2 * i]     = *reinterpret_cast<uint32_t*>(&p0);
                v[2 * i + 1] = *reinterpret_cast<uint32_t*>(&p1);
            }
            STTM_X64(tm_a + 64 + warp_off, v);
            TC_WAIT_ST();
            TC_FENCE_BEFORE();
        } else if (it > 0) {
            // -- consumer warps 0-3: epilogue of tile it-1 (overlaps A load) --
            int q = p ^ 1;
            mbar_wait(sbase + 8 + 8 * q, ((it - 1) >> 1) & 1);
            TC_FENCE_AFTER();
            gemm_epilogue<FOUT>(tmem + 256 + q * 128, prev_bm, wid, lane, C, n);
        }
        __syncthreads();

        if (wid == 0) {
            TC_FENCE_AFTER();
            if (elect_one()) {
#pragma unroll
                for (int t = 0; t < 3; t++) {
                    uint32_t a_base = tm_a + ((t == 2) ? 64 : 0);
                    uint64_t b_base = (t == 1) ? bl : bh;
#pragma unroll
                    for (int k = 0; k < 8; k++) {
                        uint64_t bd = b_base + ((k < 4) ? (uint64_t)(k * 2)
                                                        : BCOL + (uint64_t)((k - 4) * 2));
                        mma_f16_rs(tm_d, a_base + k * 8, bd, IDESC,
                                   (t > 0 || k > 0) ? 1u : 0u);
                    }
                }
                TC_COMMIT(sbase + 8 + 8 * p);
            }
        }
        prev_bm = bm;
    }
    if (it > 0 && wid < 4) {
        int q = (it - 1) & 1;
        mbar_wait(sbase + 8 + 8 * q, ((it - 1) >> 1) & 1);
        TC_FENCE_AFTER();
        gemm_epilogue<FOUT>(tmem + 256 + q * 128, prev_bm, wid, lane, C, n);
    }
    __syncthreads();
    if (tid == 0) { MBAR_INVAL(sbase + 8); MBAR_INVAL(sbase + 16); }
    __syncthreads();
    if (wid == 0) TC_DEALLOC(tmem, 512);
#else
    int tid = threadIdx.x;
    for (int tile = blockIdx.x; tile * 128 < n; tile += gridDim.x) {
        int bm = tile * 128;
        for (int idx = tid; idx < 128 * FOUT; idx += 256) {
            int r = bm + idx / FOUT, c = idx % FOUT;
            if (r < n) {
                float acc = 0.f;
                for (int k = 0; k < 128; k++)
                    acc += A[(size_t)r * 128 + k] * W[(size_t)k * FOUT + c];
                C[(size_t)r * FOUT + c] = __float2half_rn(acc);
            }
        }
    }
#endif
}

// ---------------- GEMM #2: fp16 input, 2-term (layers 2..4) ----------------
template <int FOUT>
__global__ void __launch_bounds__(256, 1) __cluster_dims__(1, 1, 1) k_gemm_f16(
    const __half* __restrict__ A, const float* __restrict__ W,
    __half* __restrict__ C, int n) {
#if HAS_TCGEN05
    extern __shared__ char smem[];
    constexpr int BH_OFF = 1024;
    constexpr int BL_OFF = BH_OFF + FOUT * 128 * 2;
    constexpr uint32_t IDESC = (1u << 4) | ((FOUT / 8) << 17) | (8u << 24);

    uint32_t sbase = smem_u32(smem);
    int tid = threadIdx.x;
    int wid = tid >> 5;
    int lane = tid & 31;

    if (wid == 0) TC_ALLOC(sbase, 512);
    if (tid == 0) { MBAR_INIT(sbase + 8, 1); MBAR_INIT(sbase + 16, 1); }
    __syncthreads();
    uint32_t tmem;
    asm volatile("ld.shared.b32 %0, [%1];" : "=r"(tmem) : "r"(sbase));

    for (int g = tid; g < FOUT * 16; g += 256) {
        int r = g >> 4;
        int k8 = (g & 15) << 3;
        uint32_t hu[4], lu[4];
#pragma unroll
        for (int j = 0; j < 4; j++) {
            float x0 = W[(size_t)(k8 + 2 * j) * FOUT + r];
            float x1 = W[(size_t)(k8 + 2 * j + 1) * FOUT + r];
            __half h0 = __float2half_rn(x0);
            __half h1 = __float2half_rn(x1);
            float l0 = x0 - __half2float(h0);
            float l1 = x1 - __half2float(h1);
            __half2 hp = __halves2half2(h0, h1);
            __half2 lp = __halves2half2(__float2half_rn(l0), __float2half_rn(l1));
            hu[j] = *reinterpret_cast<uint32_t*>(&hp);
            lu[j] = *reinterpret_cast<uint32_t*>(&lp);
        }
        int atom = (r >> 3) + (k8 >> 6) * (FOUT >> 3);
        uint32_t boff = atom * 1024 + (r & 7) * 128 + (k8 & 63) * 2;
        uint32_t sw = boff ^ ((boff >> 3) & 0x70);
        *(uint4*)(smem + BH_OFF + sw) = make_uint4(hu[0], hu[1], hu[2], hu[3]);
        *(uint4*)(smem + BL_OFF + sw) = make_uint4(lu[0], lu[1], lu[2], lu[3]);
    }
    FENCE_ASYNC_SHARED();
    __syncthreads();

    uint64_t bh = make_desc(sbase + BH_OFF);
    uint64_t bl = make_desc(sbase + BL_OFF);
    const uint64_t BCOL = (uint64_t)FOUT * 8;

    int it = 0;
    int prev_bm = 0;
    for (int tile = blockIdx.x; tile * 128 < n; tile += gridDim.x, it++) {
        int p = it & 1;
        int bm = tile * 128;
        uint32_t tm_a = tmem + p * 64;
        uint32_t tm_d = tmem + 256 + p * 128;

        if (tid >= 128) {
            int wg_tid = tid - 128;
            int row = bm + wg_tid;
            const uint4* a4 = (const uint4*)&A[(size_t)row * 128];
            uint32_t v[64];
#pragma unroll
            for (int i = 0; i < 16; i++) {
                uint4 u = (row < n) ? a4[i] : make_uint4(0, 0, 0, 0);
                v[4 * i] = u.x; v[4 * i + 1] = u.y; v[4 * i + 2] = u.z; v[4 * i + 3] = u.w;
            }
            uint32_t warp_off = (wg_tid >> 5) << 21;
            STTM_X64(tm_a + warp_off, v);
            TC_WAIT_ST();
            TC_FENCE_BEFORE();
        } else if (it > 0) {
            int q = p ^ 1;
            mbar_wait(sbase + 8 + 8 * q, ((it - 1) >> 1) & 1);
            TC_FENCE_AFTER();
            gemm_epilogue<FOUT>(tmem + 256 + q * 128, prev_bm, wid, lane, C, n);
        }
        __syncthreads();

        if (wid == 0) {
            TC_FENCE_AFTER();
            if (elect_one()) {
#pragma unroll
                for (int t = 0; t < 2; t++) {
                    uint64_t b_base = (t == 1) ? bl : bh;
#pragma unroll
                    for (int k = 0; k < 8; k++) {
                        uint64_t bd = b_base + ((k < 4) ? (uint64_t)(k * 2)
                                                        : BCOL + (uint64_t)((k - 4) * 2));
                        mma_f16_rs(tm_d, tm_a + k * 8, bd, IDESC,
                                   (t > 0 || k > 0) ? 1u : 0u);
                    }
                }
                TC_COMMIT(sbase + 8 + 8 * p);
            }
        }
        prev_bm = bm;
    }
    if (it > 0 && wid < 4) {
        int q = (it - 1) & 1;
        mbar_wait(sbase + 8 + 8 * q, ((it - 1) >> 1) & 1);
        TC_FENCE_AFTER();
        gemm_epilogue<FOUT>(tmem + 256 + q * 128, prev_bm, wid, lane, C, n);
    }
    __syncthreads();
    if (tid == 0) { MBAR_INVAL(sbase + 8); MBAR_INVAL(sbase + 16); }
    __syncthreads();
    if (wid == 0) TC_DEALLOC(tmem, 512);
#else
    int tid = threadIdx.x;
    for (int tile = blockIdx.x; tile * 128 < n; tile += gridDim.x) {
        int bm = tile * 128;
        for (int idx = tid; idx < 128 * FOUT; idx += 256) {
            int r = bm + idx / FOUT, c = idx % FOUT;
            if (r < n) {
                float acc = 0.f;
                for (int k = 0; k < 128; k++)
                    acc += __half2float(A[(size_t)r * 128 + k]) * W[(size_t)k * FOUT + c];
                C[(size_t)r * FOUT + c] = __float2half_rn(acc);
            }
        }
    }
#endif
}

// ---------------- aggregation: 8-edge unroll, vector index loads ----------
__global__ void k_agg128h(const __half* __restrict__ t, const int* __restrict__ rowptr,
                          const int* __restrict__ esrc, const float* __restrict__ enorm,
                          const float* __restrict__ bias, __half* __restrict__ out,
                          int n) {
    int w = (blockIdx.x * blockDim.x + threadIdx.x) >> 5;
    if (w >= n) return;
    int lane = threadIdx.x & 31;
    int beg = rowptr[w], end = rowptr[w + 1];
    float ax = 0.f, ay = 0.f, az = 0.f, aw = 0.f;
    int e = beg;
    for (; e < end && (e & 3); e++) {
        int s0 = esrc[e];
        float n0 = enorm[e];
        uint2 u0 = *(const uint2*)&t[(size_t)s0 * 128 + lane * 4];
        float2 a0 = __half22float2(*reinterpret_cast<__half2*>(&u0.x));
        float2 b0 = __half22float2(*reinterpret_cast<__half2*>(&u0.y));
        ax += a0.x * n0; ay += a0.y * n0; az += b0.x * n0; aw += b0.y * n0;
    }
    for (; e + 7 < end; e += 8) {
        int4 s4a = *(const int4*)&esrc[e];
        int4 s4b = *(const int4*)&esrc[e + 4];
        float4 n4a = *(const float4*)&enorm[e];
        float4 n4b = *(const float4*)&enorm[e + 4];
        uint2 u0 = *(const uint2*)&t[(size_t)s4a.x * 128 + lane * 4];
        uint2 u1 = *(const uint2*)&t[(size_t)s4a.y * 128 + lane * 4];
        uint2 u2 = *(const uint2*)&t[(size_t)s4a.z * 128 + lane * 4];
        uint2 u3 = *(const uint2*)&t[(size_t)s4a.w * 128 + lane * 4];
        uint2 u4 = *(const uint2*)&t[(size_t)s4b.x * 128 + lane * 4];
        uint2 u5 = *(const uint2*)&t[(size_t)s4b.y * 128 + lane * 4];
        uint2 u6 = *(const uint2*)&t[(size_t)s4b.z * 128 + lane * 4];
        uint2 u7 = *(const uint2*)&t[(size_t)s4b.w * 128 + lane * 4];
#define ACC(u, nn)                                                             \
        {                                                                      \
            float2 _a = __half22float2(*reinterpret_cast<__half2*>(&(u).x));   \
            float2 _b = __half22float2(*reinterpret_cast<__half2*>(&(u).y));   \
            ax += _a.x * (nn); ay += _a.y * (nn);                              \
            az += _b.x * (nn); aw += _b.y * (nn);                              \
        }
        ACC(u0, n4a.x) ACC(u1, n4a.y) ACC(u2, n4a.z) ACC(u3, n4a.w)
        ACC(u4, n4b.x) ACC(u5, n4b.y) ACC(u6, n4b.z) ACC(u7, n4b.w)
#undef ACC
    }
    for (; e < end; e++) {
        int s0 = esrc[e];
        float n0 = enorm[e];
        uint2 u0 = *(const uint2*)&t[(size_t)s0 * 128 + lane * 4];
        float2 a0 = __half22float2(*reinterpret_cast<__half2*>(&u0.x));
        float2 b0 = __half22float2(*reinterpret_cast<__half2*>(&u0.y));
        ax += a0.x * n0; ay += a0.y * n0; az += b0.x * n0; aw += b0.y * n0;
    }
    float4 b4 = *(const float4*)&bias[lane * 4];
    ax = fmaxf(ax + b4.x, 0.f);
    ay = fmaxf(ay + b4.y, 0.f);
    az = fmaxf(az + b4.z, 0.f);
    aw = fmaxf(aw + b4.w, 0.f);
    __half2 h0 = __halves2half2(__float2half_rn(ax), __float2half_rn(ay));
    __half2 h1 = __halves2half2(__float2half_rn(az), __float2half_rn(aw));
    *(uint2*)&out[(size_t)w * 128 + lane * 4] =
        make_uint2(*reinterpret_cast<uint32_t*>(&h0), *reinterpret_cast<uint32_t*>(&h1));
}

__global__ void k_agg64h(const __half* __restrict__ t, const int* __restrict__ rowptr,
                         const int* __restrict__ esrc, const float* __restrict__ enorm,
                         const float* __restrict__ bias, float* __restrict__ out,
                         int n) {
    int w = (blockIdx.x * blockDim.x + threadIdx.x) >> 5;
    if (w >= n) return;
    int lane = threadIdx.x & 31;
    int beg = rowptr[w], end = rowptr[w + 1];
    float ax = 0.f, ay = 0.f;
    int e = beg;
    for (; e < end && (e & 3); e++) {
        int s0 = esrc[e];
        float n0 = enorm[e];
        uint32_t u0 = *(const uint32_t*)&t[(size_t)s0 * 64 + lane * 2];
        float2 a0 = __half22float2(*reinterpret_cast<__half2*>(&u0));
        ax += a0.x * n0; ay += a0.y * n0;
    }
    for (; e + 7 < end; e += 8) {
        int4 s4a = *(const int4*)&esrc[e];
        int4 s4b = *(const int4*)&esrc[e + 4];
        float4 n4a = *(const float4*)&enorm[e];
        float4 n4b = *(const float4*)&enorm[e + 4];
        uint32_t u0 = *(const uint32_t*)&t[(size_t)s4a.x * 64 + lane * 2];
        uint32_t u1 = *(const uint32_t*)&t[(size_t)s4a.y * 64 + lane * 2];
        uint32_t u2 = *(const uint32_t*)&t[(size_t)s4a.z * 64 + lane * 2];
        uint32_t u3 = *(const uint32_t*)&t[(size_t)s4a.w * 64 + lane * 2];
        uint32_t u4 = *(const uint32_t*)&t[(size_t)s4b.x * 64 + lane * 2];
        uint32_t u5 = *(const uint32_t*)&t[(size_t)s4b.y * 64 + lane * 2];
        uint32_t u6 = *(const uint32_t*)&t[(size_t)s4b.z * 64 + lane * 2];
        uint32_t u7 = *(const uint32_t*)&t[(size_t)s4b.w * 64 + lane * 2];
#define ACC(u, nn)                                                             \
        {                                                                      \
            float2 _a = __half22float2(*reinterpret_cast<__half2*>(&(u)));     \
            ax += _a.x * (nn); ay += _a.y * (nn);                              \
        }
        ACC(u0, n4a.x) ACC(u1, n4a.y) ACC(u2, n4a.z) ACC(u3, n4a.w)
        ACC(u4, n4b.x) ACC(u5, n4b.y) ACC(u6, n4b.z) ACC(u7, n4b.w)
#undef ACC
    }
    for (; e < end; e++) {
        int s0 = esrc[e];
        float n0 = enorm[e];
        uint32_t u0 = *(const uint32_t*)&t[(size_t)s0 * 64 + lane * 2];
        float2 a0 = __half22float2(*reinterpret_cast<__half2*>(&u0));
        ax += a0.x * n0; ay += a0.y * n0;
    }
    float2 b2 = *(const float2*)&bias[lane * 2];
    ax += b2.x; ay += b2.y;
    *(float2*)&out[(size_t)w * 64 + lane * 2] = make_float2(ax, ay);
}

// ---------------- host ----------------
extern "C" void kernel_launch(void* const* d_in, const int* in_sizes, int n_in,
                              void* d_out, int out_size) {
    const float* x   = (const float*)d_in[0];
    const int*   ei  = (const int*)d_in[1];
    const float* W1  = (const float*)d_in[2];
    const float* b1  = (const float*)d_in[3];
    const float* Wm1 = (const float*)d_in[4];
    const float* bm1 = (const float*)d_in[5];
    const float* Wm2 = (const float*)d_in[6];
    const float* bm2 = (const float*)d_in[7];
    const float* W2  = (const float*)d_in[8];
    const float* b2  = (const float*)d_in[9];

    int n = in_sizes[0] / 128;
    int E = in_sizes[1] / 2;

    void* p;
    int *indeg, *rowptr, *cursor, *bsum, *esrc;
    float *dinv, *enorm;
    __half *hA, *hB, *bufT;
    cudaGetSymbolAddress(&p, g_indeg);  indeg  = (int*)p;
    cudaGetSymbolAddress(&p, g_dinv);   dinv   = (float*)p;
    cudaGetSymbolAddress(&p, g_rowptr); rowptr = (int*)p;
    cudaGetSymbolAddress(&p, g_cursor); cursor = (int*)p;
    cudaGetSymbolAddress(&p, g_bsum);   bsum   = (int*)p;
    cudaGetSymbolAddress(&p, g_esrc);   esrc   = (int*)p;
    cudaGetSymbolAddress(&p, g_enorm);  enorm  = (float*)p;
    cudaGetSymbolAddress(&p, g_bufA);   hA     = (__half*)p;
    cudaGetSymbolAddress(&p, g_bufB);   hB     = (__half*)p;
    cudaGetSymbolAddress(&p, g_bufT);   bufT   = (__half*)p;

    int nb = (n + 1023) / 1024;

    // ---- graph normalization + CSR build ----
    cudaMemsetAsync(indeg, 0, n * sizeof(int));
    k_deg_count<<<(E + 255) / 256, 256>>>(ei, indeg, E);
    k_scan1<<<nb, 1024>>>(indeg, rowptr, bsum, dinv, n);
    k_scan2<<<1, 1024>>>(bsum, nb);
    k_scan3<<<nb, 1024>>>(rowptr, bsum, cursor, n, E + n);
    k_fill<<<(E + n + 255) / 256, 256>>>(ei, E, n, dinv, cursor, esrc, enorm);

    int gblocks = (n + 127) / 128;
    int ggrid = gblocks < 148 ? gblocks : 148;
    int agg_blocks = (n * 32 + 255) / 256;
    const int SMEM128 = 1024 + 2 * 128 * 128 * 2;  // 66560
    const int SMEM64  = 1024 + 2 * 64 * 128 * 2;   // 33792
    cudaFuncSetAttribute(k_gemm_f32<128>, cudaFuncAttributeMaxDynamicSharedMemorySize, SMEM128);
    cudaFuncSetAttribute(k_gemm_f16<128>, cudaFuncAttributeMaxDynamicSharedMemorySize, SMEM128);
    cudaFuncSetAttribute(k_gemm_f16<64>,  cudaFuncAttributeMaxDynamicSharedMemorySize, SMEM64);

    // ---- layer 1 (fp32 input) ----
    k_gemm_f32<128><<<ggrid, 256, SMEM128>>>(x, W1, bufT, n);
    k_agg128h<<<agg_blocks, 256>>>(bufT, rowptr, esrc, enorm, b1, hA, n);
    // ---- layer 2 ----
    k_gemm_f16<128><<<ggrid, 256, SMEM128>>>(hA, Wm1, bufT, n);
    k_agg128h<<<agg_blocks, 256>>>(bufT, rowptr, esrc, enorm, bm1, hB, n);
    // ---- layer 3 ----
    k_gemm_f16<128><<<ggrid, 256, SMEM128>>>(hB, Wm2, bufT, n);
    k_agg128h<<<agg_blocks, 256>>>(bufT, rowptr, esrc, enorm, bm2, hA, n);
    // ---- layer 4 (64 out, fp32 out, no relu) ----
    k_gemm_f16<64><<<ggrid, 256, SMEM64>>>(hA, W2, bufT, n);
    k_agg64h<<<agg_blocks, 256>>>(bufT, rowptr, esrc, enorm, b2, (float*)d_out, n);
}